// round 5
// baseline (speedup 1.0000x reference)
#include <cuda_runtime.h>
#include <cuda_fp16.h>
#include <math_constants.h>
#include <cstdint>

#define N_PTS   92160
#define D_DIM   192
#define BD_DIM  256
#define H_HEADS 8
#define FF_DIM  768
#define S_SETS  2560
#define L_LEN   36
#define M_BOX   256
#define HD_DIM  24

// ---------------- scratch (static device globals; no allocation) ----------------
__device__ float g_q[N_PTS * D_DIM];
__device__ float g_proj[N_PTS * D_DIM];
__device__ float g_x[N_PTS * D_DIM];
__device__ float g_y[N_PTS * D_DIM];
__device__ float g_k[M_BOX * D_DIM];
__device__ float g_v[M_BOX * D_DIM];
__device__ int   g_fp[N_PTS];

__device__ __half g_qinh[N_PTS * D_DIM];
__device__ __half g_ctxh[N_PTS * D_DIM];
__device__ __half g_xh[N_PTS * D_DIM];
__device__ __half g_hh[(size_t)N_PTS * FF_DIM];
#define WOFF_Q 0
#define WOFF_O 36864
#define WOFF_1 73728
#define WOFF_2 221184
__device__ __half g_wh[368640];

// ---------------- cp.async helpers ----------------
__device__ __forceinline__ void cp_async16(void* smem, const void* gmem) {
    uint32_t s = (uint32_t)__cvta_generic_to_shared(smem);
    asm volatile("cp.async.cg.shared.global [%0], [%1], 16;" :: "r"(s), "l"(gmem));
}
__device__ __forceinline__ void cp_commit() {
    asm volatile("cp.async.commit_group;");
}
template<int N>
__device__ __forceinline__ void cp_wait() {
    asm volatile("cp.async.wait_group %0;" :: "n"(N));
}

// ================= fp16 mma.sync GEMM with 3-stage cp.async pipeline =================
// A: (Mrows, K) half row-major, W: (Dout, K) half row-major. C = A @ W^T + bias.
// CTA tile 128 x 64, BK = 32, 256 threads = 8 warps (4m x 2n), warp tile 32 x 32.
#define HPAD 40
#define STG  3

__device__ __forceinline__ void mma16816(float* d, const uint32_t* a, const uint32_t* b) {
    asm volatile(
        "mma.sync.aligned.m16n8k16.row.col.f32.f16.f16.f32 "
        "{%0,%1,%2,%3}, {%4,%5,%6,%7}, {%8,%9}, {%0,%1,%2,%3};\n"
        : "+f"(d[0]), "+f"(d[1]), "+f"(d[2]), "+f"(d[3])
        : "r"(a[0]), "r"(a[1]), "r"(a[2]), "r"(a[3]), "r"(b[0]), "r"(b[1]));
}

template<bool RELU, bool OUTH>
__global__ __launch_bounds__(256)
void hgemm(const __half* __restrict__ A, const __half* __restrict__ W,
           const float* __restrict__ bias, float* __restrict__ C,
           __half* __restrict__ Ch, int K, int Dout)
{
    __shared__ __half sb[STG][192 * HPAD];

    const int tid  = threadIdx.x;
    const int lane = tid & 31;
    const int wid  = tid >> 5;
    const int wm   = wid & 3;
    const int wn   = wid >> 2;
    const int m0   = blockIdx.y * 128;
    const int n0   = blockIdx.x * 64;
    const int lr   = lane >> 2;
    const int lc2  = (lane & 3) * 2;

    // per-thread load slots: rows r0, r0+64 of A and row r0 of W (3 x 16B per stage)
    const int r0   = tid >> 2;             // 0..63
    const int c8   = (tid & 3) * 8;        // 0,8,16,24
    const __half* gA0 = A + (size_t)(m0 + r0)      * K + c8;
    const __half* gA1 = A + (size_t)(m0 + r0 + 64) * K + c8;
    const __half* gW  = W + (size_t)(n0 + r0)      * K + c8;
    const int s0 = r0 * HPAD + c8;
    const int s1 = (r0 + 64) * HPAD + c8;
    const int s2 = (r0 + 128) * HPAD + c8;

    const int nT = K >> 5;

    float acc[2][4][4];
    #pragma unroll
    for (int i = 0; i < 2; i++)
        #pragma unroll
        for (int j = 0; j < 4; j++)
            #pragma unroll
            for (int e = 0; e < 4; e++) acc[i][j][e] = 0.f;

    // prologue: stages 0,1
    {
        cp_async16(sb[0] + s0, gA0);
        cp_async16(sb[0] + s1, gA1);
        cp_async16(sb[0] + s2, gW);
        cp_commit();
        cp_async16(sb[1] + s0, gA0 + 32);
        cp_async16(sb[1] + s1, gA1 + 32);
        cp_async16(sb[1] + s2, gW + 32);
        cp_commit();
    }

    for (int t = 0; t < nT; ++t) {
        cp_wait<1>();
        __syncthreads();

        // issue prefetch for t+2 (buffer safe: its last compute was t-1, done by the sync above)
        if (t + 2 < nT) {
            const int sNext = (t + 2) % STG;
            const int off = (t + 2) * 32;
            cp_async16(sb[sNext] + s0, gA0 + off);
            cp_async16(sb[sNext] + s1, gA1 + off);
            cp_async16(sb[sNext] + s2, gW + off);
        }
        cp_commit();   // always commit (possibly empty) to keep group accounting fixed

        const __half* As = sb[t % STG];
        const __half* Ws = As + 128 * HPAD;

        #pragma unroll
        for (int ks = 0; ks < 32; ks += 16) {
            uint32_t af[2][4], bf[4][2];
            #pragma unroll
            for (int i = 0; i < 2; i++) {
                const int base = (wm * 32 + i * 16 + lr) * HPAD + ks + lc2;
                af[i][0] = *(const uint32_t*)(As + base);
                af[i][1] = *(const uint32_t*)(As + base + 8 * HPAD);
                af[i][2] = *(const uint32_t*)(As + base + 8);
                af[i][3] = *(const uint32_t*)(As + base + 8 * HPAD + 8);
            }
            #pragma unroll
            for (int j = 0; j < 4; j++) {
                const int base = (wn * 32 + j * 8 + lr) * HPAD + ks + lc2;
                bf[j][0] = *(const uint32_t*)(Ws + base);
                bf[j][1] = *(const uint32_t*)(Ws + base + 8);
            }
            #pragma unroll
            for (int i = 0; i < 2; i++)
                #pragma unroll
                for (int j = 0; j < 4; j++)
                    mma16816(acc[i][j], af[i], bf[j]);
        }
        __syncthreads();
    }

    // epilogue
    float2 bx[4];
    #pragma unroll
    for (int j = 0; j < 4; j++) {
        const int cj = n0 + wn * 32 + j * 8 + lc2;
        bx[j] = *(const float2*)(bias + cj);
    }
    #pragma unroll
    for (int i = 0; i < 2; i++) {
        const int r = m0 + wm * 32 + i * 16 + lr;
        #pragma unroll
        for (int j = 0; j < 4; j++) {
            const int cj = n0 + wn * 32 + j * 8 + lc2;
            float v0 = acc[i][j][0] + bx[j].x;
            float v1 = acc[i][j][1] + bx[j].y;
            float v2 = acc[i][j][2] + bx[j].x;
            float v3 = acc[i][j][3] + bx[j].y;
            if (RELU) {
                v0 = fmaxf(v0, 0.f); v1 = fmaxf(v1, 0.f);
                v2 = fmaxf(v2, 0.f); v3 = fmaxf(v3, 0.f);
            }
            if (OUTH) {
                *(__half2*)(Ch + (size_t)r       * Dout + cj) = __floats2half2_rn(v0, v1);
                *(__half2*)(Ch + (size_t)(r + 8) * Dout + cj) = __floats2half2_rn(v2, v3);
            } else {
                *(float2*)(C + (size_t)r       * Dout + cj) = make_float2(v0, v1);
                *(float2*)(C + (size_t)(r + 8) * Dout + cj) = make_float2(v2, v3);
            }
        }
    }
}

// ---------------- small SIMT GEMM for K/V projections ----------------
#define BM 128
#define BN 64
#define BK 16

template<bool RELU, bool ADD2>
__global__ __launch_bounds__(256, 2)
void gemm_kernel(const float* __restrict__ A, const float* __restrict__ A2,
                 const float* __restrict__ W, const float* __restrict__ bias,
                 float* __restrict__ C, int K, int Dout)
{
    __shared__ float As[BK][BM + 4];
    __shared__ float Ws[BK][BN + 4];

    const int tid = threadIdx.x;
    const int tx = tid & 15;
    const int ty = tid >> 4;
    const int m0 = blockIdx.y * BM;
    const int n0 = blockIdx.x * BN;

    const int ar = tid >> 2;
    const int ac = (tid & 3) << 2;

    const float* Ap0  = A  + (size_t)(m0 + ar)      * K + ac;
    const float* Ap1  = A  + (size_t)(m0 + ar + 64) * K + ac;
    const float* A2p0 = ADD2 ? (A2 + (size_t)(m0 + ar)      * K + ac) : nullptr;
    const float* A2p1 = ADD2 ? (A2 + (size_t)(m0 + ar + 64) * K + ac) : nullptr;
    const float* Wp   = W  + (size_t)(n0 + ar)      * K + ac;

    const int nT = K / BK;

    float4 pa0 = *(const float4*)(Ap0);
    float4 pa1 = *(const float4*)(Ap1);
    float4 pw  = *(const float4*)(Wp);
    if (ADD2) {
        float4 q0 = *(const float4*)(A2p0);
        float4 q1 = *(const float4*)(A2p1);
        pa0.x += q0.x; pa0.y += q0.y; pa0.z += q0.z; pa0.w += q0.w;
        pa1.x += q1.x; pa1.y += q1.y; pa1.z += q1.z; pa1.w += q1.w;
    }

    float acc[8][4];
    #pragma unroll
    for (int i = 0; i < 8; i++)
        #pragma unroll
        for (int j = 0; j < 4; j++) acc[i][j] = 0.f;

    for (int t = 0; t < nT; ++t) {
        As[ac+0][ar]    = pa0.x; As[ac+1][ar]    = pa0.y;
        As[ac+2][ar]    = pa0.z; As[ac+3][ar]    = pa0.w;
        As[ac+0][ar+64] = pa1.x; As[ac+1][ar+64] = pa1.y;
        As[ac+2][ar+64] = pa1.z; As[ac+3][ar+64] = pa1.w;
        Ws[ac+0][ar]    = pw.x;  Ws[ac+1][ar]    = pw.y;
        Ws[ac+2][ar]    = pw.z;  Ws[ac+3][ar]    = pw.w;
        __syncthreads();

        if (t + 1 < nT) {
            const int off = (t + 1) * BK;
            pa0 = *(const float4*)(Ap0 + off);
            pa1 = *(const float4*)(Ap1 + off);
            pw  = *(const float4*)(Wp  + off);
            if (ADD2) {
                float4 q0 = *(const float4*)(A2p0 + off);
                float4 q1 = *(const float4*)(A2p1 + off);
                pa0.x += q0.x; pa0.y += q0.y; pa0.z += q0.z; pa0.w += q0.w;
                pa1.x += q1.x; pa1.y += q1.y; pa1.z += q1.z; pa1.w += q1.w;
            }
        }

        #pragma unroll
        for (int k = 0; k < BK; ++k) {
            float a[8], w[4];
            #pragma unroll
            for (int i = 0; i < 8; i++) a[i] = As[k][ty * 8 + i];
            #pragma unroll
            for (int j = 0; j < 4; j++) w[j] = Ws[k][tx * 4 + j];
            #pragma unroll
            for (int i = 0; i < 8; i++)
                #pragma unroll
                for (int j = 0; j < 4; j++) acc[i][j] += a[i] * w[j];
        }
        __syncthreads();
    }

    const float b0 = bias[n0 + tx*4 + 0];
    const float b1 = bias[n0 + tx*4 + 1];
    const float b2 = bias[n0 + tx*4 + 2];
    const float b3 = bias[n0 + tx*4 + 3];
    #pragma unroll
    for (int i = 0; i < 8; i++) {
        float4 o;
        o.x = acc[i][0] + b0; o.y = acc[i][1] + b1;
        o.z = acc[i][2] + b2; o.w = acc[i][3] + b3;
        if (RELU) {
            o.x = fmaxf(o.x, 0.f); o.y = fmaxf(o.y, 0.f);
            o.z = fmaxf(o.z, 0.f); o.w = fmaxf(o.w, 0.f);
        }
        *(float4*)(C + (size_t)(m0 + ty*8 + i) * Dout + n0 + tx*4) = o;
    }
}

// ---------------- fused attention: one CTA per (set, head), writes half ctx ----------------
#define ATTN_SMEM ((L_LEN*HD_DIM + M_BOX*HD_DIM + L_LEN*M_BOX) * 4 + L_LEN * 4)

__global__ __launch_bounds__(256)
void attn_kernel(const float* __restrict__ qbuf, const float* __restrict__ kbuf,
                 const float* __restrict__ vbuf, const int* __restrict__ vinds,
                 const int* __restrict__ vcoords, const int* __restrict__ bcoords,
                 __half* __restrict__ ctxh)
{
    extern __shared__ float smf[];
    float* qs = smf;
    float* vs = qs + L_LEN * HD_DIM;
    float* sc = vs + M_BOX * HD_DIM;
    int*   qb = (int*)(sc + L_LEN * M_BOX);

    const int s = blockIdx.x;
    const int h = blockIdx.y;
    const int t = threadIdx.x;

    float kr[HD_DIM];
    {
        const float4* kp = (const float4*)(kbuf + (size_t)t * D_DIM + h * HD_DIM);
        const float4* vp = (const float4*)(vbuf + (size_t)t * D_DIM + h * HD_DIM);
        #pragma unroll
        for (int i = 0; i < 6; i++) {
            float4 f = kp[i];
            kr[4*i+0] = f.x; kr[4*i+1] = f.y; kr[4*i+2] = f.z; kr[4*i+3] = f.w;
            float4 g = vp[i];
            vs[t*HD_DIM + 4*i + 0] = g.x; vs[t*HD_DIM + 4*i + 1] = g.y;
            vs[t*HD_DIM + 4*i + 2] = g.z; vs[t*HD_DIM + 4*i + 3] = g.w;
        }
    }
    const int bb = bcoords[t * 4];

    if (t < L_LEN) qb[t] = vcoords[(size_t)vinds[s * L_LEN + t] * 4];
    for (int i = t; i < L_LEN * HD_DIM; i += 256) {
        int l = i / HD_DIM, dd = i % HD_DIM;
        qs[i] = qbuf[(size_t)vinds[s * L_LEN + l] * D_DIM + h * HD_DIM + dd];
    }
    __syncthreads();

    const float scale = 0.20412414523193154f;
    #pragma unroll 2
    for (int l = 0; l < L_LEN; l++) {
        const float* qr = qs + l * HD_DIM;
        float dot = 0.f;
        #pragma unroll
        for (int j = 0; j < HD_DIM; j++) dot += qr[j] * kr[j];
        sc[l * M_BOX + t] = (qb[l] != bb) ? -CUDART_INF_F : dot * scale;
    }
    __syncthreads();

    const int w = t >> 5, lane = t & 31;
    for (int l = w; l < L_LEN; l += 8) {
        float* row = sc + l * M_BOX;
        float e[8];
        float mx = -CUDART_INF_F;
        #pragma unroll
        for (int i = 0; i < 8; i++) { e[i] = row[lane + 32*i]; mx = fmaxf(mx, e[i]); }
        #pragma unroll
        for (int o = 16; o > 0; o >>= 1) mx = fmaxf(mx, __shfl_xor_sync(0xffffffffu, mx, o));
        float sum = 0.f;
        if (mx > -CUDART_INF_F) {
            #pragma unroll
            for (int i = 0; i < 8; i++) { e[i] = __expf(e[i] - mx); sum += e[i]; }
        } else {
            #pragma unroll
            for (int i = 0; i < 8; i++) e[i] = 0.f;
        }
        #pragma unroll
        for (int o = 16; o > 0; o >>= 1) sum += __shfl_xor_sync(0xffffffffu, sum, o);
        const float inv = sum > 0.f ? 1.0f / sum : 0.f;
        #pragma unroll
        for (int i = 0; i < 8; i++) row[lane + 32*i] = e[i] * inv;
    }
    __syncthreads();

    if (lane < HD_DIM) {
        const float* s0 = sc + (w +  0) * M_BOX;
        const float* s1 = sc + (w +  8) * M_BOX;
        const float* s2 = sc + (w + 16) * M_BOX;
        const float* s3 = sc + (w + 24) * M_BOX;
        const bool has5 = (w < L_LEN - 32);
        const float* s4 = has5 ? (sc + (w + 32) * M_BOX) : s0;
        float a0 = 0.f, a1 = 0.f, a2 = 0.f, a3 = 0.f, a4 = 0.f;
        #pragma unroll 2
        for (int m = 0; m < M_BOX; m++) {
            const float vv = vs[m * HD_DIM + lane];
            a0 += s0[m] * vv;
            a1 += s1[m] * vv;
            a2 += s2[m] * vv;
            a3 += s3[m] * vv;
            if (has5) a4 += s4[m] * vv;
        }
        const size_t base = (size_t)s * L_LEN;
        const int    off  = h * HD_DIM + lane;
        ctxh[(base + w +  0) * D_DIM + off] = __float2half(a0);
        ctxh[(base + w +  8) * D_DIM + off] = __float2half(a1);
        ctxh[(base + w + 16) * D_DIM + off] = __float2half(a2);
        ctxh[(base + w + 24) * D_DIM + off] = __float2half(a3);
        if (has5) ctxh[(base + w + 32) * D_DIM + off] = __float2half(a4);
    }
}

// ---------------- first-occurrence scatter index ----------------
__global__ void init_fp_kernel(int* __restrict__ fp)
{
    int i = blockIdx.x * blockDim.x + threadIdx.x;
    if (i < N_PTS) fp[i] = 0x7FFFFFFF;
}

__global__ void fill_fp_kernel(const int* __restrict__ vinds, int* __restrict__ fp)
{
    int p = blockIdx.x * blockDim.x + threadIdx.x;
    if (p < S_SETS * L_LEN) {
        int n = vinds[p];
        if (n >= 0 && n < N_PTS) atomicMin(&fp[n], p);
    }
}

// ---------------- residual + layernorm (warp per row) ----------------
template<bool GATHER, bool OUTH>
__global__ __launch_bounds__(256)
void ln_kernel(const float* __restrict__ a, const float* __restrict__ b,
               const int* __restrict__ fp, const float* __restrict__ gamma,
               const float* __restrict__ beta, float* __restrict__ outp,
               __half* __restrict__ oh)
{
    const int row  = (blockIdx.x * 256 + threadIdx.x) >> 5;
    const int lane = threadIdx.x & 31;
    if (row >= N_PTS) return;

    const float* arow = a + (size_t)row * D_DIM;
    const float* brow;
    if (GATHER) {
        int p = fp[row];
        if (p < 0 || p >= N_PTS) p = row;
        brow = b + (size_t)p * D_DIM;
    } else {
        brow = b + (size_t)row * D_DIM;
    }

    float v[6];
    float s = 0.f;
    #pragma unroll
    for (int i = 0; i < 6; i++) {
        const int idx = lane + 32 * i;
        v[i] = arow[idx] + brow[idx];
        s += v[i];
    }
    #pragma unroll
    for (int o = 16; o > 0; o >>= 1) s += __shfl_xor_sync(0xffffffffu, s, o);
    const float mean = s * (1.0f / D_DIM);

    float q = 0.f;
    #pragma unroll
    for (int i = 0; i < 6; i++) { const float d = v[i] - mean; q += d * d; }
    #pragma unroll
    for (int o = 16; o > 0; o >>= 1) q += __shfl_xor_sync(0xffffffffu, q, o);
    const float inv = rsqrtf(q * (1.0f / D_DIM) + 1e-5f);

    float* orow = outp + (size_t)row * D_DIM;
    #pragma unroll
    for (int i = 0; i < 6; i++) {
        const int idx = lane + 32 * i;
        const float val = (v[i] - mean) * inv * gamma[idx] + beta[idx];
        orow[idx] = val;
        if (OUTH) oh[(size_t)row * D_DIM + idx] = __float2half(val);
    }
}

// ---------------- conversion kernels ----------------
__global__ void add_half_kernel(const float* __restrict__ a, const float* __restrict__ b,
                                __half* __restrict__ c, int n4)
{
    int i = blockIdx.x * blockDim.x + threadIdx.x;
    if (i >= n4) return;
    float4 x = ((const float4*)a)[i];
    float4 y = ((const float4*)b)[i];
    ((__half2*)c)[2*i]   = __floats2half2_rn(x.x + y.x, x.y + y.y);
    ((__half2*)c)[2*i+1] = __floats2half2_rn(x.z + y.z, x.w + y.w);
}

__global__ void cvt_half_kernel(const float* __restrict__ a, __half* __restrict__ c, int n4)
{
    int i = blockIdx.x * blockDim.x + threadIdx.x;
    if (i >= n4) return;
    float4 x = ((const float4*)a)[i];
    ((__half2*)c)[2*i]   = __floats2half2_rn(x.x, x.y);
    ((__half2*)c)[2*i+1] = __floats2half2_rn(x.z, x.w);
}

// ---------------- launch ----------------
extern "C" void kernel_launch(void* const* d_in, const int* in_sizes, int n_in,
                              void* d_out, int out_size)
{
    const float* src     = (const float*)d_in[0];
    const float* pos     = (const float*)d_in[1];
    const float* boxf    = (const float*)d_in[2];
    const float* boxp    = (const float*)d_in[3];
    const int*   vcoords = (const int*)  d_in[4];
    const int*   bcoords = (const int*)  d_in[5];
    const int*   vinds   = (const int*)  d_in[6];
    const float* Wq = (const float*)d_in[7];  const float* bq  = (const float*)d_in[8];
    const float* Wk = (const float*)d_in[9];  const float* bk  = (const float*)d_in[10];
    const float* Wv = (const float*)d_in[11]; const float* bv  = (const float*)d_in[12];
    const float* Wo = (const float*)d_in[13]; const float* bo  = (const float*)d_in[14];
    const float* W1 = (const float*)d_in[15]; const float* b1  = (const float*)d_in[16];
    const float* W2 = (const float*)d_in[17]; const float* b2  = (const float*)d_in[18];
    const float* g1 = (const float*)d_in[19]; const float* be1 = (const float*)d_in[20];
    const float* g2 = (const float*)d_in[21]; const float* be2 = (const float*)d_in[22];
    float* out = (float*)d_out;

    float *qb, *projb, *xb, *yb, *kb, *vb;
    int* fpb;
    __half *qinh, *ctxh, *xh, *hh, *wh;
    cudaGetSymbolAddress((void**)&qb,    g_q);
    cudaGetSymbolAddress((void**)&projb, g_proj);
    cudaGetSymbolAddress((void**)&xb,    g_x);
    cudaGetSymbolAddress((void**)&yb,    g_y);
    cudaGetSymbolAddress((void**)&kb,    g_k);
    cudaGetSymbolAddress((void**)&vb,    g_v);
    cudaGetSymbolAddress((void**)&fpb,   g_fp);
    cudaGetSymbolAddress((void**)&qinh,  g_qinh);
    cudaGetSymbolAddress((void**)&ctxh,  g_ctxh);
    cudaGetSymbolAddress((void**)&xh,    g_xh);
    cudaGetSymbolAddress((void**)&hh,    g_hh);
    cudaGetSymbolAddress((void**)&wh,    g_wh);

    cudaFuncSetAttribute(attn_kernel, cudaFuncAttributeMaxDynamicSharedMemorySize, ATTN_SMEM);

    const int MB = N_PTS / 128;   // 720

    // conversions
    {
        const int n4 = N_PTS * D_DIM / 4;
        add_half_kernel<<<(n4 + 255)/256, 256>>>(src, pos, qinh, n4);
    }
    cvt_half_kernel<<<36864/4/256,  256>>>(Wq, wh + WOFF_Q, 36864/4);
    cvt_half_kernel<<<36864/4/256,  256>>>(Wo, wh + WOFF_O, 36864/4);
    cvt_half_kernel<<<147456/4/256, 256>>>(W1, wh + WOFF_1, 147456/4);
    cvt_half_kernel<<<147456/4/256, 256>>>(W2, wh + WOFF_2, 147456/4);

    // K/V projections (tiny, SIMT fp32)
    gemm_kernel<false, true ><<<dim3(D_DIM/BN, M_BOX/BM), 256>>>(boxf, boxp,    Wk, bk, kb, BD_DIM, D_DIM);
    gemm_kernel<false, false><<<dim3(D_DIM/BN, M_BOX/BM), 256>>>(boxf, nullptr, Wv, bv, vb, BD_DIM, D_DIM);

    // Q = (src + pos) @ Wq^T + bq (fp16 tensor cores)
    hgemm<false, false><<<dim3(D_DIM/64, MB), 256>>>(qinh, wh + WOFF_Q, bq, qb, nullptr, D_DIM, D_DIM);

    // fused masked attention (writes half ctx)
    attn_kernel<<<dim3(S_SETS, H_HEADS), 256, ATTN_SMEM>>>(qb, kb, vb, vinds, vcoords, bcoords, ctxh);

    // O projection
    hgemm<false, false><<<dim3(D_DIM/64, MB), 256>>>(ctxh, wh + WOFF_O, bo, projb, nullptr, D_DIM, D_DIM);

    // first-occurrence scatter index
    init_fp_kernel<<<N_PTS / 256, 256>>>(fpb);
    fill_fp_kernel<<<(S_SETS * L_LEN) / 256, 256>>>(vinds, fpb);

    // x = LN(src + proj[first_pos]) (+ half copy)
    ln_kernel<true, true><<<N_PTS / 8, 256>>>(src, projb, fpb, g1, be1, xb, xh);

    // FFN
    hgemm<true,  true ><<<dim3(FF_DIM/64, MB), 256>>>(xh, wh + WOFF_1, b1, nullptr, hh, D_DIM, FF_DIM);
    hgemm<false, false><<<dim3(D_DIM/64, MB), 256>>>(hh, wh + WOFF_2, b2, yb, nullptr, FF_DIM, D_DIM);

    // out = LN(x + ffn)
    ln_kernel<false, false><<<N_PTS / 8, 256>>>(xb, yb, nullptr, g2, be2, out, nullptr);
}

// round 6
// speedup vs baseline: 1.5162x; 1.5162x over previous
#include <cuda_runtime.h>
#include <cuda_fp16.h>
#include <math_constants.h>
#include <cstdint>

#define N_PTS   92160
#define D_DIM   192
#define BD_DIM  256
#define H_HEADS 8
#define FF_DIM  768
#define S_SETS  2560
#define L_LEN   36
#define M_BOX   256
#define HD_DIM  24

// ---------------- scratch (static device globals; no allocation) ----------------
__device__ float g_q[N_PTS * D_DIM];
__device__ float g_proj[N_PTS * D_DIM];
__device__ float g_x[N_PTS * D_DIM];
__device__ float g_y[N_PTS * D_DIM];
__device__ float g_k[M_BOX * D_DIM];
__device__ float g_v[M_BOX * D_DIM];
__device__ int   g_fp[N_PTS];

__device__ __half g_qinh[N_PTS * D_DIM];
__device__ __half g_ctxh[N_PTS * D_DIM];
__device__ __half g_xh[N_PTS * D_DIM];
__device__ __half g_hh[(size_t)N_PTS * FF_DIM];
#define WOFF_Q 0
#define WOFF_O 36864
#define WOFF_1 73728
#define WOFF_2 221184
__device__ __half g_wh[368640];

// ================= fp16 mma.sync GEMM: C = A @ W^T + bias =================
// A: (Mrows, K) half row-major, W: (Dout, K) half row-major.
// CTA tile 128 x 64, BK = 32, 256 threads = 8 warps (4m x 2n), warp tile 32 x 32.
// Double-buffered smem, ONE __syncthreads per K-chunk.
#define HPAD 40

__device__ __forceinline__ void mma16816(float* d, const uint32_t* a, const uint32_t* b) {
    asm volatile(
        "mma.sync.aligned.m16n8k16.row.col.f32.f16.f16.f32 "
        "{%0,%1,%2,%3}, {%4,%5,%6,%7}, {%8,%9}, {%0,%1,%2,%3};\n"
        : "+f"(d[0]), "+f"(d[1]), "+f"(d[2]), "+f"(d[3])
        : "r"(a[0]), "r"(a[1]), "r"(a[2]), "r"(a[3]), "r"(b[0]), "r"(b[1]));
}

template<bool RELU, bool OUTH>
__global__ __launch_bounds__(256)
void hgemm(const __half* __restrict__ A, const __half* __restrict__ W,
           const float* __restrict__ bias, float* __restrict__ C,
           __half* __restrict__ Ch, int K, int Dout)
{
    __shared__ __half sb[2][192 * HPAD];

    const int tid  = threadIdx.x;
    const int lane = tid & 31;
    const int wid  = tid >> 5;
    const int wm   = wid & 3;          // 0..3 -> 32-row band
    const int wn   = wid >> 2;         // 0..1 -> 32-col band
    const int m0   = blockIdx.y * 128;
    const int n0   = blockIdx.x * 64;
    const int lr   = lane >> 2;        // 0..7
    const int lc2  = (lane & 3) * 2;   // 0,2,4,6

    // global->smem mapping (16B chunks): rows r0, r0+64 of A; row r0 of W
    const int r0 = tid >> 2;           // 0..63
    const int c8 = (tid & 3) * 8;      // 0,8,16,24
    const __half* gA0 = A + (size_t)(m0 + r0)      * K + c8;
    const __half* gA1 = A + (size_t)(m0 + r0 + 64) * K + c8;
    const __half* gW  = W + (size_t)(n0 + r0)      * K + c8;
    const int s0 = r0 * HPAD + c8;
    const int s1 = (r0 + 64) * HPAD + c8;
    const int s2 = (r0 + 128) * HPAD + c8;

    const int nT = K >> 5;

    uint4 pa0 = *(const uint4*)gA0;
    uint4 pa1 = *(const uint4*)gA1;
    uint4 pw  = *(const uint4*)gW;

    float acc[2][4][4];
    #pragma unroll
    for (int i = 0; i < 2; i++)
        #pragma unroll
        for (int j = 0; j < 4; j++)
            #pragma unroll
            for (int e = 0; e < 4; e++) acc[i][j][e] = 0.f;

    // stage 0 store
    *(uint4*)(sb[0] + s0) = pa0;
    *(uint4*)(sb[0] + s1) = pa1;
    *(uint4*)(sb[0] + s2) = pw;

    for (int t = 0; t < nT; ++t) {
        __syncthreads();   // buf[t&1] fully written; prior reads of buf[(t+1)&1] finished

        if (t + 1 < nT) {
            const int off = (t + 1) * 32;
            pa0 = *(const uint4*)(gA0 + off);
            pa1 = *(const uint4*)(gA1 + off);
            pw  = *(const uint4*)(gW  + off);
        }

        const __half* As = sb[t & 1];
        const __half* Ws = As + 128 * HPAD;

        #pragma unroll
        for (int ks = 0; ks < 32; ks += 16) {
            uint32_t af[2][4], bf[4][2];
            #pragma unroll
            for (int i = 0; i < 2; i++) {
                const int base = (wm * 32 + i * 16 + lr) * HPAD + ks + lc2;
                af[i][0] = *(const uint32_t*)(As + base);
                af[i][1] = *(const uint32_t*)(As + base + 8 * HPAD);
                af[i][2] = *(const uint32_t*)(As + base + 8);
                af[i][3] = *(const uint32_t*)(As + base + 8 * HPAD + 8);
            }
            #pragma unroll
            for (int j = 0; j < 4; j++) {
                const int base = (wn * 32 + j * 8 + lr) * HPAD + ks + lc2;
                bf[j][0] = *(const uint32_t*)(Ws + base);
                bf[j][1] = *(const uint32_t*)(Ws + base + 8);
            }
            #pragma unroll
            for (int i = 0; i < 2; i++)
                #pragma unroll
                for (int j = 0; j < 4; j++)
                    mma16816(acc[i][j], af[i], bf[j]);
        }

        // store prefetched chunk into the other buffer (not read this iteration)
        if (t + 1 < nT) {
            __half* nb = sb[(t + 1) & 1];
            *(uint4*)(nb + s0) = pa0;
            *(uint4*)(nb + s1) = pa1;
            *(uint4*)(nb + s2) = pw;
        }
    }

    // epilogue: direct stores, bias preloaded per thread
    float2 bx[4];
    #pragma unroll
    for (int j = 0; j < 4; j++) {
        const int cj = n0 + wn * 32 + j * 8 + lc2;
        bx[j] = *(const float2*)(bias + cj);
    }
    #pragma unroll
    for (int i = 0; i < 2; i++) {
        const int r = m0 + wm * 32 + i * 16 + lr;
        #pragma unroll
        for (int j = 0; j < 4; j++) {
            const int cj = n0 + wn * 32 + j * 8 + lc2;
            float v0 = acc[i][j][0] + bx[j].x;
            float v1 = acc[i][j][1] + bx[j].y;
            float v2 = acc[i][j][2] + bx[j].x;
            float v3 = acc[i][j][3] + bx[j].y;
            if (RELU) {
                v0 = fmaxf(v0, 0.f); v1 = fmaxf(v1, 0.f);
                v2 = fmaxf(v2, 0.f); v3 = fmaxf(v3, 0.f);
            }
            if (OUTH) {
                *(__half2*)(Ch + (size_t)r       * Dout + cj) = __floats2half2_rn(v0, v1);
                *(__half2*)(Ch + (size_t)(r + 8) * Dout + cj) = __floats2half2_rn(v2, v3);
            } else {
                *(float2*)(C + (size_t)r       * Dout + cj) = make_float2(v0, v1);
                *(float2*)(C + (size_t)(r + 8) * Dout + cj) = make_float2(v2, v3);
            }
        }
    }
}

// ---------------- small SIMT GEMM for K/V projections ----------------
#define BM 128
#define BN 64
#define BK 16

template<bool RELU, bool ADD2>
__global__ __launch_bounds__(256, 2)
void gemm_kernel(const float* __restrict__ A, const float* __restrict__ A2,
                 const float* __restrict__ W, const float* __restrict__ bias,
                 float* __restrict__ C, int K, int Dout)
{
    __shared__ float As[BK][BM + 4];
    __shared__ float Ws[BK][BN + 4];

    const int tid = threadIdx.x;
    const int tx = tid & 15;
    const int ty = tid >> 4;
    const int m0 = blockIdx.y * BM;
    const int n0 = blockIdx.x * BN;

    const int ar = tid >> 2;
    const int ac = (tid & 3) << 2;

    const float* Ap0  = A  + (size_t)(m0 + ar)      * K + ac;
    const float* Ap1  = A  + (size_t)(m0 + ar + 64) * K + ac;
    const float* A2p0 = ADD2 ? (A2 + (size_t)(m0 + ar)      * K + ac) : nullptr;
    const float* A2p1 = ADD2 ? (A2 + (size_t)(m0 + ar + 64) * K + ac) : nullptr;
    const float* Wp   = W  + (size_t)(n0 + ar)      * K + ac;

    const int nT = K / BK;

    float4 pa0 = *(const float4*)(Ap0);
    float4 pa1 = *(const float4*)(Ap1);
    float4 pw  = *(const float4*)(Wp);
    if (ADD2) {
        float4 q0 = *(const float4*)(A2p0);
        float4 q1 = *(const float4*)(A2p1);
        pa0.x += q0.x; pa0.y += q0.y; pa0.z += q0.z; pa0.w += q0.w;
        pa1.x += q1.x; pa1.y += q1.y; pa1.z += q1.z; pa1.w += q1.w;
    }

    float acc[8][4];
    #pragma unroll
    for (int i = 0; i < 8; i++)
        #pragma unroll
        for (int j = 0; j < 4; j++) acc[i][j] = 0.f;

    for (int t = 0; t < nT; ++t) {
        As[ac+0][ar]    = pa0.x; As[ac+1][ar]    = pa0.y;
        As[ac+2][ar]    = pa0.z; As[ac+3][ar]    = pa0.w;
        As[ac+0][ar+64] = pa1.x; As[ac+1][ar+64] = pa1.y;
        As[ac+2][ar+64] = pa1.z; As[ac+3][ar+64] = pa1.w;
        Ws[ac+0][ar]    = pw.x;  Ws[ac+1][ar]    = pw.y;
        Ws[ac+2][ar]    = pw.z;  Ws[ac+3][ar]    = pw.w;
        __syncthreads();

        if (t + 1 < nT) {
            const int off = (t + 1) * BK;
            pa0 = *(const float4*)(Ap0 + off);
            pa1 = *(const float4*)(Ap1 + off);
            pw  = *(const float4*)(Wp  + off);
            if (ADD2) {
                float4 q0 = *(const float4*)(A2p0 + off);
                float4 q1 = *(const float4*)(A2p1 + off);
                pa0.x += q0.x; pa0.y += q0.y; pa0.z += q0.z; pa0.w += q0.w;
                pa1.x += q1.x; pa1.y += q1.y; pa1.z += q1.z; pa1.w += q1.w;
            }
        }

        #pragma unroll
        for (int k = 0; k < BK; ++k) {
            float a[8], w[4];
            #pragma unroll
            for (int i = 0; i < 8; i++) a[i] = As[k][ty * 8 + i];
            #pragma unroll
            for (int j = 0; j < 4; j++) w[j] = Ws[k][tx * 4 + j];
            #pragma unroll
            for (int i = 0; i < 8; i++)
                #pragma unroll
                for (int j = 0; j < 4; j++) acc[i][j] += a[i] * w[j];
        }
        __syncthreads();
    }

    const float b0 = bias[n0 + tx*4 + 0];
    const float b1 = bias[n0 + tx*4 + 1];
    const float b2 = bias[n0 + tx*4 + 2];
    const float b3 = bias[n0 + tx*4 + 3];
    #pragma unroll
    for (int i = 0; i < 8; i++) {
        float4 o;
        o.x = acc[i][0] + b0; o.y = acc[i][1] + b1;
        o.z = acc[i][2] + b2; o.w = acc[i][3] + b3;
        if (RELU) {
            o.x = fmaxf(o.x, 0.f); o.y = fmaxf(o.y, 0.f);
            o.z = fmaxf(o.z, 0.f); o.w = fmaxf(o.w, 0.f);
        }
        *(float4*)(C + (size_t)(m0 + ty*8 + i) * Dout + n0 + tx*4) = o;
    }
}

// ---------------- fused attention: one CTA per (set, head), writes half ctx ----------------
#define ATTN_SMEM ((L_LEN*HD_DIM + M_BOX*HD_DIM + L_LEN*M_BOX) * 4 + L_LEN * 4)

__global__ __launch_bounds__(256)
void attn_kernel(const float* __restrict__ qbuf, const float* __restrict__ kbuf,
                 const float* __restrict__ vbuf, const int* __restrict__ vinds,
                 const int* __restrict__ vcoords, const int* __restrict__ bcoords,
                 __half* __restrict__ ctxh)
{
    extern __shared__ float smf[];
    float* qs = smf;
    float* vs = qs + L_LEN * HD_DIM;
    float* sc = vs + M_BOX * HD_DIM;
    int*   qb = (int*)(sc + L_LEN * M_BOX);

    const int s = blockIdx.x;
    const int h = blockIdx.y;
    const int t = threadIdx.x;

    float kr[HD_DIM];
    {
        const float4* kp = (const float4*)(kbuf + (size_t)t * D_DIM + h * HD_DIM);
        const float4* vp = (const float4*)(vbuf + (size_t)t * D_DIM + h * HD_DIM);
        #pragma unroll
        for (int i = 0; i < 6; i++) {
            float4 f = kp[i];
            kr[4*i+0] = f.x; kr[4*i+1] = f.y; kr[4*i+2] = f.z; kr[4*i+3] = f.w;
            float4 g = vp[i];
            vs[t*HD_DIM + 4*i + 0] = g.x; vs[t*HD_DIM + 4*i + 1] = g.y;
            vs[t*HD_DIM + 4*i + 2] = g.z; vs[t*HD_DIM + 4*i + 3] = g.w;
        }
    }
    const int bb = bcoords[t * 4];

    if (t < L_LEN) qb[t] = vcoords[(size_t)vinds[s * L_LEN + t] * 4];
    for (int i = t; i < L_LEN * HD_DIM; i += 256) {
        int l = i / HD_DIM, dd = i % HD_DIM;
        qs[i] = qbuf[(size_t)vinds[s * L_LEN + l] * D_DIM + h * HD_DIM + dd];
    }
    __syncthreads();

    const float scale = 0.20412414523193154f;
    #pragma unroll 2
    for (int l = 0; l < L_LEN; l++) {
        const float* qr = qs + l * HD_DIM;
        float dot = 0.f;
        #pragma unroll
        for (int j = 0; j < HD_DIM; j++) dot += qr[j] * kr[j];
        sc[l * M_BOX + t] = (qb[l] != bb) ? -CUDART_INF_F : dot * scale;
    }
    __syncthreads();

    const int w = t >> 5, lane = t & 31;
    for (int l = w; l < L_LEN; l += 8) {
        float* row = sc + l * M_BOX;
        float e[8];
        float mx = -CUDART_INF_F;
        #pragma unroll
        for (int i = 0; i < 8; i++) { e[i] = row[lane + 32*i]; mx = fmaxf(mx, e[i]); }
        #pragma unroll
        for (int o = 16; o > 0; o >>= 1) mx = fmaxf(mx, __shfl_xor_sync(0xffffffffu, mx, o));
        float sum = 0.f;
        if (mx > -CUDART_INF_F) {
            #pragma unroll
            for (int i = 0; i < 8; i++) { e[i] = __expf(e[i] - mx); sum += e[i]; }
        } else {
            #pragma unroll
            for (int i = 0; i < 8; i++) e[i] = 0.f;
        }
        #pragma unroll
        for (int o = 16; o > 0; o >>= 1) sum += __shfl_xor_sync(0xffffffffu, sum, o);
        const float inv = sum > 0.f ? 1.0f / sum : 0.f;
        #pragma unroll
        for (int i = 0; i < 8; i++) row[lane + 32*i] = e[i] * inv;
    }
    __syncthreads();

    if (lane < HD_DIM) {
        const float* s0 = sc + (w +  0) * M_BOX;
        const float* s1 = sc + (w +  8) * M_BOX;
        const float* s2 = sc + (w + 16) * M_BOX;
        const float* s3 = sc + (w + 24) * M_BOX;
        const bool has5 = (w < L_LEN - 32);
        const float* s4 = has5 ? (sc + (w + 32) * M_BOX) : s0;
        float a0 = 0.f, a1 = 0.f, a2 = 0.f, a3 = 0.f, a4 = 0.f;
        #pragma unroll 2
        for (int m = 0; m < M_BOX; m++) {
            const float vv = vs[m * HD_DIM + lane];
            a0 += s0[m] * vv;
            a1 += s1[m] * vv;
            a2 += s2[m] * vv;
            a3 += s3[m] * vv;
            if (has5) a4 += s4[m] * vv;
        }
        const size_t base = (size_t)s * L_LEN;
        const int    off  = h * HD_DIM + lane;
        ctxh[(base + w +  0) * D_DIM + off] = __float2half(a0);
        ctxh[(base + w +  8) * D_DIM + off] = __float2half(a1);
        ctxh[(base + w + 16) * D_DIM + off] = __float2half(a2);
        ctxh[(base + w + 24) * D_DIM + off] = __float2half(a3);
        if (has5) ctxh[(base + w + 32) * D_DIM + off] = __float2half(a4);
    }
}

// ---------------- first-occurrence scatter index ----------------
__global__ void init_fp_kernel(int* __restrict__ fp)
{
    int i = blockIdx.x * blockDim.x + threadIdx.x;
    if (i < N_PTS) fp[i] = 0x7FFFFFFF;
}

__global__ void fill_fp_kernel(const int* __restrict__ vinds, int* __restrict__ fp)
{
    int p = blockIdx.x * blockDim.x + threadIdx.x;
    if (p < S_SETS * L_LEN) {
        int n = vinds[p];
        if (n >= 0 && n < N_PTS) atomicMin(&fp[n], p);
    }
}

// ---------------- residual + layernorm (warp per row) ----------------
template<bool GATHER, bool OUTH>
__global__ __launch_bounds__(256)
void ln_kernel(const float* __restrict__ a, const float* __restrict__ b,
               const int* __restrict__ fp, const float* __restrict__ gamma,
               const float* __restrict__ beta, float* __restrict__ outp,
               __half* __restrict__ oh)
{
    const int row  = (blockIdx.x * 256 + threadIdx.x) >> 5;
    const int lane = threadIdx.x & 31;
    if (row >= N_PTS) return;

    const float* arow = a + (size_t)row * D_DIM;
    const float* brow;
    if (GATHER) {
        int p = fp[row];
        if (p < 0 || p >= N_PTS) p = row;
        brow = b + (size_t)p * D_DIM;
    } else {
        brow = b + (size_t)row * D_DIM;
    }

    float v[6];
    float s = 0.f;
    #pragma unroll
    for (int i = 0; i < 6; i++) {
        const int idx = lane + 32 * i;
        v[i] = arow[idx] + brow[idx];
        s += v[i];
    }
    #pragma unroll
    for (int o = 16; o > 0; o >>= 1) s += __shfl_xor_sync(0xffffffffu, s, o);
    const float mean = s * (1.0f / D_DIM);

    float q = 0.f;
    #pragma unroll
    for (int i = 0; i < 6; i++) { const float d = v[i] - mean; q += d * d; }
    #pragma unroll
    for (int o = 16; o > 0; o >>= 1) q += __shfl_xor_sync(0xffffffffu, q, o);
    const float inv = rsqrtf(q * (1.0f / D_DIM) + 1e-5f);

    float* orow = outp + (size_t)row * D_DIM;
    #pragma unroll
    for (int i = 0; i < 6; i++) {
        const int idx = lane + 32 * i;
        const float val = (v[i] - mean) * inv * gamma[idx] + beta[idx];
        orow[idx] = val;
        if (OUTH) oh[(size_t)row * D_DIM + idx] = __float2half(val);
    }
}

// ---------------- conversion kernels ----------------
__global__ void add_half_kernel(const float* __restrict__ a, const float* __restrict__ b,
                                __half* __restrict__ c, int n4)
{
    int i = blockIdx.x * blockDim.x + threadIdx.x;
    if (i >= n4) return;
    float4 x = ((const float4*)a)[i];
    float4 y = ((const float4*)b)[i];
    ((__half2*)c)[2*i]   = __floats2half2_rn(x.x + y.x, x.y + y.y);
    ((__half2*)c)[2*i+1] = __floats2half2_rn(x.z + y.z, x.w + y.w);
}

// one kernel converts all four weight matrices
__global__ void cvt_weights_kernel(const float* __restrict__ Wq, const float* __restrict__ Wo,
                                   const float* __restrict__ W1, const float* __restrict__ W2,
                                   __half* __restrict__ wh)
{
    const int i = blockIdx.x * blockDim.x + threadIdx.x;   // float4 index over 368640 elems
    const int n4 = 368640 / 4;                             // 92160
    if (i >= n4) return;
    const int e = i * 4;
    const float* srcp;
    int off;
    if (e < WOFF_O)        { srcp = Wq; off = e - WOFF_Q; }
    else if (e < WOFF_1)   { srcp = Wo; off = e - WOFF_O; }
    else if (e < WOFF_2)   { srcp = W1; off = e - WOFF_1; }
    else                   { srcp = W2; off = e - WOFF_2; }
    float4 x = *(const float4*)(srcp + off);
    ((__half2*)wh)[2*i]   = __floats2half2_rn(x.x, x.y);
    ((__half2*)wh)[2*i+1] = __floats2half2_rn(x.z, x.w);
}

// ---------------- launch ----------------
extern "C" void kernel_launch(void* const* d_in, const int* in_sizes, int n_in,
                              void* d_out, int out_size)
{
    const float* src     = (const float*)d_in[0];
    const float* pos     = (const float*)d_in[1];
    const float* boxf    = (const float*)d_in[2];
    const float* boxp    = (const float*)d_in[3];
    const int*   vcoords = (const int*)  d_in[4];
    const int*   bcoords = (const int*)  d_in[5];
    const int*   vinds   = (const int*)  d_in[6];
    const float* Wq = (const float*)d_in[7];  const float* bq  = (const float*)d_in[8];
    const float* Wk = (const float*)d_in[9];  const float* bk  = (const float*)d_in[10];
    const float* Wv = (const float*)d_in[11]; const float* bv  = (const float*)d_in[12];
    const float* Wo = (const float*)d_in[13]; const float* bo  = (const float*)d_in[14];
    const float* W1 = (const float*)d_in[15]; const float* b1  = (const float*)d_in[16];
    const float* W2 = (const float*)d_in[17]; const float* b2  = (const float*)d_in[18];
    const float* g1 = (const float*)d_in[19]; const float* be1 = (const float*)d_in[20];
    const float* g2 = (const float*)d_in[21]; const float* be2 = (const float*)d_in[22];
    float* out = (float*)d_out;

    float *qb, *projb, *xb, *yb, *kb, *vb;
    int* fpb;
    __half *qinh, *ctxh, *xh, *hh, *wh;
    cudaGetSymbolAddress((void**)&qb,    g_q);
    cudaGetSymbolAddress((void**)&projb, g_proj);
    cudaGetSymbolAddress((void**)&xb,    g_x);
    cudaGetSymbolAddress((void**)&yb,    g_y);
    cudaGetSymbolAddress((void**)&kb,    g_k);
    cudaGetSymbolAddress((void**)&vb,    g_v);
    cudaGetSymbolAddress((void**)&fpb,   g_fp);
    cudaGetSymbolAddress((void**)&qinh,  g_qinh);
    cudaGetSymbolAddress((void**)&ctxh,  g_ctxh);
    cudaGetSymbolAddress((void**)&xh,    g_xh);
    cudaGetSymbolAddress((void**)&hh,    g_hh);
    cudaGetSymbolAddress((void**)&wh,    g_wh);

    cudaFuncSetAttribute(attn_kernel, cudaFuncAttributeMaxDynamicSharedMemorySize, ATTN_SMEM);

    const int MB = N_PTS / 128;   // 720

    // conversions
    {
        const int n4 = N_PTS * D_DIM / 4;
        add_half_kernel<<<(n4 + 255)/256, 256>>>(src, pos, qinh, n4);
    }
    cvt_weights_kernel<<<(368640/4 + 255)/256, 256>>>(Wq, Wo, W1, W2, wh);

    // K/V projections (tiny, SIMT fp32)
    gemm_kernel<false, true ><<<dim3(D_DIM/BN, M_BOX/BM), 256>>>(boxf, boxp,    Wk, bk, kb, BD_DIM, D_DIM);
    gemm_kernel<false, false><<<dim3(D_DIM/BN, M_BOX/BM), 256>>>(boxf, nullptr, Wv, bv, vb, BD_DIM, D_DIM);

    // Q = (src + pos) @ Wq^T + bq (fp16 tensor cores)
    hgemm<false, false><<<dim3(D_DIM/64, MB), 256>>>(qinh, wh + WOFF_Q, bq, qb, nullptr, D_DIM, D_DIM);

    // fused masked attention (writes half ctx)
    attn_kernel<<<dim3(S_SETS, H_HEADS), 256, ATTN_SMEM>>>(qb, kb, vb, vinds, vcoords, bcoords, ctxh);

    // O projection
    hgemm<false, false><<<dim3(D_DIM/64, MB), 256>>>(ctxh, wh + WOFF_O, bo, projb, nullptr, D_DIM, D_DIM);

    // first-occurrence scatter index
    init_fp_kernel<<<N_PTS / 256, 256>>>(fpb);
    fill_fp_kernel<<<(S_SETS * L_LEN) / 256, 256>>>(vinds, fpb);

    // x = LN(src + proj[first_pos]) (+ half copy)
    ln_kernel<true, true><<<N_PTS / 8, 256>>>(src, projb, fpb, g1, be1, xb, xh);

    // FFN
    hgemm<true,  true ><<<dim3(FF_DIM/64, MB), 256>>>(xh, wh + WOFF_1, b1, nullptr, hh, D_DIM, FF_DIM);
    hgemm<false, false><<<dim3(D_DIM/64, MB), 256>>>(hh, wh + WOFF_2, b2, yb, nullptr, FF_DIM, D_DIM);

    // out = LN(x + ffn)
    ln_kernel<false, false><<<N_PTS / 8, 256>>>(xb, yb, nullptr, g2, be2, out, nullptr);
}

// round 7
// speedup vs baseline: 1.5974x; 1.0536x over previous
#include <cuda_runtime.h>
#include <cuda_fp16.h>
#include <math_constants.h>
#include <cstdint>

#define N_PTS   92160
#define D_DIM   192
#define BD_DIM  256
#define H_HEADS 8
#define FF_DIM  768
#define S_SETS  2560
#define L_LEN   36
#define M_BOX   256
#define HD_DIM  24

// ---------------- scratch (static device globals; no allocation) ----------------
__device__ float g_q[N_PTS * D_DIM];
__device__ float g_proj[N_PTS * D_DIM];
__device__ float g_x[N_PTS * D_DIM];
__device__ float g_y[N_PTS * D_DIM];
__device__ float g_k[M_BOX * D_DIM];
__device__ float g_v[M_BOX * D_DIM];
__device__ int   g_fp[N_PTS];

__device__ __half g_ctxh[N_PTS * D_DIM];
__device__ __half g_xh[N_PTS * D_DIM];
__device__ __half g_hh[(size_t)N_PTS * FF_DIM];
#define WOFF_Q 0
#define WOFF_O 36864
#define WOFF_1 73728
#define WOFF_2 221184
__device__ __half g_wh[368640];

// ================= fp16 mma.sync GEMM: C = A @ W^T + bias =================
// A: (Mrows, K) half row-major (or ADDIN: two fp32 arrays summed+converted on load),
// W: (Dout, K) half row-major. CTA tile 128 x 64, BK = 32, 256 threads = 8 warps.
// Double-buffered smem, one __syncthreads per K-chunk.
#define HPAD 40

__device__ __forceinline__ void mma16816(float* d, const uint32_t* a, const uint32_t* b) {
    asm volatile(
        "mma.sync.aligned.m16n8k16.row.col.f32.f16.f16.f32 "
        "{%0,%1,%2,%3}, {%4,%5,%6,%7}, {%8,%9}, {%0,%1,%2,%3};\n"
        : "+f"(d[0]), "+f"(d[1]), "+f"(d[2]), "+f"(d[3])
        : "r"(a[0]), "r"(a[1]), "r"(a[2]), "r"(a[3]), "r"(b[0]), "r"(b[1]));
}

__device__ __forceinline__ uint4 add_cvt8(const float* p, const float* q) {
    float4 x0 = *(const float4*)p;
    float4 x1 = *(const float4*)(p + 4);
    float4 y0 = *(const float4*)q;
    float4 y1 = *(const float4*)(q + 4);
    __half2 h0 = __floats2half2_rn(x0.x + y0.x, x0.y + y0.y);
    __half2 h1 = __floats2half2_rn(x0.z + y0.z, x0.w + y0.w);
    __half2 h2 = __floats2half2_rn(x1.x + y1.x, x1.y + y1.y);
    __half2 h3 = __floats2half2_rn(x1.z + y1.z, x1.w + y1.w);
    uint4 r;
    r.x = *(uint32_t*)&h0; r.y = *(uint32_t*)&h1;
    r.z = *(uint32_t*)&h2; r.w = *(uint32_t*)&h3;
    return r;
}

template<bool RELU, bool OUTH, bool ADDIN>
__global__ __launch_bounds__(256)
void hgemm(const __half* __restrict__ A, const float* __restrict__ Af, const float* __restrict__ Af2,
           const __half* __restrict__ W, const float* __restrict__ bias,
           float* __restrict__ C, __half* __restrict__ Ch, int K, int Dout)
{
    __shared__ __half sb[2][192 * HPAD];

    const int tid  = threadIdx.x;
    const int lane = tid & 31;
    const int wid  = tid >> 5;
    const int wm   = wid & 3;
    const int wn   = wid >> 2;
    const int m0   = blockIdx.y * 128;
    const int n0   = blockIdx.x * 64;
    const int lr   = lane >> 2;
    const int lc2  = (lane & 3) * 2;

    const int r0 = tid >> 2;           // 0..63
    const int c8 = (tid & 3) * 8;      // 0,8,16,24
    const size_t oA0 = (size_t)(m0 + r0)      * K + c8;
    const size_t oA1 = (size_t)(m0 + r0 + 64) * K + c8;
    const __half* gW = W + (size_t)(n0 + r0) * K + c8;
    const int s0 = r0 * HPAD + c8;
    const int s1 = (r0 + 64) * HPAD + c8;
    const int s2 = (r0 + 128) * HPAD + c8;

    const int nT = K >> 5;

    uint4 pa0, pa1, pw;
    if (ADDIN) {
        pa0 = add_cvt8(Af + oA0, Af2 + oA0);
        pa1 = add_cvt8(Af + oA1, Af2 + oA1);
    } else {
        pa0 = *(const uint4*)(A + oA0);
        pa1 = *(const uint4*)(A + oA1);
    }
    pw = *(const uint4*)gW;

    float acc[2][4][4];
    #pragma unroll
    for (int i = 0; i < 2; i++)
        #pragma unroll
        for (int j = 0; j < 4; j++)
            #pragma unroll
            for (int e = 0; e < 4; e++) acc[i][j][e] = 0.f;

    *(uint4*)(sb[0] + s0) = pa0;
    *(uint4*)(sb[0] + s1) = pa1;
    *(uint4*)(sb[0] + s2) = pw;

    for (int t = 0; t < nT; ++t) {
        __syncthreads();

        if (t + 1 < nT) {
            const int off = (t + 1) * 32;
            if (ADDIN) {
                pa0 = add_cvt8(Af + oA0 + off, Af2 + oA0 + off);
                pa1 = add_cvt8(Af + oA1 + off, Af2 + oA1 + off);
            } else {
                pa0 = *(const uint4*)(A + oA0 + off);
                pa1 = *(const uint4*)(A + oA1 + off);
            }
            pw = *(const uint4*)(gW + off);
        }

        const __half* As = sb[t & 1];
        const __half* Ws = As + 128 * HPAD;

        #pragma unroll
        for (int ks = 0; ks < 32; ks += 16) {
            uint32_t af[2][4], bf[4][2];
            #pragma unroll
            for (int i = 0; i < 2; i++) {
                const int base = (wm * 32 + i * 16 + lr) * HPAD + ks + lc2;
                af[i][0] = *(const uint32_t*)(As + base);
                af[i][1] = *(const uint32_t*)(As + base + 8 * HPAD);
                af[i][2] = *(const uint32_t*)(As + base + 8);
                af[i][3] = *(const uint32_t*)(As + base + 8 * HPAD + 8);
            }
            #pragma unroll
            for (int j = 0; j < 4; j++) {
                const int base = (wn * 32 + j * 8 + lr) * HPAD + ks + lc2;
                bf[j][0] = *(const uint32_t*)(Ws + base);
                bf[j][1] = *(const uint32_t*)(Ws + base + 8);
            }
            #pragma unroll
            for (int i = 0; i < 2; i++)
                #pragma unroll
                for (int j = 0; j < 4; j++)
                    mma16816(acc[i][j], af[i], bf[j]);
        }

        if (t + 1 < nT) {
            __half* nb = sb[(t + 1) & 1];
            *(uint4*)(nb + s0) = pa0;
            *(uint4*)(nb + s1) = pa1;
            *(uint4*)(nb + s2) = pw;
        }
    }

    float2 bx[4];
    #pragma unroll
    for (int j = 0; j < 4; j++) {
        const int cj = n0 + wn * 32 + j * 8 + lc2;
        bx[j] = *(const float2*)(bias + cj);
    }
    #pragma unroll
    for (int i = 0; i < 2; i++) {
        const int r = m0 + wm * 32 + i * 16 + lr;
        #pragma unroll
        for (int j = 0; j < 4; j++) {
            const int cj = n0 + wn * 32 + j * 8 + lc2;
            float v0 = acc[i][j][0] + bx[j].x;
            float v1 = acc[i][j][1] + bx[j].y;
            float v2 = acc[i][j][2] + bx[j].x;
            float v3 = acc[i][j][3] + bx[j].y;
            if (RELU) {
                v0 = fmaxf(v0, 0.f); v1 = fmaxf(v1, 0.f);
                v2 = fmaxf(v2, 0.f); v3 = fmaxf(v3, 0.f);
            }
            if (OUTH) {
                *(__half2*)(Ch + (size_t)r       * Dout + cj) = __floats2half2_rn(v0, v1);
                *(__half2*)(Ch + (size_t)(r + 8) * Dout + cj) = __floats2half2_rn(v2, v3);
            } else {
                *(float2*)(C + (size_t)r       * Dout + cj) = make_float2(v0, v1);
                *(float2*)(C + (size_t)(r + 8) * Dout + cj) = make_float2(v2, v3);
            }
        }
    }
}

// ---------------- combined K/V projection (SIMT fp32), blockIdx.z selects ----------------
#define BM 128
#define BN 64
#define BK 16

__global__ __launch_bounds__(256, 2)
void gemm_kv(const float* __restrict__ boxf, const float* __restrict__ boxp,
             const float* __restrict__ Wk, const float* __restrict__ bk, float* __restrict__ Ck,
             const float* __restrict__ Wv, const float* __restrict__ bv, float* __restrict__ Cv)
{
    const bool isK = (blockIdx.z == 0);
    const float* A   = boxf;
    const float* A2  = isK ? boxp : nullptr;
    const float* W   = isK ? Wk : Wv;
    const float* bias= isK ? bk : bv;
    float* C         = isK ? Ck : Cv;
    const int K = BD_DIM, Dout = D_DIM;

    __shared__ float As[BK][BM + 4];
    __shared__ float Ws[BK][BN + 4];

    const int tid = threadIdx.x;
    const int tx = tid & 15;
    const int ty = tid >> 4;
    const int m0 = blockIdx.y * BM;
    const int n0 = blockIdx.x * BN;

    const int ar = tid >> 2;
    const int ac = (tid & 3) << 2;

    const float* Ap0 = A + (size_t)(m0 + ar)      * K + ac;
    const float* Ap1 = A + (size_t)(m0 + ar + 64) * K + ac;
    const float* Wp  = W + (size_t)(n0 + ar)      * K + ac;

    const int nT = K / BK;

    float4 pa0 = *(const float4*)(Ap0);
    float4 pa1 = *(const float4*)(Ap1);
    float4 pw  = *(const float4*)(Wp);
    if (isK) {
        const float* B0 = A2 + (size_t)(m0 + ar) * K + ac;
        const float* B1 = A2 + (size_t)(m0 + ar + 64) * K + ac;
        float4 q0 = *(const float4*)B0;
        float4 q1 = *(const float4*)B1;
        pa0.x += q0.x; pa0.y += q0.y; pa0.z += q0.z; pa0.w += q0.w;
        pa1.x += q1.x; pa1.y += q1.y; pa1.z += q1.z; pa1.w += q1.w;
    }

    float acc[8][4];
    #pragma unroll
    for (int i = 0; i < 8; i++)
        #pragma unroll
        for (int j = 0; j < 4; j++) acc[i][j] = 0.f;

    for (int t = 0; t < nT; ++t) {
        As[ac+0][ar]    = pa0.x; As[ac+1][ar]    = pa0.y;
        As[ac+2][ar]    = pa0.z; As[ac+3][ar]    = pa0.w;
        As[ac+0][ar+64] = pa1.x; As[ac+1][ar+64] = pa1.y;
        As[ac+2][ar+64] = pa1.z; As[ac+3][ar+64] = pa1.w;
        Ws[ac+0][ar]    = pw.x;  Ws[ac+1][ar]    = pw.y;
        Ws[ac+2][ar]    = pw.z;  Ws[ac+3][ar]    = pw.w;
        __syncthreads();

        if (t + 1 < nT) {
            const int off = (t + 1) * BK;
            pa0 = *(const float4*)(Ap0 + off);
            pa1 = *(const float4*)(Ap1 + off);
            pw  = *(const float4*)(Wp  + off);
            if (isK) {
                const float* B0 = A2 + (size_t)(m0 + ar) * K + ac + off;
                const float* B1 = A2 + (size_t)(m0 + ar + 64) * K + ac + off;
                float4 q0 = *(const float4*)B0;
                float4 q1 = *(const float4*)B1;
                pa0.x += q0.x; pa0.y += q0.y; pa0.z += q0.z; pa0.w += q0.w;
                pa1.x += q1.x; pa1.y += q1.y; pa1.z += q1.z; pa1.w += q1.w;
            }
        }

        #pragma unroll
        for (int k = 0; k < BK; ++k) {
            float a[8], w[4];
            #pragma unroll
            for (int i = 0; i < 8; i++) a[i] = As[k][ty * 8 + i];
            #pragma unroll
            for (int j = 0; j < 4; j++) w[j] = Ws[k][tx * 4 + j];
            #pragma unroll
            for (int i = 0; i < 8; i++)
                #pragma unroll
                for (int j = 0; j < 4; j++) acc[i][j] += a[i] * w[j];
        }
        __syncthreads();
    }

    const float b0 = bias[n0 + tx*4 + 0];
    const float b1 = bias[n0 + tx*4 + 1];
    const float b2 = bias[n0 + tx*4 + 2];
    const float b3 = bias[n0 + tx*4 + 3];
    #pragma unroll
    for (int i = 0; i < 8; i++) {
        float4 o;
        o.x = acc[i][0] + b0; o.y = acc[i][1] + b1;
        o.z = acc[i][2] + b2; o.w = acc[i][3] + b3;
        *(float4*)(C + (size_t)(m0 + ty*8 + i) * Dout + n0 + tx*4) = o;
    }
}

// ---------------- fused attention: one CTA per (set, head), writes half ctx ----------------
#define ATTN_SMEM ((L_LEN*HD_DIM + M_BOX*HD_DIM + L_LEN*M_BOX) * 4 + L_LEN * 4)

__global__ __launch_bounds__(256)
void attn_kernel(const float* __restrict__ qbuf, const float* __restrict__ kbuf,
                 const float* __restrict__ vbuf, const int* __restrict__ vinds,
                 const int* __restrict__ vcoords, const int* __restrict__ bcoords,
                 __half* __restrict__ ctxh)
{
    extern __shared__ float smf[];
    float* qs = smf;                       // 36*24, rows 96B (16B aligned)
    float* vs = qs + L_LEN * HD_DIM;       // 256*24
    float* sc = vs + M_BOX * HD_DIM;       // 36*256, rows 1KB aligned
    int*   qb = (int*)(sc + L_LEN * M_BOX);

    const int s = blockIdx.x;
    const int h = blockIdx.y;
    const int t = threadIdx.x;

    float kr[HD_DIM];
    {
        const float4* kp = (const float4*)(kbuf + (size_t)t * D_DIM + h * HD_DIM);
        const float4* vp = (const float4*)(vbuf + (size_t)t * D_DIM + h * HD_DIM);
        #pragma unroll
        for (int i = 0; i < 6; i++) {
            float4 f = kp[i];
            kr[4*i+0] = f.x; kr[4*i+1] = f.y; kr[4*i+2] = f.z; kr[4*i+3] = f.w;
            float4 g = vp[i];
            vs[t*HD_DIM + 4*i + 0] = g.x; vs[t*HD_DIM + 4*i + 1] = g.y;
            vs[t*HD_DIM + 4*i + 2] = g.z; vs[t*HD_DIM + 4*i + 3] = g.w;
        }
    }
    const int bb = bcoords[t * 4];

    if (t < L_LEN) qb[t] = vcoords[(size_t)vinds[s * L_LEN + t] * 4];
    for (int i = t; i < L_LEN * HD_DIM; i += 256) {
        int l = i / HD_DIM, dd = i % HD_DIM;
        qs[i] = qbuf[(size_t)vinds[s * L_LEN + l] * D_DIM + h * HD_DIM + dd];
    }
    __syncthreads();

    // scores: thread t owns column m = t; qs rows read as float4 (broadcast)
    const float scale = 0.20412414523193154f;
    #pragma unroll 2
    for (int l = 0; l < L_LEN; l++) {
        const float4* qr = (const float4*)(qs + l * HD_DIM);
        float dot = 0.f;
        #pragma unroll
        for (int i = 0; i < 6; i++) {
            float4 q4 = qr[i];
            dot += q4.x * kr[4*i+0] + q4.y * kr[4*i+1] + q4.z * kr[4*i+2] + q4.w * kr[4*i+3];
        }
        sc[l * M_BOX + t] = (qb[l] != bb) ? -CUDART_INF_F : dot * scale;
    }
    __syncthreads();

    const int w = t >> 5, lane = t & 31;
    for (int l = w; l < L_LEN; l += 8) {
        float* row = sc + l * M_BOX;
        float e[8];
        float mx = -CUDART_INF_F;
        #pragma unroll
        for (int i = 0; i < 8; i++) { e[i] = row[lane + 32*i]; mx = fmaxf(mx, e[i]); }
        #pragma unroll
        for (int o = 16; o > 0; o >>= 1) mx = fmaxf(mx, __shfl_xor_sync(0xffffffffu, mx, o));
        float sum = 0.f;
        if (mx > -CUDART_INF_F) {
            #pragma unroll
            for (int i = 0; i < 8; i++) { e[i] = __expf(e[i] - mx); sum += e[i]; }
        } else {
            #pragma unroll
            for (int i = 0; i < 8; i++) e[i] = 0.f;
        }
        #pragma unroll
        for (int o = 16; o > 0; o >>= 1) sum += __shfl_xor_sync(0xffffffffu, sum, o);
        const float inv = sum > 0.f ? 1.0f / sum : 0.f;
        #pragma unroll
        for (int i = 0; i < 8; i++) row[lane + 32*i] = e[i] * inv;
    }
    __syncthreads();

    // ctx: warp w rows {w, w+8, w+16, w+24, (+w+32)}, lanes 0..23 = d.
    // probability rows read as float4 (broadcast), vs scalar.
    if (lane < HD_DIM) {
        const float* s0 = sc + (w +  0) * M_BOX;
        const float* s1 = sc + (w +  8) * M_BOX;
        const float* s2 = sc + (w + 16) * M_BOX;
        const float* s3 = sc + (w + 24) * M_BOX;
        const bool has5 = (w < L_LEN - 32);
        const float* s4 = has5 ? (sc + (w + 32) * M_BOX) : s0;
        float a0 = 0.f, a1 = 0.f, a2 = 0.f, a3 = 0.f, a4 = 0.f;
        #pragma unroll 2
        for (int m = 0; m < M_BOX; m += 4) {
            const float v0 = vs[(m+0) * HD_DIM + lane];
            const float v1 = vs[(m+1) * HD_DIM + lane];
            const float v2 = vs[(m+2) * HD_DIM + lane];
            const float v3 = vs[(m+3) * HD_DIM + lane];
            float4 p;
            p = *(const float4*)(s0 + m); a0 += p.x*v0 + p.y*v1 + p.z*v2 + p.w*v3;
            p = *(const float4*)(s1 + m); a1 += p.x*v0 + p.y*v1 + p.z*v2 + p.w*v3;
            p = *(const float4*)(s2 + m); a2 += p.x*v0 + p.y*v1 + p.z*v2 + p.w*v3;
            p = *(const float4*)(s3 + m); a3 += p.x*v0 + p.y*v1 + p.z*v2 + p.w*v3;
            if (has5) { p = *(const float4*)(s4 + m); a4 += p.x*v0 + p.y*v1 + p.z*v2 + p.w*v3; }
        }
        const size_t base = (size_t)s * L_LEN;
        const int    off  = h * HD_DIM + lane;
        ctxh[(base + w +  0) * D_DIM + off] = __float2half(a0);
        ctxh[(base + w +  8) * D_DIM + off] = __float2half(a1);
        ctxh[(base + w + 16) * D_DIM + off] = __float2half(a2);
        ctxh[(base + w + 24) * D_DIM + off] = __float2half(a3);
        if (has5) ctxh[(base + w + 32) * D_DIM + off] = __float2half(a4);
    }
}

// ---------------- first-occurrence scatter index ----------------
__global__ void init_fp_kernel(int* __restrict__ fp)
{
    int i = blockIdx.x * blockDim.x + threadIdx.x;
    if (i < N_PTS) fp[i] = 0x7FFFFFFF;
}

__global__ void fill_fp_kernel(const int* __restrict__ vinds, int* __restrict__ fp)
{
    int p = blockIdx.x * blockDim.x + threadIdx.x;
    if (p < S_SETS * L_LEN) {
        int n = vinds[p];
        if (n >= 0 && n < N_PTS) atomicMin(&fp[n], p);
    }
}

// ---------------- residual + layernorm (warp per row) ----------------
template<bool GATHER, bool OUTH>
__global__ __launch_bounds__(256)
void ln_kernel(const float* __restrict__ a, const float* __restrict__ b,
               const int* __restrict__ fp, const float* __restrict__ gamma,
               const float* __restrict__ beta, float* __restrict__ outp,
               __half* __restrict__ oh)
{
    const int row  = (blockIdx.x * 256 + threadIdx.x) >> 5;
    const int lane = threadIdx.x & 31;
    if (row >= N_PTS) return;

    const float* arow = a + (size_t)row * D_DIM;
    const float* brow;
    if (GATHER) {
        int p = fp[row];
        if (p < 0 || p >= N_PTS) p = row;
        brow = b + (size_t)p * D_DIM;
    } else {
        brow = b + (size_t)row * D_DIM;
    }

    float v[6];
    float s = 0.f;
    #pragma unroll
    for (int i = 0; i < 6; i++) {
        const int idx = lane + 32 * i;
        v[i] = arow[idx] + brow[idx];
        s += v[i];
    }
    #pragma unroll
    for (int o = 16; o > 0; o >>= 1) s += __shfl_xor_sync(0xffffffffu, s, o);
    const float mean = s * (1.0f / D_DIM);

    float q = 0.f;
    #pragma unroll
    for (int i = 0; i < 6; i++) { const float d = v[i] - mean; q += d * d; }
    #pragma unroll
    for (int o = 16; o > 0; o >>= 1) q += __shfl_xor_sync(0xffffffffu, q, o);
    const float inv = rsqrtf(q * (1.0f / D_DIM) + 1e-5f);

    float* orow = outp + (size_t)row * D_DIM;
    #pragma unroll
    for (int i = 0; i < 6; i++) {
        const int idx = lane + 32 * i;
        const float val = (v[i] - mean) * inv * gamma[idx] + beta[idx];
        orow[idx] = val;
        if (OUTH) oh[(size_t)row * D_DIM + idx] = __float2half(val);
    }
}

// ---------------- weight conversion (all four in one launch) ----------------
__global__ void cvt_weights_kernel(const float* __restrict__ Wq, const float* __restrict__ Wo,
                                   const float* __restrict__ W1, const float* __restrict__ W2,
                                   __half* __restrict__ wh)
{
    const int i = blockIdx.x * blockDim.x + threadIdx.x;
    const int n4 = 368640 / 4;
    if (i >= n4) return;
    const int e = i * 4;
    const float* srcp;
    int off;
    if (e < WOFF_O)      { srcp = Wq; off = e - WOFF_Q; }
    else if (e < WOFF_1) { srcp = Wo; off = e - WOFF_O; }
    else if (e < WOFF_2) { srcp = W1; off = e - WOFF_1; }
    else                 { srcp = W2; off = e - WOFF_2; }
    float4 x = *(const float4*)(srcp + off);
    ((__half2*)wh)[2*i]   = __floats2half2_rn(x.x, x.y);
    ((__half2*)wh)[2*i+1] = __floats2half2_rn(x.z, x.w);
}

// ---------------- launch ----------------
extern "C" void kernel_launch(void* const* d_in, const int* in_sizes, int n_in,
                              void* d_out, int out_size)
{
    const float* src     = (const float*)d_in[0];
    const float* pos     = (const float*)d_in[1];
    const float* boxf    = (const float*)d_in[2];
    const float* boxp    = (const float*)d_in[3];
    const int*   vcoords = (const int*)  d_in[4];
    const int*   bcoords = (const int*)  d_in[5];
    const int*   vinds   = (const int*)  d_in[6];
    const float* Wq = (const float*)d_in[7];  const float* bq  = (const float*)d_in[8];
    const float* Wk = (const float*)d_in[9];  const float* bk  = (const float*)d_in[10];
    const float* Wv = (const float*)d_in[11]; const float* bv  = (const float*)d_in[12];
    const float* Wo = (const float*)d_in[13]; const float* bo  = (const float*)d_in[14];
    const float* W1 = (const float*)d_in[15]; const float* b1  = (const float*)d_in[16];
    const float* W2 = (const float*)d_in[17]; const float* b2  = (const float*)d_in[18];
    const float* g1 = (const float*)d_in[19]; const float* be1 = (const float*)d_in[20];
    const float* g2 = (const float*)d_in[21]; const float* be2 = (const float*)d_in[22];
    float* out = (float*)d_out;

    float *qb, *projb, *xb, *yb, *kb, *vb;
    int* fpb;
    __half *ctxh, *xh, *hh, *wh;
    cudaGetSymbolAddress((void**)&qb,    g_q);
    cudaGetSymbolAddress((void**)&projb, g_proj);
    cudaGetSymbolAddress((void**)&xb,    g_x);
    cudaGetSymbolAddress((void**)&yb,    g_y);
    cudaGetSymbolAddress((void**)&kb,    g_k);
    cudaGetSymbolAddress((void**)&vb,    g_v);
    cudaGetSymbolAddress((void**)&fpb,   g_fp);
    cudaGetSymbolAddress((void**)&ctxh,  g_ctxh);
    cudaGetSymbolAddress((void**)&xh,    g_xh);
    cudaGetSymbolAddress((void**)&hh,    g_hh);
    cudaGetSymbolAddress((void**)&wh,    g_wh);

    cudaFuncSetAttribute(attn_kernel, cudaFuncAttributeMaxDynamicSharedMemorySize, ATTN_SMEM);

    const int MB = N_PTS / 128;   // 720

    // 1: weight conversion
    cvt_weights_kernel<<<(368640/4 + 255)/256, 256>>>(Wq, Wo, W1, W2, wh);
    // 2: K/V projections (one launch, blockIdx.z selects)
    gemm_kv<<<dim3(D_DIM/BN, M_BOX/BM, 2), 256>>>(boxf, boxp, Wk, bk, kb, Wv, bv, vb);
    // 3: Q = (src + pos) @ Wq^T + bq (fp16 TC, fused add+cvt on load)
    hgemm<false, false, true><<<dim3(D_DIM/64, MB), 256>>>(nullptr, src, pos, wh + WOFF_Q, bq, qb, nullptr, D_DIM, D_DIM);
    // 4: fused masked attention  (<- ncu profiles launch #4)
    attn_kernel<<<dim3(S_SETS, H_HEADS), 256, ATTN_SMEM>>>(qb, kb, vb, vinds, vcoords, bcoords, ctxh);
    // 5: O projection
    hgemm<false, false, false><<<dim3(D_DIM/64, MB), 256>>>(ctxh, nullptr, nullptr, wh + WOFF_O, bo, projb, nullptr, D_DIM, D_DIM);
    // 6,7: first-occurrence scatter index
    init_fp_kernel<<<N_PTS / 256, 256>>>(fpb);
    fill_fp_kernel<<<(S_SETS * L_LEN) / 256, 256>>>(vinds, fpb);
    // 8: x = LN(src + proj[first_pos]) (+ half copy)
    ln_kernel<true, true><<<N_PTS / 8, 256>>>(src, projb, fpb, g1, be1, xb, xh);
    // 9,10: FFN
    hgemm<true,  true,  false><<<dim3(FF_DIM/64, MB), 256>>>(xh, nullptr, nullptr, wh + WOFF_1, b1, nullptr, hh, D_DIM, FF_DIM);
    hgemm<false, false, false><<<dim3(D_DIM/64, MB), 256>>>(hh, nullptr, nullptr, wh + WOFF_2, b2, yb, nullptr, FF_DIM, D_DIM);
    // 11: out = LN(x + ffn)
    ln_kernel<false, false><<<N_PTS / 8, 256>>>(xb, yb, nullptr, g2, be2, out, nullptr);
}

// round 8
// speedup vs baseline: 2.4395x; 1.5272x over previous
#include <cuda_runtime.h>
#include <cuda_fp16.h>
#include <math_constants.h>
#include <cstdint>

#define N_PTS   92160
#define D_DIM   192
#define BD_DIM  256
#define H_HEADS 8
#define FF_DIM  768
#define S_SETS  2560
#define L_LEN   36
#define M_BOX   256
#define HD_DIM  24

// ---------------- scratch (static device globals; no allocation) ----------------
__device__ float g_q[N_PTS * D_DIM];
__device__ float g_proj[N_PTS * D_DIM];
__device__ float g_x[N_PTS * D_DIM];
__device__ float g_y[N_PTS * D_DIM];
__device__ float g_k[M_BOX * D_DIM];
__device__ float g_v[M_BOX * D_DIM];
__device__ int   g_fp[N_PTS];

__device__ __half g_ctxh[N_PTS * D_DIM];
__device__ __half g_xh[N_PTS * D_DIM];
__device__ __half g_hh[(size_t)N_PTS * FF_DIM];
#define WOFF_Q 0
#define WOFF_O 36864
#define WOFF_1 73728
#define WOFF_2 221184
__device__ __half g_wh[368640];

__device__ __forceinline__ void mma16816(float* d, const uint32_t* a, const uint32_t* b) {
    asm volatile(
        "mma.sync.aligned.m16n8k16.row.col.f32.f16.f16.f32 "
        "{%0,%1,%2,%3}, {%4,%5,%6,%7}, {%8,%9}, {%0,%1,%2,%3};\n"
        : "+f"(d[0]), "+f"(d[1]), "+f"(d[2]), "+f"(d[3])
        : "r"(a[0]), "r"(a[1]), "r"(a[2]), "r"(a[3]), "r"(b[0]), "r"(b[1]));
}

// ================= fp16 mma.sync GEMM: C = A @ W^T + bias =================
#define HPAD 40

__device__ __forceinline__ uint4 add_cvt8(const float* p, const float* q) {
    float4 x0 = *(const float4*)p;
    float4 x1 = *(const float4*)(p + 4);
    float4 y0 = *(const float4*)q;
    float4 y1 = *(const float4*)(q + 4);
    __half2 h0 = __floats2half2_rn(x0.x + y0.x, x0.y + y0.y);
    __half2 h1 = __floats2half2_rn(x0.z + y0.z, x0.w + y0.w);
    __half2 h2 = __floats2half2_rn(x1.x + y1.x, x1.y + y1.y);
    __half2 h3 = __floats2half2_rn(x1.z + y1.z, x1.w + y1.w);
    uint4 r;
    r.x = *(uint32_t*)&h0; r.y = *(uint32_t*)&h1;
    r.z = *(uint32_t*)&h2; r.w = *(uint32_t*)&h3;
    return r;
}

template<bool RELU, bool OUTH, bool ADDIN>
__global__ __launch_bounds__(256)
void hgemm(const __half* __restrict__ A, const float* __restrict__ Af, const float* __restrict__ Af2,
           const __half* __restrict__ W, const float* __restrict__ bias,
           float* __restrict__ C, __half* __restrict__ Ch, int K, int Dout)
{
    __shared__ __half sb[2][192 * HPAD];

    const int tid  = threadIdx.x;
    const int lane = tid & 31;
    const int wid  = tid >> 5;
    const int wm   = wid & 3;
    const int wn   = wid >> 2;
    const int m0   = blockIdx.y * 128;
    const int n0   = blockIdx.x * 64;
    const int lr   = lane >> 2;
    const int lc2  = (lane & 3) * 2;

    const int r0 = tid >> 2;
    const int c8 = (tid & 3) * 8;
    const size_t oA0 = (size_t)(m0 + r0)      * K + c8;
    const size_t oA1 = (size_t)(m0 + r0 + 64) * K + c8;
    const __half* gW = W + (size_t)(n0 + r0) * K + c8;
    const int s0 = r0 * HPAD + c8;
    const int s1 = (r0 + 64) * HPAD + c8;
    const int s2 = (r0 + 128) * HPAD + c8;

    const int nT = K >> 5;

    uint4 pa0, pa1, pw;
    if (ADDIN) {
        pa0 = add_cvt8(Af + oA0, Af2 + oA0);
        pa1 = add_cvt8(Af + oA1, Af2 + oA1);
    } else {
        pa0 = *(const uint4*)(A + oA0);
        pa1 = *(const uint4*)(A + oA1);
    }
    pw = *(const uint4*)gW;

    float acc[2][4][4];
    #pragma unroll
    for (int i = 0; i < 2; i++)
        #pragma unroll
        for (int j = 0; j < 4; j++)
            #pragma unroll
            for (int e = 0; e < 4; e++) acc[i][j][e] = 0.f;

    *(uint4*)(sb[0] + s0) = pa0;
    *(uint4*)(sb[0] + s1) = pa1;
    *(uint4*)(sb[0] + s2) = pw;

    for (int t = 0; t < nT; ++t) {
        __syncthreads();

        if (t + 1 < nT) {
            const int off = (t + 1) * 32;
            if (ADDIN) {
                pa0 = add_cvt8(Af + oA0 + off, Af2 + oA0 + off);
                pa1 = add_cvt8(Af + oA1 + off, Af2 + oA1 + off);
            } else {
                pa0 = *(const uint4*)(A + oA0 + off);
                pa1 = *(const uint4*)(A + oA1 + off);
            }
            pw = *(const uint4*)(gW + off);
        }

        const __half* As = sb[t & 1];
        const __half* Ws = As + 128 * HPAD;

        #pragma unroll
        for (int ks = 0; ks < 32; ks += 16) {
            uint32_t af[2][4], bf[4][2];
            #pragma unroll
            for (int i = 0; i < 2; i++) {
                const int base = (wm * 32 + i * 16 + lr) * HPAD + ks + lc2;
                af[i][0] = *(const uint32_t*)(As + base);
                af[i][1] = *(const uint32_t*)(As + base + 8 * HPAD);
                af[i][2] = *(const uint32_t*)(As + base + 8);
                af[i][3] = *(const uint32_t*)(As + base + 8 * HPAD + 8);
            }
            #pragma unroll
            for (int j = 0; j < 4; j++) {
                const int base = (wn * 32 + j * 8 + lr) * HPAD + ks + lc2;
                bf[j][0] = *(const uint32_t*)(Ws + base);
                bf[j][1] = *(const uint32_t*)(Ws + base + 8);
            }
            #pragma unroll
            for (int i = 0; i < 2; i++)
                #pragma unroll
                for (int j = 0; j < 4; j++)
                    mma16816(acc[i][j], af[i], bf[j]);
        }

        if (t + 1 < nT) {
            __half* nb = sb[(t + 1) & 1];
            *(uint4*)(nb + s0) = pa0;
            *(uint4*)(nb + s1) = pa1;
            *(uint4*)(nb + s2) = pw;
        }
    }

    float2 bx[4];
    #pragma unroll
    for (int j = 0; j < 4; j++) {
        const int cj = n0 + wn * 32 + j * 8 + lc2;
        bx[j] = *(const float2*)(bias + cj);
    }
    #pragma unroll
    for (int i = 0; i < 2; i++) {
        const int r = m0 + wm * 32 + i * 16 + lr;
        #pragma unroll
        for (int j = 0; j < 4; j++) {
            const int cj = n0 + wn * 32 + j * 8 + lc2;
            float v0 = acc[i][j][0] + bx[j].x;
            float v1 = acc[i][j][1] + bx[j].y;
            float v2 = acc[i][j][2] + bx[j].x;
            float v3 = acc[i][j][3] + bx[j].y;
            if (RELU) {
                v0 = fmaxf(v0, 0.f); v1 = fmaxf(v1, 0.f);
                v2 = fmaxf(v2, 0.f); v3 = fmaxf(v3, 0.f);
            }
            if (OUTH) {
                *(__half2*)(Ch + (size_t)r       * Dout + cj) = __floats2half2_rn(v0, v1);
                *(__half2*)(Ch + (size_t)(r + 8) * Dout + cj) = __floats2half2_rn(v2, v3);
            } else {
                *(float2*)(C + (size_t)r       * Dout + cj) = make_float2(v0, v1);
                *(float2*)(C + (size_t)(r + 8) * Dout + cj) = make_float2(v2, v3);
            }
        }
    }
}

// ---------------- combined K/V projection (SIMT fp32), blockIdx.z selects ----------------
#define BM 128
#define BN 64
#define BK 16

__global__ __launch_bounds__(256, 2)
void gemm_kv(const float* __restrict__ boxf, const float* __restrict__ boxp,
             const float* __restrict__ Wk, const float* __restrict__ bk, float* __restrict__ Ck,
             const float* __restrict__ Wv, const float* __restrict__ bv, float* __restrict__ Cv)
{
    const bool isK = (blockIdx.z == 0);
    const float* A   = boxf;
    const float* A2  = isK ? boxp : nullptr;
    const float* W   = isK ? Wk : Wv;
    const float* bias= isK ? bk : bv;
    float* C         = isK ? Ck : Cv;
    const int K = BD_DIM, Dout = D_DIM;

    __shared__ float As[BK][BM + 4];
    __shared__ float Ws[BK][BN + 4];

    const int tid = threadIdx.x;
    const int tx = tid & 15;
    const int ty = tid >> 4;
    const int m0 = blockIdx.y * BM;
    const int n0 = blockIdx.x * BN;

    const int ar = tid >> 2;
    const int ac = (tid & 3) << 2;

    const float* Ap0 = A + (size_t)(m0 + ar)      * K + ac;
    const float* Ap1 = A + (size_t)(m0 + ar + 64) * K + ac;
    const float* Wp  = W + (size_t)(n0 + ar)      * K + ac;

    const int nT = K / BK;

    float4 pa0 = *(const float4*)(Ap0);
    float4 pa1 = *(const float4*)(Ap1);
    float4 pw  = *(const float4*)(Wp);
    if (isK) {
        const float* B0 = A2 + (size_t)(m0 + ar) * K + ac;
        const float* B1 = A2 + (size_t)(m0 + ar + 64) * K + ac;
        float4 q0 = *(const float4*)B0;
        float4 q1 = *(const float4*)B1;
        pa0.x += q0.x; pa0.y += q0.y; pa0.z += q0.z; pa0.w += q0.w;
        pa1.x += q1.x; pa1.y += q1.y; pa1.z += q1.z; pa1.w += q1.w;
    }

    float acc[8][4];
    #pragma unroll
    for (int i = 0; i < 8; i++)
        #pragma unroll
        for (int j = 0; j < 4; j++) acc[i][j] = 0.f;

    for (int t = 0; t < nT; ++t) {
        As[ac+0][ar]    = pa0.x; As[ac+1][ar]    = pa0.y;
        As[ac+2][ar]    = pa0.z; As[ac+3][ar]    = pa0.w;
        As[ac+0][ar+64] = pa1.x; As[ac+1][ar+64] = pa1.y;
        As[ac+2][ar+64] = pa1.z; As[ac+3][ar+64] = pa1.w;
        Ws[ac+0][ar]    = pw.x;  Ws[ac+1][ar]    = pw.y;
        Ws[ac+2][ar]    = pw.z;  Ws[ac+3][ar]    = pw.w;
        __syncthreads();

        if (t + 1 < nT) {
            const int off = (t + 1) * BK;
            pa0 = *(const float4*)(Ap0 + off);
            pa1 = *(const float4*)(Ap1 + off);
            pw  = *(const float4*)(Wp  + off);
            if (isK) {
                const float* B0 = A2 + (size_t)(m0 + ar) * K + ac + off;
                const float* B1 = A2 + (size_t)(m0 + ar + 64) * K + ac + off;
                float4 q0 = *(const float4*)B0;
                float4 q1 = *(const float4*)B1;
                pa0.x += q0.x; pa0.y += q0.y; pa0.z += q0.z; pa0.w += q0.w;
                pa1.x += q1.x; pa1.y += q1.y; pa1.z += q1.z; pa1.w += q1.w;
            }
        }

        #pragma unroll
        for (int k = 0; k < BK; ++k) {
            float a[8], w[4];
            #pragma unroll
            for (int i = 0; i < 8; i++) a[i] = As[k][ty * 8 + i];
            #pragma unroll
            for (int j = 0; j < 4; j++) w[j] = Ws[k][tx * 4 + j];
            #pragma unroll
            for (int i = 0; i < 8; i++)
                #pragma unroll
                for (int j = 0; j < 4; j++) acc[i][j] += a[i] * w[j];
        }
        __syncthreads();
    }

    const float b0 = bias[n0 + tx*4 + 0];
    const float b1 = bias[n0 + tx*4 + 1];
    const float b2 = bias[n0 + tx*4 + 2];
    const float b3 = bias[n0 + tx*4 + 3];
    #pragma unroll
    for (int i = 0; i < 8; i++) {
        float4 o;
        o.x = acc[i][0] + b0; o.y = acc[i][1] + b1;
        o.z = acc[i][2] + b2; o.w = acc[i][3] + b3;
        *(float4*)(C + (size_t)(m0 + ty*8 + i) * Dout + n0 + tx*4) = o;
    }
}

// ================= tensor-core attention: one CTA per (set, head) =================
// Smem (halves): Qs 48x40 @0 | Ks 256x40 @1920 | Vt 24x264 @12160 | Ps 48x264 @18496
// ints after 31168 halves: qb[36], bb[256]. Total 63504 B.
#define AT_QS   0
#define AT_KS   1920
#define AT_VT   12160
#define AT_PS   18496
#define AT_INT  31168
#define ATTN_SMEM (31168 * 2 + (36 + 256) * 4)

__global__ __launch_bounds__(256)
void attn_mma(const float* __restrict__ qbuf, const float* __restrict__ kbuf,
              const float* __restrict__ vbuf, const int* __restrict__ vinds,
              const int* __restrict__ vcoords, const int* __restrict__ bcoords,
              __half* __restrict__ ctxh)
{
    extern __shared__ __half sm[];
    __half* Qs = sm + AT_QS;     // 48 x 40 (k padded 24->32 with zeros)
    __half* Ks = sm + AT_KS;     // 256 x 40
    __half* Vt = sm + AT_VT;     // 24 x 264 (V transposed: [d][m])
    __half* Ps = sm + AT_PS;     // 48 x 264 (scores -> probs, half)
    int* qb = (int*)(sm + AT_INT);
    int* bb = qb + 36;

    const int s = blockIdx.x, h = blockIdx.y;
    const int t = threadIdx.x, lane = t & 31, wid = t >> 5;
    const int lr = lane >> 2, lc2 = (lane & 3) * 2;
    const __half2 zz = __floats2half2_rn(0.f, 0.f);

    // ---- load K row + V row (transposed), thread t = box m ----
    {
        const float4* kp = (const float4*)(kbuf + (size_t)t * D_DIM + h * HD_DIM);
        const float4* vp = (const float4*)(vbuf + (size_t)t * D_DIM + h * HD_DIM);
        __half2* krow = (__half2*)(Ks + t * 40);
        #pragma unroll
        for (int i = 0; i < 6; i++) {
            float4 f = kp[i];
            krow[2*i]   = __floats2half2_rn(f.x, f.y);
            krow[2*i+1] = __floats2half2_rn(f.z, f.w);
            float4 g = vp[i];
            Vt[(4*i+0)*264 + t] = __float2half(g.x);
            Vt[(4*i+1)*264 + t] = __float2half(g.y);
            Vt[(4*i+2)*264 + t] = __float2half(g.z);
            Vt[(4*i+3)*264 + t] = __float2half(g.w);
        }
        krow[12] = zz; krow[13] = zz; krow[14] = zz; krow[15] = zz;   // k 24..31 zero
        bb[t] = bcoords[t * 4];
    }
    // ---- load Q (gathered rows), 36 rows x 8 chunks of 4 halves ----
    for (int i = t; i < 36 * 8; i += 256) {
        const int l = i >> 3, c = i & 7;
        __half2* qrow = (__half2*)(Qs + l * 40);
        if (c < 6) {
            float4 f = *(const float4*)(qbuf + (size_t)vinds[s * L_LEN + l] * D_DIM + h * HD_DIM + c * 4);
            qrow[2*c]   = __floats2half2_rn(f.x, f.y);
            qrow[2*c+1] = __floats2half2_rn(f.z, f.w);
        } else {
            qrow[2*c] = zz; qrow[2*c+1] = zz;                          // k 24..31 zero
        }
    }
    if (t < 36) qb[t] = vcoords[(size_t)vinds[s * L_LEN + t] * 4];
    __syncthreads();

    // ---- scores: S = Q @ K^T (warp w covers n in [w*32, w*32+32)) ----
    float acc[3][4][4];
    #pragma unroll
    for (int i = 0; i < 3; i++)
        #pragma unroll
        for (int j = 0; j < 4; j++)
            #pragma unroll
            for (int e = 0; e < 4; e++) acc[i][j][e] = 0.f;

    #pragma unroll
    for (int kk = 0; kk < 2; kk++) {
        const int k0 = kk * 16;
        uint32_t af[3][4], bf[4][2];
        #pragma unroll
        for (int i = 0; i < 3; i++) {
            const __half* p = Qs + (i * 16 + lr) * 40 + k0 + lc2;
            af[i][0] = *(const uint32_t*)(p);
            af[i][1] = *(const uint32_t*)(p + 8 * 40);
            af[i][2] = *(const uint32_t*)(p + 8);
            af[i][3] = *(const uint32_t*)(p + 8 * 40 + 8);
        }
        #pragma unroll
        for (int j = 0; j < 4; j++) {
            const __half* p = Ks + (wid * 32 + j * 8 + lr) * 40 + k0 + lc2;
            bf[j][0] = *(const uint32_t*)(p);
            bf[j][1] = *(const uint32_t*)(p + 8);
        }
        #pragma unroll
        for (int i = 0; i < 3; i++)
            #pragma unroll
            for (int j = 0; j < 4; j++)
                mma16816(acc[i][j], af[i], bf[j]);
    }

    // write scores (scaled + masked) as half into Ps, rows < 36 only
    {
        const float scale = 0.20412414523193154f;
        #pragma unroll
        for (int i = 0; i < 3; i++) {
            const int r0 = i * 16 + lr, r1 = r0 + 8;
            const int q0 = (r0 < L_LEN) ? qb[r0] : 0;
            const int q1 = (r1 < L_LEN) ? qb[r1] : 0;
            #pragma unroll
            for (int j = 0; j < 4; j++) {
                const int c = wid * 32 + j * 8 + lc2;
                const int b0 = bb[c], b1 = bb[c + 1];
                if (r0 < L_LEN) {
                    float v0 = (q0 != b0) ? -CUDART_INF_F : acc[i][j][0] * scale;
                    float v1 = (q0 != b1) ? -CUDART_INF_F : acc[i][j][1] * scale;
                    *(__half2*)(Ps + r0 * 264 + c) = __floats2half2_rn(v0, v1);
                }
                if (r1 < L_LEN) {
                    float v2 = (q1 != b0) ? -CUDART_INF_F : acc[i][j][2] * scale;
                    float v3 = (q1 != b1) ? -CUDART_INF_F : acc[i][j][3] * scale;
                    *(__half2*)(Ps + r1 * 264 + c) = __floats2half2_rn(v2, v3);
                }
            }
        }
    }
    __syncthreads();

    // ---- softmax (fp32 math, half storage), warp per row, in place ----
    for (int l = wid; l < L_LEN; l += 8) {
        __half* row = Ps + l * 264;
        float e[8];
        float mx = -CUDART_INF_F;
        #pragma unroll
        for (int i = 0; i < 8; i++) { e[i] = __half2float(row[lane + 32*i]); mx = fmaxf(mx, e[i]); }
        #pragma unroll
        for (int o = 16; o > 0; o >>= 1) mx = fmaxf(mx, __shfl_xor_sync(0xffffffffu, mx, o));
        float sum = 0.f;
        if (mx > -CUDART_INF_F) {
            #pragma unroll
            for (int i = 0; i < 8; i++) { e[i] = __expf(e[i] - mx); sum += e[i]; }
        } else {
            #pragma unroll
            for (int i = 0; i < 8; i++) e[i] = 0.f;
        }
        #pragma unroll
        for (int o = 16; o > 0; o >>= 1) sum += __shfl_xor_sync(0xffffffffu, sum, o);
        const float inv = sum > 0.f ? 1.0f / sum : 0.f;
        #pragma unroll
        for (int i = 0; i < 8; i++) row[lane + 32*i] = __float2half(e[i] * inv);
    }
    __syncthreads();

    // ---- ctx = P @ V : 9 (mtile, ntile) combos over 8 warps ----
    for (int cb = wid; cb < 9; cb += 8) {
        const int mt = cb / 3, nt = cb % 3;
        float a2[4] = {0.f, 0.f, 0.f, 0.f};
        #pragma unroll 4
        for (int kt = 0; kt < 16; kt++) {
            uint32_t af[4], bf[2];
            const __half* pa = Ps + (mt * 16 + lr) * 264 + kt * 16 + lc2;
            af[0] = *(const uint32_t*)(pa);
            af[1] = *(const uint32_t*)(pa + 8 * 264);
            af[2] = *(const uint32_t*)(pa + 8);
            af[3] = *(const uint32_t*)(pa + 8 * 264 + 8);
            const __half* pb = Vt + (nt * 8 + lr) * 264 + kt * 16 + lc2;
            bf[0] = *(const uint32_t*)(pb);
            bf[1] = *(const uint32_t*)(pb + 8);
            mma16816(a2, af, bf);
        }
        const int r0 = mt * 16 + lr, r1 = r0 + 8;
        const int c = nt * 8 + lc2;
        if (r0 < L_LEN)
            *(__half2*)(ctxh + ((size_t)s * L_LEN + r0) * D_DIM + h * HD_DIM + c) = __floats2half2_rn(a2[0], a2[1]);
        if (r1 < L_LEN)
            *(__half2*)(ctxh + ((size_t)s * L_LEN + r1) * D_DIM + h * HD_DIM + c) = __floats2half2_rn(a2[2], a2[3]);
    }
}

// ---------------- first-occurrence scatter index ----------------
__global__ void init_fp_kernel(int* __restrict__ fp)
{
    int i = blockIdx.x * blockDim.x + threadIdx.x;
    if (i < N_PTS) fp[i] = 0x7FFFFFFF;
}

__global__ void fill_fp_kernel(const int* __restrict__ vinds, int* __restrict__ fp)
{
    int p = blockIdx.x * blockDim.x + threadIdx.x;
    if (p < S_SETS * L_LEN) {
        int n = vinds[p];
        if (n >= 0 && n < N_PTS) atomicMin(&fp[n], p);
    }
}

// ---------------- residual + layernorm (warp per row) ----------------
template<bool GATHER, bool OUTH>
__global__ __launch_bounds__(256)
void ln_kernel(const float* __restrict__ a, const float* __restrict__ b,
               const int* __restrict__ fp, const float* __restrict__ gamma,
               const float* __restrict__ beta, float* __restrict__ outp,
               __half* __restrict__ oh)
{
    const int row  = (blockIdx.x * 256 + threadIdx.x) >> 5;
    const int lane = threadIdx.x & 31;
    if (row >= N_PTS) return;

    const float* arow = a + (size_t)row * D_DIM;
    const float* brow;
    if (GATHER) {
        int p = fp[row];
        if (p < 0 || p >= N_PTS) p = row;
        brow = b + (size_t)p * D_DIM;
    } else {
        brow = b + (size_t)row * D_DIM;
    }

    float v[6];
    float s = 0.f;
    #pragma unroll
    for (int i = 0; i < 6; i++) {
        const int idx = lane + 32 * i;
        v[i] = arow[idx] + brow[idx];
        s += v[i];
    }
    #pragma unroll
    for (int o = 16; o > 0; o >>= 1) s += __shfl_xor_sync(0xffffffffu, s, o);
    const float mean = s * (1.0f / D_DIM);

    float q = 0.f;
    #pragma unroll
    for (int i = 0; i < 6; i++) { const float d = v[i] - mean; q += d * d; }
    #pragma unroll
    for (int o = 16; o > 0; o >>= 1) q += __shfl_xor_sync(0xffffffffu, q, o);
    const float inv = rsqrtf(q * (1.0f / D_DIM) + 1e-5f);

    float* orow = outp + (size_t)row * D_DIM;
    #pragma unroll
    for (int i = 0; i < 6; i++) {
        const int idx = lane + 32 * i;
        const float val = (v[i] - mean) * inv * gamma[idx] + beta[idx];
        orow[idx] = val;
        if (OUTH) oh[(size_t)row * D_DIM + idx] = __float2half(val);
    }
}

// ---------------- weight conversion (all four in one launch) ----------------
__global__ void cvt_weights_kernel(const float* __restrict__ Wq, const float* __restrict__ Wo,
                                   const float* __restrict__ W1, const float* __restrict__ W2,
                                   __half* __restrict__ wh)
{
    const int i = blockIdx.x * blockDim.x + threadIdx.x;
    const int n4 = 368640 / 4;
    if (i >= n4) return;
    const int e = i * 4;
    const float* srcp;
    int off;
    if (e < WOFF_O)      { srcp = Wq; off = e - WOFF_Q; }
    else if (e < WOFF_1) { srcp = Wo; off = e - WOFF_O; }
    else if (e < WOFF_2) { srcp = W1; off = e - WOFF_1; }
    else                 { srcp = W2; off = e - WOFF_2; }
    float4 x = *(const float4*)(srcp + off);
    ((__half2*)wh)[2*i]   = __floats2half2_rn(x.x, x.y);
    ((__half2*)wh)[2*i+1] = __floats2half2_rn(x.z, x.w);
}

// ---------------- launch ----------------
extern "C" void kernel_launch(void* const* d_in, const int* in_sizes, int n_in,
                              void* d_out, int out_size)
{
    const float* src     = (const float*)d_in[0];
    const float* pos     = (const float*)d_in[1];
    const float* boxf    = (const float*)d_in[2];
    const float* boxp    = (const float*)d_in[3];
    const int*   vcoords = (const int*)  d_in[4];
    const int*   bcoords = (const int*)  d_in[5];
    const int*   vinds   = (const int*)  d_in[6];
    const float* Wq = (const float*)d_in[7];  const float* bq  = (const float*)d_in[8];
    const float* Wk = (const float*)d_in[9];  const float* bk  = (const float*)d_in[10];
    const float* Wv = (const float*)d_in[11]; const float* bv  = (const float*)d_in[12];
    const float* Wo = (const float*)d_in[13]; const float* bo  = (const float*)d_in[14];
    const float* W1 = (const float*)d_in[15]; const float* b1  = (const float*)d_in[16];
    const float* W2 = (const float*)d_in[17]; const float* b2  = (const float*)d_in[18];
    const float* g1 = (const float*)d_in[19]; const float* be1 = (const float*)d_in[20];
    const float* g2 = (const float*)d_in[21]; const float* be2 = (const float*)d_in[22];
    float* out = (float*)d_out;

    float *qb, *projb, *xb, *yb, *kb, *vb;
    int* fpb;
    __half *ctxh, *xh, *hh, *wh;
    cudaGetSymbolAddress((void**)&qb,    g_q);
    cudaGetSymbolAddress((void**)&projb, g_proj);
    cudaGetSymbolAddress((void**)&xb,    g_x);
    cudaGetSymbolAddress((void**)&yb,    g_y);
    cudaGetSymbolAddress((void**)&kb,    g_k);
    cudaGetSymbolAddress((void**)&vb,    g_v);
    cudaGetSymbolAddress((void**)&fpb,   g_fp);
    cudaGetSymbolAddress((void**)&ctxh,  g_ctxh);
    cudaGetSymbolAddress((void**)&xh,    g_xh);
    cudaGetSymbolAddress((void**)&hh,    g_hh);
    cudaGetSymbolAddress((void**)&wh,    g_wh);

    cudaFuncSetAttribute(attn_mma, cudaFuncAttributeMaxDynamicSharedMemorySize, ATTN_SMEM);

    const int MB = N_PTS / 128;   // 720

    // 1: weight conversion
    cvt_weights_kernel<<<(368640/4 + 255)/256, 256>>>(Wq, Wo, W1, W2, wh);
    // 2: K/V projections
    gemm_kv<<<dim3(D_DIM/BN, M_BOX/BM, 2), 256>>>(boxf, boxp, Wk, bk, kb, Wv, bv, vb);
    // 3: Q = (src + pos) @ Wq^T + bq (fused add+cvt on load)
    hgemm<false, false, true><<<dim3(D_DIM/64, MB), 256>>>(nullptr, src, pos, wh + WOFF_Q, bq, qb, nullptr, D_DIM, D_DIM);
    // 4: tensor-core masked attention
    attn_mma<<<dim3(S_SETS, H_HEADS), 256, ATTN_SMEM>>>(qb, kb, vb, vinds, vcoords, bcoords, ctxh);
    // 5: O projection
    hgemm<false, false, false><<<dim3(D_DIM/64, MB), 256>>>(ctxh, nullptr, nullptr, wh + WOFF_O, bo, projb, nullptr, D_DIM, D_DIM);
    // 6,7: first-occurrence scatter index
    init_fp_kernel<<<N_PTS / 256, 256>>>(fpb);
    fill_fp_kernel<<<(S_SETS * L_LEN) / 256, 256>>>(vinds, fpb);
    // 8: x = LN(src + proj[first_pos]) (+ half copy)
    ln_kernel<true, true><<<N_PTS / 8, 256>>>(src, projb, fpb, g1, be1, xb, xh);
    // 9,10: FFN
    hgemm<true,  true,  false><<<dim3(FF_DIM/64, MB), 256>>>(xh, nullptr, nullptr, wh + WOFF_1, b1, nullptr, hh, D_DIM, FF_DIM);
    hgemm<false, false, false><<<dim3(D_DIM/64, MB), 256>>>(hh, nullptr, nullptr, wh + WOFF_2, b2, yb, nullptr, FF_DIM, D_DIM);
    // 11: out = LN(x + ffn)
    ln_kernel<false, false><<<N_PTS / 8, 256>>>(xb, yb, nullptr, g2, be2, out, nullptr);
}

// round 10
// speedup vs baseline: 2.9190x; 1.1966x over previous
#include <cuda_runtime.h>
#include <cuda_fp16.h>
#include <math_constants.h>
#include <cstdint>

#define N_PTS   92160
#define D_DIM   192
#define BD_DIM  256
#define H_HEADS 8
#define FF_DIM  768
#define S_SETS  2560
#define L_LEN   36
#define M_BOX   256
#define HD_DIM  24

// ---------------- scratch (static device globals; no allocation) ----------------
__device__ float g_q[N_PTS * D_DIM];
__device__ float g_proj[N_PTS * D_DIM];
__device__ float g_x[N_PTS * D_DIM];
__device__ float g_y[N_PTS * D_DIM];
__device__ float g_k[M_BOX * D_DIM];
__device__ float g_v[M_BOX * D_DIM];
__device__ int   g_fp[N_PTS];

__device__ __half g_ctxh[N_PTS * D_DIM];
__device__ __half g_xh[N_PTS * D_DIM];
__device__ __half g_hh[(size_t)N_PTS * FF_DIM];
__device__ __half g_kh[H_HEADS * M_BOX * 32];      // [h][m][32] padded fp16 K
__device__ __half g_vt[H_HEADS * HD_DIM * M_BOX];  // [h][d][m]  transposed fp16 V
#define WOFF_Q 0
#define WOFF_O 36864
#define WOFF_1 73728
#define WOFF_2 221184
__device__ __half g_wh[368640];

__device__ __forceinline__ void mma16816(float* d, const uint32_t* a, const uint32_t* b) {
    asm volatile(
        "mma.sync.aligned.m16n8k16.row.col.f32.f16.f16.f32 "
        "{%0,%1,%2,%3}, {%4,%5,%6,%7}, {%8,%9}, {%0,%1,%2,%3};\n"
        : "+f"(d[0]), "+f"(d[1]), "+f"(d[2]), "+f"(d[3])
        : "r"(a[0]), "r"(a[1]), "r"(a[2]), "r"(a[3]), "r"(b[0]), "r"(b[1]));
}

// ================= fp16 mma.sync GEMM: C = A @ W^T + bias =================
#define HPAD 40

__device__ __forceinline__ uint4 add_cvt8(const float* p, const float* q) {
    float4 x0 = *(const float4*)p;
    float4 x1 = *(const float4*)(p + 4);
    float4 y0 = *(const float4*)q;
    float4 y1 = *(const float4*)(q + 4);
    __half2 h0 = __floats2half2_rn(x0.x + y0.x, x0.y + y0.y);
    __half2 h1 = __floats2half2_rn(x0.z + y0.z, x0.w + y0.w);
    __half2 h2 = __floats2half2_rn(x1.x + y1.x, x1.y + y1.y);
    __half2 h3 = __floats2half2_rn(x1.z + y1.z, x1.w + y1.w);
    uint4 r;
    r.x = *(uint32_t*)&h0; r.y = *(uint32_t*)&h1;
    r.z = *(uint32_t*)&h2; r.w = *(uint32_t*)&h3;
    return r;
}

template<bool RELU, bool OUTH, bool ADDIN>
__global__ __launch_bounds__(256)
void hgemm(const __half* __restrict__ A, const float* __restrict__ Af, const float* __restrict__ Af2,
           const __half* __restrict__ W, const float* __restrict__ bias,
           float* __restrict__ C, __half* __restrict__ Ch, int K, int Dout)
{
    __shared__ __half sb[2][192 * HPAD];

    const int tid  = threadIdx.x;
    const int lane = tid & 31;
    const int wid  = tid >> 5;
    const int wm   = wid & 3;
    const int wn   = wid >> 2;
    const int m0   = blockIdx.y * 128;
    const int n0   = blockIdx.x * 64;
    const int lr   = lane >> 2;
    const int lc2  = (lane & 3) * 2;

    const int r0 = tid >> 2;
    const int c8 = (tid & 3) * 8;
    const size_t oA0 = (size_t)(m0 + r0)      * K + c8;
    const size_t oA1 = (size_t)(m0 + r0 + 64) * K + c8;
    const __half* gW = W + (size_t)(n0 + r0) * K + c8;
    const int s0 = r0 * HPAD + c8;
    const int s1 = (r0 + 64) * HPAD + c8;
    const int s2 = (r0 + 128) * HPAD + c8;

    const int nT = K >> 5;

    uint4 pa0, pa1, pw;
    if (ADDIN) {
        pa0 = add_cvt8(Af + oA0, Af2 + oA0);
        pa1 = add_cvt8(Af + oA1, Af2 + oA1);
    } else {
        pa0 = *(const uint4*)(A + oA0);
        pa1 = *(const uint4*)(A + oA1);
    }
    pw = *(const uint4*)gW;

    float acc[2][4][4];
    #pragma unroll
    for (int i = 0; i < 2; i++)
        #pragma unroll
        for (int j = 0; j < 4; j++)
            #pragma unroll
            for (int e = 0; e < 4; e++) acc[i][j][e] = 0.f;

    *(uint4*)(sb[0] + s0) = pa0;
    *(uint4*)(sb[0] + s1) = pa1;
    *(uint4*)(sb[0] + s2) = pw;

    for (int t = 0; t < nT; ++t) {
        __syncthreads();

        if (t + 1 < nT) {
            const int off = (t + 1) * 32;
            if (ADDIN) {
                pa0 = add_cvt8(Af + oA0 + off, Af2 + oA0 + off);
                pa1 = add_cvt8(Af + oA1 + off, Af2 + oA1 + off);
            } else {
                pa0 = *(const uint4*)(A + oA0 + off);
                pa1 = *(const uint4*)(A + oA1 + off);
            }
            pw = *(const uint4*)(gW + off);
        }

        const __half* As = sb[t & 1];
        const __half* Ws = As + 128 * HPAD;

        #pragma unroll
        for (int ks = 0; ks < 32; ks += 16) {
            uint32_t af[2][4], bf[4][2];
            #pragma unroll
            for (int i = 0; i < 2; i++) {
                const int base = (wm * 32 + i * 16 + lr) * HPAD + ks + lc2;
                af[i][0] = *(const uint32_t*)(As + base);
                af[i][1] = *(const uint32_t*)(As + base + 8 * HPAD);
                af[i][2] = *(const uint32_t*)(As + base + 8);
                af[i][3] = *(const uint32_t*)(As + base + 8 * HPAD + 8);
            }
            #pragma unroll
            for (int j = 0; j < 4; j++) {
                const int base = (wn * 32 + j * 8 + lr) * HPAD + ks + lc2;
                bf[j][0] = *(const uint32_t*)(Ws + base);
                bf[j][1] = *(const uint32_t*)(Ws + base + 8);
            }
            #pragma unroll
            for (int i = 0; i < 2; i++)
                #pragma unroll
                for (int j = 0; j < 4; j++)
                    mma16816(acc[i][j], af[i], bf[j]);
        }

        if (t + 1 < nT) {
            __half* nb = sb[(t + 1) & 1];
            *(uint4*)(nb + s0) = pa0;
            *(uint4*)(nb + s1) = pa1;
            *(uint4*)(nb + s2) = pw;
        }
    }

    float2 bx[4];
    #pragma unroll
    for (int j = 0; j < 4; j++) {
        const int cj = n0 + wn * 32 + j * 8 + lc2;
        bx[j] = *(const float2*)(bias + cj);
    }
    #pragma unroll
    for (int i = 0; i < 2; i++) {
        const int r = m0 + wm * 32 + i * 16 + lr;
        #pragma unroll
        for (int j = 0; j < 4; j++) {
            const int cj = n0 + wn * 32 + j * 8 + lc2;
            float v0 = acc[i][j][0] + bx[j].x;
            float v1 = acc[i][j][1] + bx[j].y;
            float v2 = acc[i][j][2] + bx[j].x;
            float v3 = acc[i][j][3] + bx[j].y;
            if (RELU) {
                v0 = fmaxf(v0, 0.f); v1 = fmaxf(v1, 0.f);
                v2 = fmaxf(v2, 0.f); v3 = fmaxf(v3, 0.f);
            }
            if (OUTH) {
                *(__half2*)(Ch + (size_t)r       * Dout + cj) = __floats2half2_rn(v0, v1);
                *(__half2*)(Ch + (size_t)(r + 8) * Dout + cj) = __floats2half2_rn(v2, v3);
            } else {
                *(float2*)(C + (size_t)r       * Dout + cj) = make_float2(v0, v1);
                *(float2*)(C + (size_t)(r + 8) * Dout + cj) = make_float2(v2, v3);
            }
        }
    }
}

// ---------------- combined K/V projection (SIMT fp32), blockIdx.z selects ----------------
#define BM 128
#define BN 64
#define BK 16

__global__ __launch_bounds__(256, 2)
void gemm_kv(const float* __restrict__ boxf, const float* __restrict__ boxp,
             const float* __restrict__ Wk, const float* __restrict__ bk, float* __restrict__ Ck,
             const float* __restrict__ Wv, const float* __restrict__ bv, float* __restrict__ Cv)
{
    const bool isK = (blockIdx.z == 0);
    const float* A   = boxf;
    const float* A2  = isK ? boxp : nullptr;
    const float* W   = isK ? Wk : Wv;
    const float* bias= isK ? bk : bv;
    float* C         = isK ? Ck : Cv;
    const int K = BD_DIM, Dout = D_DIM;

    __shared__ float As[BK][BM + 4];
    __shared__ float Ws[BK][BN + 4];

    const int tid = threadIdx.x;
    const int tx = tid & 15;
    const int ty = tid >> 4;
    const int m0 = blockIdx.y * BM;
    const int n0 = blockIdx.x * BN;

    const int ar = tid >> 2;
    const int ac = (tid & 3) << 2;

    const float* Ap0 = A + (size_t)(m0 + ar)      * K + ac;
    const float* Ap1 = A + (size_t)(m0 + ar + 64) * K + ac;
    const float* Wp  = W + (size_t)(n0 + ar)      * K + ac;

    const int nT = K / BK;

    float4 pa0 = *(const float4*)(Ap0);
    float4 pa1 = *(const float4*)(Ap1);
    float4 pw  = *(const float4*)(Wp);
    if (isK) {
        const float* B0 = A2 + (size_t)(m0 + ar) * K + ac;
        const float* B1 = A2 + (size_t)(m0 + ar + 64) * K + ac;
        float4 q0 = *(const float4*)B0;
        float4 q1 = *(const float4*)B1;
        pa0.x += q0.x; pa0.y += q0.y; pa0.z += q0.z; pa0.w += q0.w;
        pa1.x += q1.x; pa1.y += q1.y; pa1.z += q1.z; pa1.w += q1.w;
    }

    float acc[8][4];
    #pragma unroll
    for (int i = 0; i < 8; i++)
        #pragma unroll
        for (int j = 0; j < 4; j++) acc[i][j] = 0.f;

    for (int t = 0; t < nT; ++t) {
        As[ac+0][ar]    = pa0.x; As[ac+1][ar]    = pa0.y;
        As[ac+2][ar]    = pa0.z; As[ac+3][ar]    = pa0.w;
        As[ac+0][ar+64] = pa1.x; As[ac+1][ar+64] = pa1.y;
        As[ac+2][ar+64] = pa1.z; As[ac+3][ar+64] = pa1.w;
        Ws[ac+0][ar]    = pw.x;  Ws[ac+1][ar]    = pw.y;
        Ws[ac+2][ar]    = pw.z;  Ws[ac+3][ar]    = pw.w;
        __syncthreads();

        if (t + 1 < nT) {
            const int off = (t + 1) * BK;
            pa0 = *(const float4*)(Ap0 + off);
            pa1 = *(const float4*)(Ap1 + off);
            pw  = *(const float4*)(Wp  + off);
            if (isK) {
                const float* B0 = A2 + (size_t)(m0 + ar) * K + ac + off;
                const float* B1 = A2 + (size_t)(m0 + ar + 64) * K + ac + off;
                float4 q0 = *(const float4*)B0;
                float4 q1 = *(const float4*)B1;
                pa0.x += q0.x; pa0.y += q0.y; pa0.z += q0.z; pa0.w += q0.w;
                pa1.x += q1.x; pa1.y += q1.y; pa1.z += q1.z; pa1.w += q1.w;
            }
        }

        #pragma unroll
        for (int k = 0; k < BK; ++k) {
            float a[8], w[4];
            #pragma unroll
            for (int i = 0; i < 8; i++) a[i] = As[k][ty * 8 + i];
            #pragma unroll
            for (int j = 0; j < 4; j++) w[j] = Ws[k][tx * 4 + j];
            #pragma unroll
            for (int i = 0; i < 8; i++)
                #pragma unroll
                for (int j = 0; j < 4; j++) acc[i][j] += a[i] * w[j];
        }
        __syncthreads();
    }

    const float b0 = bias[n0 + tx*4 + 0];
    const float b1 = bias[n0 + tx*4 + 1];
    const float b2 = bias[n0 + tx*4 + 2];
    const float b3 = bias[n0 + tx*4 + 3];
    #pragma unroll
    for (int i = 0; i < 8; i++) {
        float4 o;
        o.x = acc[i][0] + b0; o.y = acc[i][1] + b1;
        o.z = acc[i][2] + b2; o.w = acc[i][3] + b3;
        *(float4*)(C + (size_t)(m0 + ty*8 + i) * Dout + n0 + tx*4) = o;
    }
}

// ---------------- K/V pack: fp32 -> fp16, K padded [h][m][32], V transposed [h][d][m] ----------------
__global__ void kv_pack(const float* __restrict__ kb, const float* __restrict__ vb,
                        __half* __restrict__ khg, __half* __restrict__ vtg)
{
    const int i = blockIdx.x * 256 + threadIdx.x;   // 0..2047
    if (i >= H_HEADS * M_BOX) return;
    const int h = i >> 8, m = i & 255;

    // K row: 24 fp32 -> 24 fp16 + 8 zero pad  (32 halves = 4 uint4)
    {
        const float4* kp = (const float4*)(kb + (size_t)m * D_DIM + h * HD_DIM);
        __half2 hrow[16];
        #pragma unroll
        for (int j = 0; j < 6; j++) {
            float4 f = kp[j];
            hrow[2*j]   = __floats2half2_rn(f.x, f.y);
            hrow[2*j+1] = __floats2half2_rn(f.z, f.w);
        }
        const __half2 zz = __floats2half2_rn(0.f, 0.f);
        hrow[12] = zz; hrow[13] = zz; hrow[14] = zz; hrow[15] = zz;
        uint4* dst = (uint4*)(khg + ((size_t)h * M_BOX + m) * 32);
        dst[0] = ((const uint4*)hrow)[0];
        dst[1] = ((const uint4*)hrow)[1];
        dst[2] = ((const uint4*)hrow)[2];
        dst[3] = ((const uint4*)hrow)[3];
    }
    // V transposed: vtg[h][d][m] (scalar stores, coalesced across m)
    {
        const float4* vp = (const float4*)(vb + (size_t)m * D_DIM + h * HD_DIM);
        __half* base = vtg + (size_t)h * HD_DIM * M_BOX + m;
        #pragma unroll
        for (int j = 0; j < 6; j++) {
            float4 g = vp[j];
            base[(4*j+0) * M_BOX] = __float2half(g.x);
            base[(4*j+1) * M_BOX] = __float2half(g.y);
            base[(4*j+2) * M_BOX] = __float2half(g.z);
            base[(4*j+3) * M_BOX] = __float2half(g.w);
        }
    }
}

// ================= tensor-core attention: one CTA per (set, head) =================
// Smem (halves): Qs 48x40 @0 | Ks 256x40 @1920 | Vt 24x264 @12160 | Ps 48x264 @18496
// ints after 31168 halves: qb[36], bb[256]. Total 63504 B.
#define AT_QS   0
#define AT_KS   1920
#define AT_VT   12160
#define AT_PS   18496
#define AT_INT  31168
#define ATTN_SMEM (31168 * 2 + (36 + 256) * 4)

__global__ __launch_bounds__(256)
void attn_mma(const float* __restrict__ qbuf, const __half* __restrict__ khg,
              const __half* __restrict__ vtg, const int* __restrict__ vinds,
              const int* __restrict__ vcoords, const int* __restrict__ bcoords,
              __half* __restrict__ ctxh)
{
    extern __shared__ __half sm[];
    __half* Qs = sm + AT_QS;     // 48 x 40 (k padded 24->32 with zeros)
    __half* Ks = sm + AT_KS;     // 256 x 40
    __half* Vt = sm + AT_VT;     // 24 x 264 (V transposed: [d][m])
    __half* Ps = sm + AT_PS;     // 48 x 264 (scores -> probs, half)
    int* qb = (int*)(sm + AT_INT);
    int* bb = qb + 36;

    const int s = blockIdx.x, h = blockIdx.y;
    const int t = threadIdx.x, lane = t & 31, wid = t >> 5;
    const int lr = lane >> 2, lc2 = (lane & 3) * 2;
    const __half2 zz = __floats2half2_rn(0.f, 0.f);

    // ---- K copy: pre-packed half rows (32 halves = 4 uint4) ----
    {
        const uint4* kp = (const uint4*)(khg + ((size_t)h * M_BOX + t) * 32);
        uint4* krow = (uint4*)(Ks + t * 40);
        krow[0] = kp[0];
        krow[1] = kp[1];
        krow[2] = kp[2];
        krow[3] = kp[3];
        bb[t] = bcoords[t * 4];
    }
    // ---- Vt copy: 24x256 half, 768 uint4 over 256 threads ----
    {
        const __half* vsrc = vtg + (size_t)h * HD_DIM * M_BOX;
        #pragma unroll
        for (int j = 0; j < 3; j++) {
            const int idx = t + 256 * j;         // 0..767
            const int r = idx >> 5, c = idx & 31;
            *(uint4*)(Vt + r * 264 + c * 8) = *(const uint4*)(vsrc + r * M_BOX + c * 8);
        }
    }
    // ---- load Q (gathered rows), 36 rows x 8 chunks of 4 halves ----
    for (int i = t; i < 36 * 8; i += 256) {
        const int l = i >> 3, c = i & 7;
        __half2* qrow = (__half2*)(Qs + l * 40);
        if (c < 6) {
            float4 f = *(const float4*)(qbuf + (size_t)vinds[s * L_LEN + l] * D_DIM + h * HD_DIM + c * 4);
            qrow[2*c]   = __floats2half2_rn(f.x, f.y);
            qrow[2*c+1] = __floats2half2_rn(f.z, f.w);
        } else {
            qrow[2*c] = zz; qrow[2*c+1] = zz;
        }
    }
    if (t < 36) qb[t] = vcoords[(size_t)vinds[s * L_LEN + t] * 4];
    __syncthreads();

    // ---- scores: S = Q @ K^T (warp w covers n in [w*32, w*32+32)) ----
    float acc[3][4][4];
    #pragma unroll
    for (int i = 0; i < 3; i++)
        #pragma unroll
        for (int j = 0; j < 4; j++)
            #pragma unroll
            for (int e = 0; e < 4; e++) acc[i][j][e] = 0.f;

    #pragma unroll
    for (int kk = 0; kk < 2; kk++) {
        const int k0 = kk * 16;
        uint32_t af[3][4], bf[4][2];
        #pragma unroll
        for (int i = 0; i < 3; i++) {
            const __half* p = Qs + (i * 16 + lr) * 40 + k0 + lc2;
            af[i][0] = *(const uint32_t*)(p);
            af[i][1] = *(const uint32_t*)(p + 8 * 40);
            af[i][2] = *(const uint32_t*)(p + 8);
            af[i][3] = *(const uint32_t*)(p + 8 * 40 + 8);
        }
        #pragma unroll
        for (int j = 0; j < 4; j++) {
            const __half* p = Ks + (wid * 32 + j * 8 + lr) * 40 + k0 + lc2;
            bf[j][0] = *(const uint32_t*)(p);
            bf[j][1] = *(const uint32_t*)(p + 8);
        }
        #pragma unroll
        for (int i = 0; i < 3; i++)
            #pragma unroll
            for (int j = 0; j < 4; j++)
                mma16816(acc[i][j], af[i], bf[j]);
    }

    // write scores (scaled + masked) as half into Ps, rows < 36 only
    {
        const float scale = 0.20412414523193154f;
        #pragma unroll
        for (int i = 0; i < 3; i++) {
            const int r0 = i * 16 + lr, r1 = r0 + 8;
            const int q0 = (r0 < L_LEN) ? qb[r0] : 0;
            const int q1 = (r1 < L_LEN) ? qb[r1] : 0;
            #pragma unroll
            for (int j = 0; j < 4; j++) {
                const int c = wid * 32 + j * 8 + lc2;
                const int b0 = bb[c], b1 = bb[c + 1];
                if (r0 < L_LEN) {
                    float v0 = (q0 != b0) ? -CUDART_INF_F : acc[i][j][0] * scale;
                    float v1 = (q0 != b1) ? -CUDART_INF_F : acc[i][j][1] * scale;
                    *(__half2*)(Ps + r0 * 264 + c) = __floats2half2_rn(v0, v1);
                }
                if (r1 < L_LEN) {
                    float v2 = (q1 != b0) ? -CUDART_INF_F : acc[i][j][2] * scale;
                    float v3 = (q1 != b1) ? -CUDART_INF_F : acc[i][j][3] * scale;
                    *(__half2*)(Ps + r1 * 264 + c) = __floats2half2_rn(v2, v3);
                }
            }
        }
    }
    __syncthreads();

    // ---- softmax (fp32 math, half storage), warp per row, in place ----
    for (int l = wid; l < L_LEN; l += 8) {
        __half* row = Ps + l * 264;
        float e[8];
        float mx = -CUDART_INF_F;
        #pragma unroll
        for (int i = 0; i < 8; i++) { e[i] = __half2float(row[lane + 32*i]); mx = fmaxf(mx, e[i]); }
        #pragma unroll
        for (int o = 16; o > 0; o >>= 1) mx = fmaxf(mx, __shfl_xor_sync(0xffffffffu, mx, o));
        float sum = 0.f;
        if (mx > -CUDART_INF_F) {
            #pragma unroll
            for (int i = 0; i < 8; i++) { e[i] = __expf(e[i] - mx); sum += e[i]; }
        } else {
            #pragma unroll
            for (int i = 0; i < 8; i++) e[i] = 0.f;
        }
        #pragma unroll
        for (int o = 16; o > 0; o >>= 1) sum += __shfl_xor_sync(0xffffffffu, sum, o);
        const float inv = sum > 0.f ? 1.0f / sum : 0.f;
        #pragma unroll
        for (int i = 0; i < 8; i++) row[lane + 32*i] = __float2half(e[i] * inv);
    }
    __syncthreads();

    // ---- ctx = P @ V : 9 (mtile, ntile) combos over 8 warps ----
    for (int cb = wid; cb < 9; cb += 8) {
        const int mt = cb / 3, nt = cb % 3;
        float a2[4] = {0.f, 0.f, 0.f, 0.f};
        #pragma unroll 4
        for (int kt = 0; kt < 16; kt++) {
            uint32_t af[4], bf[2];
            const __half* pa = Ps + (mt * 16 + lr) * 264 + kt * 16 + lc2;
            af[0] = *(const uint32_t*)(pa);
            af[1] = *(const uint32_t*)(pa + 8 * 264);
            af[2] = *(const uint32_t*)(pa + 8);
            af[3] = *(const uint32_t*)(pa + 8 * 264 + 8);
            const __half* pb = Vt + (nt * 8 + lr) * 264 + kt * 16 + lc2;
            bf[0] = *(const uint32_t*)(pb);
            bf[1] = *(const uint32_t*)(pb + 8);
            mma16816(a2, af, bf);
        }
        const int r0 = mt * 16 + lr, r1 = r0 + 8;
        const int c = nt * 8 + lc2;
        if (r0 < L_LEN)
            *(__half2*)(ctxh + ((size_t)s * L_LEN + r0) * D_DIM + h * HD_DIM + c) = __floats2half2_rn(a2[0], a2[1]);
        if (r1 < L_LEN)
            *(__half2*)(ctxh + ((size_t)s * L_LEN + r1) * D_DIM + h * HD_DIM + c) = __floats2half2_rn(a2[2], a2[3]);
    }
}

// ---------------- first-occurrence scatter index ----------------
__global__ void init_fp_kernel(int* __restrict__ fp)
{
    int i = blockIdx.x * blockDim.x + threadIdx.x;
    if (i < N_PTS) fp[i] = 0x7FFFFFFF;
}

__global__ void fill_fp_kernel(const int* __restrict__ vinds, int* __restrict__ fp)
{
    int p = blockIdx.x * blockDim.x + threadIdx.x;
    if (p < S_SETS * L_LEN) {
        int n = vinds[p];
        if (n >= 0 && n < N_PTS) atomicMin(&fp[n], p);
    }
}

// ---------------- residual + layernorm (warp per row) ----------------
template<bool GATHER, bool OUTH>
__global__ __launch_bounds__(256)
void ln_kernel(const float* __restrict__ a, const float* __restrict__ b,
               const int* __restrict__ fp, const float* __restrict__ gamma,
               const float* __restrict__ beta, float* __restrict__ outp,
               __half* __restrict__ oh)
{
    const int row  = (blockIdx.x * 256 + threadIdx.x) >> 5;
    const int lane = threadIdx.x & 31;
    if (row >= N_PTS) return;

    const float* arow = a + (size_t)row * D_DIM;
    const float* brow;
    if (GATHER) {
        int p = fp[row];
        if (p < 0 || p >= N_PTS) p = row;
        brow = b + (size_t)p * D_DIM;
    } else {
        brow = b + (size_t)row * D_DIM;
    }

    float v[6];
    float s = 0.f;
    #pragma unroll
    for (int i = 0; i < 6; i++) {
        const int idx = lane + 32 * i;
        v[i] = arow[idx] + brow[idx];
        s += v[i];
    }
    #pragma unroll
    for (int o = 16; o > 0; o >>= 1) s += __shfl_xor_sync(0xffffffffu, s, o);
    const float mean = s * (1.0f / D_DIM);

    float q = 0.f;
    #pragma unroll
    for (int i = 0; i < 6; i++) { const float d = v[i] - mean; q += d * d; }
    #pragma unroll
    for (int o = 16; o > 0; o >>= 1) q += __shfl_xor_sync(0xffffffffu, q, o);
    const float inv = rsqrtf(q * (1.0f / D_DIM) + 1e-5f);

    float* orow = outp + (size_t)row * D_DIM;
    #pragma unroll
    for (int i = 0; i < 6; i++) {
        const int idx = lane + 32 * i;
        const float val = (v[i] - mean) * inv * gamma[idx] + beta[idx];
        orow[idx] = val;
        if (OUTH) oh[(size_t)row * D_DIM + idx] = __float2half(val);
    }
}

// ---------------- weight conversion (all four in one launch) ----------------
__global__ void cvt_weights_kernel(const float* __restrict__ Wq, const float* __restrict__ Wo,
                                   const float* __restrict__ W1, const float* __restrict__ W2,
                                   __half* __restrict__ wh)
{
    const int i = blockIdx.x * blockDim.x + threadIdx.x;
    const int n4 = 368640 / 4;
    if (i >= n4) return;
    const int e = i * 4;
    const float* srcp;
    int off;
    if (e < WOFF_O)      { srcp = Wq; off = e - WOFF_Q; }
    else if (e < WOFF_1) { srcp = Wo; off = e - WOFF_O; }
    else if (e < WOFF_2) { srcp = W1; off = e - WOFF_1; }
    else                 { srcp = W2; off = e - WOFF_2; }
    float4 x = *(const float4*)(srcp + off);
    ((__half2*)wh)[2*i]   = __floats2half2_rn(x.x, x.y);
    ((__half2*)wh)[2*i+1] = __floats2half2_rn(x.z, x.w);
}

// ---------------- launch ----------------
extern "C" void kernel_launch(void* const* d_in, const int* in_sizes, int n_in,
                              void* d_out, int out_size)
{
    const float* src     = (const float*)d_in[0];
    const float* pos     = (const float*)d_in[1];
    const float* boxf    = (const float*)d_in[2];
    const float* boxp    = (const float*)d_in[3];
    const int*   vcoords = (const int*)  d_in[4];
    const int*   bcoords = (const int*)  d_in[5];
    const int*   vinds   = (const int*)  d_in[6];
    const float* Wq = (const float*)d_in[7];  const float* bq  = (const float*)d_in[8];
    const float* Wk = (const float*)d_in[9];  const float* bk  = (const float*)d_in[10];
    const float* Wv = (const float*)d_in[11]; const float* bv  = (const float*)d_in[12];
    const float* Wo = (const float*)d_in[13]; const float* bo  = (const float*)d_in[14];
    const float* W1 = (const float*)d_in[15]; const float* b1  = (const float*)d_in[16];
    const float* W2 = (const float*)d_in[17]; const float* b2  = (const float*)d_in[18];
    const float* g1 = (const float*)d_in[19]; const float* be1 = (const float*)d_in[20];
    const float* g2 = (const float*)d_in[21]; const float* be2 = (const float*)d_in[22];
    float* out = (float*)d_out;

    float *qb, *projb, *xb, *yb, *kb, *vb;
    int* fpb;
    __half *ctxh, *xh, *hh, *wh, *khg, *vtg;
    cudaGetSymbolAddress((void**)&qb,    g_q);
    cudaGetSymbolAddress((void**)&projb, g_proj);
    cudaGetSymbolAddress((void**)&xb,    g_x);
    cudaGetSymbolAddress((void**)&yb,    g_y);
    cudaGetSymbolAddress((void**)&kb,    g_k);
    cudaGetSymbolAddress((void**)&vb,    g_v);
    cudaGetSymbolAddress((void**)&fpb,   g_fp);
    cudaGetSymbolAddress((void**)&ctxh,  g_ctxh);
    cudaGetSymbolAddress((void**)&xh,    g_xh);
    cudaGetSymbolAddress((void**)&hh,    g_hh);
    cudaGetSymbolAddress((void**)&wh,    g_wh);
    cudaGetSymbolAddress((void**)&khg,   g_kh);
    cudaGetSymbolAddress((void**)&vtg,   g_vt);

    cudaFuncSetAttribute(attn_mma, cudaFuncAttributeMaxDynamicSharedMemorySize, ATTN_SMEM);

    const int MB = N_PTS / 128;   // 720

    // 1: weight conversion
    cvt_weights_kernel<<<(368640/4 + 255)/256, 256>>>(Wq, Wo, W1, W2, wh);
    // 2: K/V projections
    gemm_kv<<<dim3(D_DIM/BN, M_BOX/BM, 2), 256>>>(boxf, boxp, Wk, bk, kb, Wv, bv, vb);
    // 3: pack K/V into attention-ready fp16 layouts
    kv_pack<<<(H_HEADS * M_BOX) / 256, 256>>>(kb, vb, khg, vtg);
    // 4: Q = (src + pos) @ Wq^T + bq (fused add+cvt on load)
    hgemm<false, false, true><<<dim3(D_DIM/64, MB), 256>>>(nullptr, src, pos, wh + WOFF_Q, bq, qb, nullptr, D_DIM, D_DIM);
    // 5: tensor-core masked attention
    attn_mma<<<dim3(S_SETS, H_HEADS), 256, ATTN_SMEM>>>(qb, khg, vtg, vinds, vcoords, bcoords, ctxh);
    // 6: O projection
    hgemm<false, false, false><<<dim3(D_DIM/64, MB), 256>>>(ctxh, nullptr, nullptr, wh + WOFF_O, bo, projb, nullptr, D_DIM, D_DIM);
    // 7,8: first-occurrence scatter index
    init_fp_kernel<<<N_PTS / 256, 256>>>(fpb);
    fill_fp_kernel<<<(S_SETS * L_LEN) / 256, 256>>>(vinds, fpb);
    // 9: x = LN(src + proj[first_pos]) (+ half copy)
    ln_kernel<true, true><<<N_PTS / 8, 256>>>(src, projb, fpb, g1, be1, xb, xh);
    // 10,11: FFN
    hgemm<true,  true,  false><<<dim3(FF_DIM/64, MB), 256>>>(xh, nullptr, nullptr, wh + WOFF_1, b1, nullptr, hh, D_DIM, FF_DIM);
    hgemm<false, false, false><<<dim3(D_DIM/64, MB), 256>>>(hh, nullptr, nullptr, wh + WOFF_2, b2, yb, nullptr, FF_DIM, D_DIM);
    // 12: out = LN(x + ffn)
    ln_kernel<false, false><<<N_PTS / 8, 256>>>(xb, yb, nullptr, g2, be2, out, nullptr);
}

// round 11
// speedup vs baseline: 3.1588x; 1.0821x over previous
#include <cuda_runtime.h>
#include <cuda_fp16.h>
#include <math_constants.h>
#include <cstdint>

#define N_PTS   92160
#define D_DIM   192
#define BD_DIM  256
#define H_HEADS 8
#define FF_DIM  768
#define S_SETS  2560
#define L_LEN   36
#define M_BOX   256
#define HD_DIM  24

// ---------------- scratch (static device globals; no allocation) ----------------
__device__ float g_q[N_PTS * D_DIM];
__device__ float g_proj[N_PTS * D_DIM];
__device__ float g_x[N_PTS * D_DIM];
__device__ float g_y[N_PTS * D_DIM];
__device__ float g_k[M_BOX * D_DIM];
__device__ float g_v[M_BOX * D_DIM];
__device__ int   g_fp[N_PTS];

__device__ __half g_ctxh[N_PTS * D_DIM];
__device__ __half g_xh[N_PTS * D_DIM];
__device__ __half g_hh[(size_t)N_PTS * FF_DIM];
__device__ __half g_kh[H_HEADS * M_BOX * 32];      // [h][m][32] padded fp16 K
__device__ __half g_vt[H_HEADS * HD_DIM * M_BOX];  // [h][d][m]  transposed fp16 V
#define WOFF_Q 0
#define WOFF_O 36864
#define WOFF_1 73728
#define WOFF_2 221184
__device__ __half g_wh[368640];

__device__ __forceinline__ void mma16816(float* d, const uint32_t* a, const uint32_t* b) {
    asm volatile(
        "mma.sync.aligned.m16n8k16.row.col.f32.f16.f16.f32 "
        "{%0,%1,%2,%3}, {%4,%5,%6,%7}, {%8,%9}, {%0,%1,%2,%3};\n"
        : "+f"(d[0]), "+f"(d[1]), "+f"(d[2]), "+f"(d[3])
        : "r"(a[0]), "r"(a[1]), "r"(a[2]), "r"(a[3]), "r"(b[0]), "r"(b[1]));
}

__device__ __forceinline__ uint4 add_cvt8(const float* p, const float* q) {
    float4 x0 = *(const float4*)p;
    float4 x1 = *(const float4*)(p + 4);
    float4 y0 = *(const float4*)q;
    float4 y1 = *(const float4*)(q + 4);
    __half2 h0 = __floats2half2_rn(x0.x + y0.x, x0.y + y0.y);
    __half2 h1 = __floats2half2_rn(x0.z + y0.z, x0.w + y0.w);
    __half2 h2 = __floats2half2_rn(x1.x + y1.x, x1.y + y1.y);
    __half2 h3 = __floats2half2_rn(x1.z + y1.z, x1.w + y1.w);
    uint4 r;
    r.x = *(uint32_t*)&h0; r.y = *(uint32_t*)&h1;
    r.z = *(uint32_t*)&h2; r.w = *(uint32_t*)&h3;
    return r;
}

// ================= A-resident fp16 GEMM for K=192: C = A @ W^T + bias =================
// A tile (128 x 192) lives in smem for the whole kernel; CTA loops over all NTILES
// n-tiles of 64, streaming W chunks (64 x 32) with register-prefetch double buffer.
// smem: As 128*200 halves @0 | Wb[2] 64*40 halves @25600/@28160  (61440 B dynamic)
#define ARES_SMEM ((128 * 200 + 2 * 64 * 40) * 2)

template<bool RELU, bool OUTH, bool ADDIN, int NTILES>
__global__ __launch_bounds__(256)
void hgemm_ares(const __half* __restrict__ A, const float* __restrict__ Af,
                const float* __restrict__ Af2, const __half* __restrict__ W,
                const float* __restrict__ bias, float* __restrict__ C,
                __half* __restrict__ Ch, int Dout)
{
    extern __shared__ __half dsm[];
    __half* As = dsm;                 // 128 x 200
    __half* Wb0 = dsm + 25600;        // 64 x 40
    __half* Wb1 = dsm + 28160;

    const int tid  = threadIdx.x;
    const int lane = tid & 31;
    const int wid  = tid >> 5;
    const int wm   = wid & 3;          // m band
    const int wn   = wid >> 2;         // n band (0/1)
    const int m0   = blockIdx.x * 128;
    const int lr   = lane >> 2;
    const int lc2  = (lane & 3) * 2;

    // ---- load A resident: 128 x 192 halves = 3072 uint4, 12 per thread ----
    #pragma unroll
    for (int j = 0; j < 12; j++) {
        const int idx = tid + 256 * j;        // 0..3071
        const int r = idx / 24, c8 = (idx % 24) * 8;
        const size_t go = (size_t)(m0 + r) * 192 + c8;
        uint4 v;
        if (ADDIN) v = add_cvt8(Af + go, Af2 + go);
        else       v = *(const uint4*)(A + go);
        *(uint4*)(As + r * 200 + c8) = v;
    }

    // ---- W chunk loader: per thread one uint4: row rw, col cw of a 64x32 chunk ----
    const int rw = tid >> 2;             // 0..63
    const int cw = (tid & 3) * 8;        // 0,8,16,24
    const int sW = rw * 40 + cw;

    const int NI = NTILES * 6;
    uint4 pw = *(const uint4*)(W + (size_t)rw * 192 + cw);   // i=0: nt=0, kc=0
    *(uint4*)(Wb0 + sW) = pw;

    float acc[2][4][4];

    for (int i = 0; i < NI; ++i) {
        const int nt = i / 6, kc = i % 6;
        __syncthreads();

        if (kc == 0) {
            #pragma unroll
            for (int a = 0; a < 2; a++)
                #pragma unroll
                for (int b = 0; b < 4; b++)
                    #pragma unroll
                    for (int e = 0; e < 4; e++) acc[a][b][e] = 0.f;
        }

        // prefetch W for i+1
        if (i + 1 < NI) {
            const int nt2 = (i + 1) / 6, kc2 = (i + 1) % 6;
            pw = *(const uint4*)(W + (size_t)(nt2 * 64 + rw) * 192 + kc2 * 32 + cw);
        }

        const __half* Ws = (i & 1) ? Wb1 : Wb0;
        const int ca = kc * 32;

        #pragma unroll
        for (int ks = 0; ks < 32; ks += 16) {
            uint32_t af[2][4], bf[4][2];
            #pragma unroll
            for (int a = 0; a < 2; a++) {
                const __half* p = As + (wm * 32 + a * 16 + lr) * 200 + ca + ks + lc2;
                af[a][0] = *(const uint32_t*)(p);
                af[a][1] = *(const uint32_t*)(p + 8 * 200);
                af[a][2] = *(const uint32_t*)(p + 8);
                af[a][3] = *(const uint32_t*)(p + 8 * 200 + 8);
            }
            #pragma unroll
            for (int b = 0; b < 4; b++) {
                const __half* p = Ws + (wn * 32 + b * 8 + lr) * 40 + ks + lc2;
                bf[b][0] = *(const uint32_t*)(p);
                bf[b][1] = *(const uint32_t*)(p + 8);
            }
            #pragma unroll
            for (int a = 0; a < 2; a++)
                #pragma unroll
                for (int b = 0; b < 4; b++)
                    mma16816(acc[a][b], af[a], bf[b]);
        }

        // epilogue for this n-tile after its last chunk
        if (kc == 5) {
            const int n0 = nt * 64;
            #pragma unroll
            for (int a = 0; a < 2; a++) {
                const int r = m0 + wm * 32 + a * 16 + lr;
                #pragma unroll
                for (int b = 0; b < 4; b++) {
                    const int cj = n0 + wn * 32 + b * 8 + lc2;
                    const float2 bx = *(const float2*)(bias + cj);
                    float v0 = acc[a][b][0] + bx.x;
                    float v1 = acc[a][b][1] + bx.y;
                    float v2 = acc[a][b][2] + bx.x;
                    float v3 = acc[a][b][3] + bx.y;
                    if (RELU) {
                        v0 = fmaxf(v0, 0.f); v1 = fmaxf(v1, 0.f);
                        v2 = fmaxf(v2, 0.f); v3 = fmaxf(v3, 0.f);
                    }
                    if (OUTH) {
                        *(__half2*)(Ch + (size_t)r       * Dout + cj) = __floats2half2_rn(v0, v1);
                        *(__half2*)(Ch + (size_t)(r + 8) * Dout + cj) = __floats2half2_rn(v2, v3);
                    } else {
                        *(float2*)(C + (size_t)r       * Dout + cj) = make_float2(v0, v1);
                        *(float2*)(C + (size_t)(r + 8) * Dout + cj) = make_float2(v2, v3);
                    }
                }
            }
        }

        if (i + 1 < NI) {
            __half* nb = ((i + 1) & 1) ? Wb1 : Wb0;
            *(uint4*)(nb + sW) = pw;
        }
    }
}

// ================= fp16 mma.sync GEMM (generic K): used for FFN2 =================
#define HPAD 40

template<bool RELU, bool OUTH>
__global__ __launch_bounds__(256)
void hgemm(const __half* __restrict__ A, const __half* __restrict__ W,
           const float* __restrict__ bias, float* __restrict__ C,
           __half* __restrict__ Ch, int K, int Dout)
{
    __shared__ __half sb[2][192 * HPAD];

    const int tid  = threadIdx.x;
    const int lane = tid & 31;
    const int wid  = tid >> 5;
    const int wm   = wid & 3;
    const int wn   = wid >> 2;
    const int m0   = blockIdx.y * 128;
    const int n0   = blockIdx.x * 64;
    const int lr   = lane >> 2;
    const int lc2  = (lane & 3) * 2;

    const int r0 = tid >> 2;
    const int c8 = (tid & 3) * 8;
    const size_t oA0 = (size_t)(m0 + r0)      * K + c8;
    const size_t oA1 = (size_t)(m0 + r0 + 64) * K + c8;
    const __half* gW = W + (size_t)(n0 + r0) * K + c8;
    const int s0 = r0 * HPAD + c8;
    const int s1 = (r0 + 64) * HPAD + c8;
    const int s2 = (r0 + 128) * HPAD + c8;

    const int nT = K >> 5;

    uint4 pa0 = *(const uint4*)(A + oA0);
    uint4 pa1 = *(const uint4*)(A + oA1);
    uint4 pw  = *(const uint4*)gW;

    float acc[2][4][4];
    #pragma unroll
    for (int i = 0; i < 2; i++)
        #pragma unroll
        for (int j = 0; j < 4; j++)
            #pragma unroll
            for (int e = 0; e < 4; e++) acc[i][j][e] = 0.f;

    *(uint4*)(sb[0] + s0) = pa0;
    *(uint4*)(sb[0] + s1) = pa1;
    *(uint4*)(sb[0] + s2) = pw;

    for (int t = 0; t < nT; ++t) {
        __syncthreads();

        if (t + 1 < nT) {
            const int off = (t + 1) * 32;
            pa0 = *(const uint4*)(A + oA0 + off);
            pa1 = *(const uint4*)(A + oA1 + off);
            pw  = *(const uint4*)(gW + off);
        }

        const __half* As = sb[t & 1];
        const __half* Ws = As + 128 * HPAD;

        #pragma unroll
        for (int ks = 0; ks < 32; ks += 16) {
            uint32_t af[2][4], bf[4][2];
            #pragma unroll
            for (int i = 0; i < 2; i++) {
                const int base = (wm * 32 + i * 16 + lr) * HPAD + ks + lc2;
                af[i][0] = *(const uint32_t*)(As + base);
                af[i][1] = *(const uint32_t*)(As + base + 8 * HPAD);
                af[i][2] = *(const uint32_t*)(As + base + 8);
                af[i][3] = *(const uint32_t*)(As + base + 8 * HPAD + 8);
            }
            #pragma unroll
            for (int j = 0; j < 4; j++) {
                const int base = (wn * 32 + j * 8 + lr) * HPAD + ks + lc2;
                bf[j][0] = *(const uint32_t*)(Ws + base);
                bf[j][1] = *(const uint32_t*)(Ws + base + 8);
            }
            #pragma unroll
            for (int i = 0; i < 2; i++)
                #pragma unroll
                for (int j = 0; j < 4; j++)
                    mma16816(acc[i][j], af[i], bf[j]);
        }

        if (t + 1 < nT) {
            __half* nb = sb[(t + 1) & 1];
            *(uint4*)(nb + s0) = pa0;
            *(uint4*)(nb + s1) = pa1;
            *(uint4*)(nb + s2) = pw;
        }
    }

    float2 bx[4];
    #pragma unroll
    for (int j = 0; j < 4; j++) {
        const int cj = n0 + wn * 32 + j * 8 + lc2;
        bx[j] = *(const float2*)(bias + cj);
    }
    #pragma unroll
    for (int i = 0; i < 2; i++) {
        const int r = m0 + wm * 32 + i * 16 + lr;
        #pragma unroll
        for (int j = 0; j < 4; j++) {
            const int cj = n0 + wn * 32 + j * 8 + lc2;
            float v0 = acc[i][j][0] + bx[j].x;
            float v1 = acc[i][j][1] + bx[j].y;
            float v2 = acc[i][j][2] + bx[j].x;
            float v3 = acc[i][j][3] + bx[j].y;
            if (RELU) {
                v0 = fmaxf(v0, 0.f); v1 = fmaxf(v1, 0.f);
                v2 = fmaxf(v2, 0.f); v3 = fmaxf(v3, 0.f);
            }
            if (OUTH) {
                *(__half2*)(Ch + (size_t)r       * Dout + cj) = __floats2half2_rn(v0, v1);
                *(__half2*)(Ch + (size_t)(r + 8) * Dout + cj) = __floats2half2_rn(v2, v3);
            } else {
                *(float2*)(C + (size_t)r       * Dout + cj) = make_float2(v0, v1);
                *(float2*)(C + (size_t)(r + 8) * Dout + cj) = make_float2(v2, v3);
            }
        }
    }
}

// ---------------- combined K/V projection (SIMT fp32), blockIdx.z selects ----------------
#define BM 128
#define BN 64
#define BK 16

__global__ __launch_bounds__(256, 2)
void gemm_kv(const float* __restrict__ boxf, const float* __restrict__ boxp,
             const float* __restrict__ Wk, const float* __restrict__ bk, float* __restrict__ Ck,
             const float* __restrict__ Wv, const float* __restrict__ bv, float* __restrict__ Cv)
{
    const bool isK = (blockIdx.z == 0);
    const float* A   = boxf;
    const float* A2  = isK ? boxp : nullptr;
    const float* W   = isK ? Wk : Wv;
    const float* bias= isK ? bk : bv;
    float* C         = isK ? Ck : Cv;
    const int K = BD_DIM, Dout = D_DIM;

    __shared__ float As[BK][BM + 4];
    __shared__ float Ws[BK][BN + 4];

    const int tid = threadIdx.x;
    const int tx = tid & 15;
    const int ty = tid >> 4;
    const int m0 = blockIdx.y * BM;
    const int n0 = blockIdx.x * BN;

    const int ar = tid >> 2;
    const int ac = (tid & 3) << 2;

    const float* Ap0 = A + (size_t)(m0 + ar)      * K + ac;
    const float* Ap1 = A + (size_t)(m0 + ar + 64) * K + ac;
    const float* Wp  = W + (size_t)(n0 + ar)      * K + ac;

    const int nT = K / BK;

    float4 pa0 = *(const float4*)(Ap0);
    float4 pa1 = *(const float4*)(Ap1);
    float4 pw  = *(const float4*)(Wp);
    if (isK) {
        const float* B0 = A2 + (size_t)(m0 + ar) * K + ac;
        const float* B1 = A2 + (size_t)(m0 + ar + 64) * K + ac;
        float4 q0 = *(const float4*)B0;
        float4 q1 = *(const float4*)B1;
        pa0.x += q0.x; pa0.y += q0.y; pa0.z += q0.z; pa0.w += q0.w;
        pa1.x += q1.x; pa1.y += q1.y; pa1.z += q1.z; pa1.w += q1.w;
    }

    float acc[8][4];
    #pragma unroll
    for (int i = 0; i < 8; i++)
        #pragma unroll
        for (int j = 0; j < 4; j++) acc[i][j] = 0.f;

    for (int t = 0; t < nT; ++t) {
        As[ac+0][ar]    = pa0.x; As[ac+1][ar]    = pa0.y;
        As[ac+2][ar]    = pa0.z; As[ac+3][ar]    = pa0.w;
        As[ac+0][ar+64] = pa1.x; As[ac+1][ar+64] = pa1.y;
        As[ac+2][ar+64] = pa1.z; As[ac+3][ar+64] = pa1.w;
        Ws[ac+0][ar]    = pw.x;  Ws[ac+1][ar]    = pw.y;
        Ws[ac+2][ar]    = pw.z;  Ws[ac+3][ar]    = pw.w;
        __syncthreads();

        if (t + 1 < nT) {
            const int off = (t + 1) * BK;
            pa0 = *(const float4*)(Ap0 + off);
            pa1 = *(const float4*)(Ap1 + off);
            pw  = *(const float4*)(Wp  + off);
            if (isK) {
                const float* B0 = A2 + (size_t)(m0 + ar) * K + ac + off;
                const float* B1 = A2 + (size_t)(m0 + ar + 64) * K + ac + off;
                float4 q0 = *(const float4*)B0;
                float4 q1 = *(const float4*)B1;
                pa0.x += q0.x; pa0.y += q0.y; pa0.z += q0.z; pa0.w += q0.w;
                pa1.x += q1.x; pa1.y += q1.y; pa1.z += q1.z; pa1.w += q1.w;
            }
        }

        #pragma unroll
        for (int k = 0; k < BK; ++k) {
            float a[8], w[4];
            #pragma unroll
            for (int i = 0; i < 8; i++) a[i] = As[k][ty * 8 + i];
            #pragma unroll
            for (int j = 0; j < 4; j++) w[j] = Ws[k][tx * 4 + j];
            #pragma unroll
            for (int i = 0; i < 8; i++)
                #pragma unroll
                for (int j = 0; j < 4; j++) acc[i][j] += a[i] * w[j];
        }
        __syncthreads();
    }

    const float b0 = bias[n0 + tx*4 + 0];
    const float b1 = bias[n0 + tx*4 + 1];
    const float b2 = bias[n0 + tx*4 + 2];
    const float b3 = bias[n0 + tx*4 + 3];
    #pragma unroll
    for (int i = 0; i < 8; i++) {
        float4 o;
        o.x = acc[i][0] + b0; o.y = acc[i][1] + b1;
        o.z = acc[i][2] + b2; o.w = acc[i][3] + b3;
        *(float4*)(C + (size_t)(m0 + ty*8 + i) * Dout + n0 + tx*4) = o;
    }
}

// ---------------- K/V pack: fp32 -> fp16, K padded [h][m][32], V transposed [h][d][m] ----------------
__global__ void kv_pack(const float* __restrict__ kb, const float* __restrict__ vb,
                        __half* __restrict__ khg, __half* __restrict__ vtg)
{
    const int i = blockIdx.x * 256 + threadIdx.x;   // 0..2047
    if (i >= H_HEADS * M_BOX) return;
    const int h = i >> 8, m = i & 255;

    {
        const float4* kp = (const float4*)(kb + (size_t)m * D_DIM + h * HD_DIM);
        __half2 hrow[16];
        #pragma unroll
        for (int j = 0; j < 6; j++) {
            float4 f = kp[j];
            hrow[2*j]   = __floats2half2_rn(f.x, f.y);
            hrow[2*j+1] = __floats2half2_rn(f.z, f.w);
        }
        const __half2 zz = __floats2half2_rn(0.f, 0.f);
        hrow[12] = zz; hrow[13] = zz; hrow[14] = zz; hrow[15] = zz;
        uint4* dst = (uint4*)(khg + ((size_t)h * M_BOX + m) * 32);
        dst[0] = ((const uint4*)hrow)[0];
        dst[1] = ((const uint4*)hrow)[1];
        dst[2] = ((const uint4*)hrow)[2];
        dst[3] = ((const uint4*)hrow)[3];
    }
    {
        const float4* vp = (const float4*)(vb + (size_t)m * D_DIM + h * HD_DIM);
        __half* base = vtg + (size_t)h * HD_DIM * M_BOX + m;
        #pragma unroll
        for (int j = 0; j < 6; j++) {
            float4 g = vp[j];
            base[(4*j+0) * M_BOX] = __float2half(g.x);
            base[(4*j+1) * M_BOX] = __float2half(g.y);
            base[(4*j+2) * M_BOX] = __float2half(g.z);
            base[(4*j+3) * M_BOX] = __float2half(g.w);
        }
    }
}

// ================= tensor-core attention: one CTA per (set, head) =================
#define AT_QS   0
#define AT_KS   1920
#define AT_VT   12160
#define AT_PS   18496
#define AT_INT  31168
#define ATTN_SMEM (31168 * 2 + (36 + 256) * 4)

__global__ __launch_bounds__(256)
void attn_mma(const float* __restrict__ qbuf, const __half* __restrict__ khg,
              const __half* __restrict__ vtg, const int* __restrict__ vinds,
              const int* __restrict__ vcoords, const int* __restrict__ bcoords,
              __half* __restrict__ ctxh)
{
    extern __shared__ __half sm[];
    __half* Qs = sm + AT_QS;
    __half* Ks = sm + AT_KS;
    __half* Vt = sm + AT_VT;
    __half* Ps = sm + AT_PS;
    int* qb = (int*)(sm + AT_INT);
    int* bb = qb + 36;

    const int s = blockIdx.x, h = blockIdx.y;
    const int t = threadIdx.x, lane = t & 31, wid = t >> 5;
    const int lr = lane >> 2, lc2 = (lane & 3) * 2;
    const __half2 zz = __floats2half2_rn(0.f, 0.f);

    {
        const uint4* kp = (const uint4*)(khg + ((size_t)h * M_BOX + t) * 32);
        uint4* krow = (uint4*)(Ks + t * 40);
        krow[0] = kp[0];
        krow[1] = kp[1];
        krow[2] = kp[2];
        krow[3] = kp[3];
        bb[t] = bcoords[t * 4];
    }
    {
        const __half* vsrc = vtg + (size_t)h * HD_DIM * M_BOX;
        #pragma unroll
        for (int j = 0; j < 3; j++) {
            const int idx = t + 256 * j;
            const int r = idx >> 5, c = idx & 31;
            *(uint4*)(Vt + r * 264 + c * 8) = *(const uint4*)(vsrc + r * M_BOX + c * 8);
        }
    }
    for (int i = t; i < 36 * 8; i += 256) {
        const int l = i >> 3, c = i & 7;
        __half2* qrow = (__half2*)(Qs + l * 40);
        if (c < 6) {
            float4 f = *(const float4*)(qbuf + (size_t)vinds[s * L_LEN + l] * D_DIM + h * HD_DIM + c * 4);
            qrow[2*c]   = __floats2half2_rn(f.x, f.y);
            qrow[2*c+1] = __floats2half2_rn(f.z, f.w);
        } else {
            qrow[2*c] = zz; qrow[2*c+1] = zz;
        }
    }
    if (t < 36) qb[t] = vcoords[(size_t)vinds[s * L_LEN + t] * 4];
    __syncthreads();

    float acc[3][4][4];
    #pragma unroll
    for (int i = 0; i < 3; i++)
        #pragma unroll
        for (int j = 0; j < 4; j++)
            #pragma unroll
            for (int e = 0; e < 4; e++) acc[i][j][e] = 0.f;

    #pragma unroll
    for (int kk = 0; kk < 2; kk++) {
        const int k0 = kk * 16;
        uint32_t af[3][4], bf[4][2];
        #pragma unroll
        for (int i = 0; i < 3; i++) {
            const __half* p = Qs + (i * 16 + lr) * 40 + k0 + lc2;
            af[i][0] = *(const uint32_t*)(p);
            af[i][1] = *(const uint32_t*)(p + 8 * 40);
            af[i][2] = *(const uint32_t*)(p + 8);
            af[i][3] = *(const uint32_t*)(p + 8 * 40 + 8);
        }
        #pragma unroll
        for (int j = 0; j < 4; j++) {
            const __half* p = Ks + (wid * 32 + j * 8 + lr) * 40 + k0 + lc2;
            bf[j][0] = *(const uint32_t*)(p);
            bf[j][1] = *(const uint32_t*)(p + 8);
        }
        #pragma unroll
        for (int i = 0; i < 3; i++)
            #pragma unroll
            for (int j = 0; j < 4; j++)
                mma16816(acc[i][j], af[i], bf[j]);
    }

    {
        const float scale = 0.20412414523193154f;
        #pragma unroll
        for (int i = 0; i < 3; i++) {
            const int r0 = i * 16 + lr, r1 = r0 + 8;
            const int q0 = (r0 < L_LEN) ? qb[r0] : 0;
            const int q1 = (r1 < L_LEN) ? qb[r1] : 0;
            #pragma unroll
            for (int j = 0; j < 4; j++) {
                const int c = wid * 32 + j * 8 + lc2;
                const int b0 = bb[c], b1 = bb[c + 1];
                if (r0 < L_LEN) {
                    float v0 = (q0 != b0) ? -CUDART_INF_F : acc[i][j][0] * scale;
                    float v1 = (q0 != b1) ? -CUDART_INF_F : acc[i][j][1] * scale;
                    *(__half2*)(Ps + r0 * 264 + c) = __floats2half2_rn(v0, v1);
                }
                if (r1 < L_LEN) {
                    float v2 = (q1 != b0) ? -CUDART_INF_F : acc[i][j][2] * scale;
                    float v3 = (q1 != b1) ? -CUDART_INF_F : acc[i][j][3] * scale;
                    *(__half2*)(Ps + r1 * 264 + c) = __floats2half2_rn(v2, v3);
                }
            }
        }
    }
    __syncthreads();

    for (int l = wid; l < L_LEN; l += 8) {
        __half* row = Ps + l * 264;
        float e[8];
        float mx = -CUDART_INF_F;
        #pragma unroll
        for (int i = 0; i < 8; i++) { e[i] = __half2float(row[lane + 32*i]); mx = fmaxf(mx, e[i]); }
        #pragma unroll
        for (int o = 16; o > 0; o >>= 1) mx = fmaxf(mx, __shfl_xor_sync(0xffffffffu, mx, o));
        float sum = 0.f;
        if (mx > -CUDART_INF_F) {
            #pragma unroll
            for (int i = 0; i < 8; i++) { e[i] = __expf(e[i] - mx); sum += e[i]; }
        } else {
            #pragma unroll
            for (int i = 0; i < 8; i++) e[i] = 0.f;
        }
        #pragma unroll
        for (int o = 16; o > 0; o >>= 1) sum += __shfl_xor_sync(0xffffffffu, sum, o);
        const float inv = sum > 0.f ? 1.0f / sum : 0.f;
        #pragma unroll
        for (int i = 0; i < 8; i++) row[lane + 32*i] = __float2half(e[i] * inv);
    }
    __syncthreads();

    for (int cb = wid; cb < 9; cb += 8) {
        const int mt = cb / 3, nt = cb % 3;
        float a2[4] = {0.f, 0.f, 0.f, 0.f};
        #pragma unroll 4
        for (int kt = 0; kt < 16; kt++) {
            uint32_t af[4], bf[2];
            const __half* pa = Ps + (mt * 16 + lr) * 264 + kt * 16 + lc2;
            af[0] = *(const uint32_t*)(pa);
            af[1] = *(const uint32_t*)(pa + 8 * 264);
            af[2] = *(const uint32_t*)(pa + 8);
            af[3] = *(const uint32_t*)(pa + 8 * 264 + 8);
            const __half* pb = Vt + (nt * 8 + lr) * 264 + kt * 16 + lc2;
            bf[0] = *(const uint32_t*)(pb);
            bf[1] = *(const uint32_t*)(pb + 8);
            mma16816(a2, af, bf);
        }
        const int r0 = mt * 16 + lr, r1 = r0 + 8;
        const int c = nt * 8 + lc2;
        if (r0 < L_LEN)
            *(__half2*)(ctxh + ((size_t)s * L_LEN + r0) * D_DIM + h * HD_DIM + c) = __floats2half2_rn(a2[0], a2[1]);
        if (r1 < L_LEN)
            *(__half2*)(ctxh + ((size_t)s * L_LEN + r1) * D_DIM + h * HD_DIM + c) = __floats2half2_rn(a2[2], a2[3]);
    }
}

// ---------------- first-occurrence scatter index ----------------
__global__ void init_fp_kernel(int* __restrict__ fp)
{
    int i = blockIdx.x * blockDim.x + threadIdx.x;
    if (i < N_PTS) fp[i] = 0x7FFFFFFF;
}

__global__ void fill_fp_kernel(const int* __restrict__ vinds, int* __restrict__ fp)
{
    int p = blockIdx.x * blockDim.x + threadIdx.x;
    if (p < S_SETS * L_LEN) {
        int n = vinds[p];
        if (n >= 0 && n < N_PTS) atomicMin(&fp[n], p);
    }
}

// ---------------- residual + layernorm (warp per row) ----------------
template<bool GATHER, bool OUTH>
__global__ __launch_bounds__(256)
void ln_kernel(const float* __restrict__ a, const float* __restrict__ b,
               const int* __restrict__ fp, const float* __restrict__ gamma,
               const float* __restrict__ beta, float* __restrict__ outp,
               __half* __restrict__ oh)
{
    const int row  = (blockIdx.x * 256 + threadIdx.x) >> 5;
    const int lane = threadIdx.x & 31;
    if (row >= N_PTS) return;

    const float* arow = a + (size_t)row * D_DIM;
    const float* brow;
    if (GATHER) {
        int p = fp[row];
        if (p < 0 || p >= N_PTS) p = row;
        brow = b + (size_t)p * D_DIM;
    } else {
        brow = b + (size_t)row * D_DIM;
    }

    float v[6];
    float s = 0.f;
    #pragma unroll
    for (int i = 0; i < 6; i++) {
        const int idx = lane + 32 * i;
        v[i] = arow[idx] + brow[idx];
        s += v[i];
    }
    #pragma unroll
    for (int o = 16; o > 0; o >>= 1) s += __shfl_xor_sync(0xffffffffu, s, o);
    const float mean = s * (1.0f / D_DIM);

    float q = 0.f;
    #pragma unroll
    for (int i = 0; i < 6; i++) { const float d = v[i] - mean; q += d * d; }
    #pragma unroll
    for (int o = 16; o > 0; o >>= 1) q += __shfl_xor_sync(0xffffffffu, q, o);
    const float inv = rsqrtf(q * (1.0f / D_DIM) + 1e-5f);

    float* orow = outp + (size_t)row * D_DIM;
    #pragma unroll
    for (int i = 0; i < 6; i++) {
        const int idx = lane + 32 * i;
        const float val = (v[i] - mean) * inv * gamma[idx] + beta[idx];
        orow[idx] = val;
        if (OUTH) oh[(size_t)row * D_DIM + idx] = __float2half(val);
    }
}

// ---------------- weight conversion (all four in one launch) ----------------
__global__ void cvt_weights_kernel(const float* __restrict__ Wq, const float* __restrict__ Wo,
                                   const float* __restrict__ W1, const float* __restrict__ W2,
                                   __half* __restrict__ wh)
{
    const int i = blockIdx.x * blockDim.x + threadIdx.x;
    const int n4 = 368640 / 4;
    if (i >= n4) return;
    const int e = i * 4;
    const float* srcp;
    int off;
    if (e < WOFF_O)      { srcp = Wq; off = e - WOFF_Q; }
    else if (e < WOFF_1) { srcp = Wo; off = e - WOFF_O; }
    else if (e < WOFF_2) { srcp = W1; off = e - WOFF_1; }
    else                 { srcp = W2; off = e - WOFF_2; }
    float4 x = *(const float4*)(srcp + off);
    ((__half2*)wh)[2*i]   = __floats2half2_rn(x.x, x.y);
    ((__half2*)wh)[2*i+1] = __floats2half2_rn(x.z, x.w);
}

// ---------------- launch ----------------
extern "C" void kernel_launch(void* const* d_in, const int* in_sizes, int n_in,
                              void* d_out, int out_size)
{
    const float* src     = (const float*)d_in[0];
    const float* pos     = (const float*)d_in[1];
    const float* boxf    = (const float*)d_in[2];
    const float* boxp    = (const float*)d_in[3];
    const int*   vcoords = (const int*)  d_in[4];
    const int*   bcoords = (const int*)  d_in[5];
    const int*   vinds   = (const int*)  d_in[6];
    const float* Wq = (const float*)d_in[7];  const float* bq  = (const float*)d_in[8];
    const float* Wk = (const float*)d_in[9];  const float* bk  = (const float*)d_in[10];
    const float* Wv = (const float*)d_in[11]; const float* bv  = (const float*)d_in[12];
    const float* Wo = (const float*)d_in[13]; const float* bo  = (const float*)d_in[14];
    const float* W1 = (const float*)d_in[15]; const float* b1  = (const float*)d_in[16];
    const float* W2 = (const float*)d_in[17]; const float* b2  = (const float*)d_in[18];
    const float* g1 = (const float*)d_in[19]; const float* be1 = (const float*)d_in[20];
    const float* g2 = (const float*)d_in[21]; const float* be2 = (const float*)d_in[22];
    float* out = (float*)d_out;

    float *qb, *projb, *xb, *yb, *kb, *vb;
    int* fpb;
    __half *ctxh, *xh, *hh, *wh, *khg, *vtg;
    cudaGetSymbolAddress((void**)&qb,    g_q);
    cudaGetSymbolAddress((void**)&projb, g_proj);
    cudaGetSymbolAddress((void**)&xb,    g_x);
    cudaGetSymbolAddress((void**)&yb,    g_y);
    cudaGetSymbolAddress((void**)&kb,    g_k);
    cudaGetSymbolAddress((void**)&vb,    g_v);
    cudaGetSymbolAddress((void**)&fpb,   g_fp);
    cudaGetSymbolAddress((void**)&ctxh,  g_ctxh);
    cudaGetSymbolAddress((void**)&xh,    g_xh);
    cudaGetSymbolAddress((void**)&hh,    g_hh);
    cudaGetSymbolAddress((void**)&wh,    g_wh);
    cudaGetSymbolAddress((void**)&khg,   g_kh);
    cudaGetSymbolAddress((void**)&vtg,   g_vt);

    cudaFuncSetAttribute(attn_mma, cudaFuncAttributeMaxDynamicSharedMemorySize, ATTN_SMEM);
    cudaFuncSetAttribute(hgemm_ares<false, false, true,  3>,  cudaFuncAttributeMaxDynamicSharedMemorySize, ARES_SMEM);
    cudaFuncSetAttribute(hgemm_ares<false, false, false, 3>,  cudaFuncAttributeMaxDynamicSharedMemorySize, ARES_SMEM);
    cudaFuncSetAttribute(hgemm_ares<true,  true,  false, 12>, cudaFuncAttributeMaxDynamicSharedMemorySize, ARES_SMEM);

    const int MB = N_PTS / 128;   // 720

    // 1: weight conversion
    cvt_weights_kernel<<<(368640/4 + 255)/256, 256>>>(Wq, Wo, W1, W2, wh);
    // 2: K/V projections
    gemm_kv<<<dim3(D_DIM/BN, M_BOX/BM, 2), 256>>>(boxf, boxp, Wk, bk, kb, Wv, bv, vb);
    // 3: pack K/V into attention-ready fp16 layouts
    kv_pack<<<(H_HEADS * M_BOX) / 256, 256>>>(kb, vb, khg, vtg);
    // 4: Q = (src + pos) @ Wq^T + bq  (A-resident, fused add+cvt)
    hgemm_ares<false, false, true, 3><<<MB, 256, ARES_SMEM>>>(nullptr, src, pos, wh + WOFF_Q, bq, qb, nullptr, D_DIM);
    // 5: tensor-core masked attention
    attn_mma<<<dim3(S_SETS, H_HEADS), 256, ATTN_SMEM>>>(qb, khg, vtg, vinds, vcoords, bcoords, ctxh);
    // 6: O projection (A-resident)
    hgemm_ares<false, false, false, 3><<<MB, 256, ARES_SMEM>>>(ctxh, nullptr, nullptr, wh + WOFF_O, bo, projb, nullptr, D_DIM);
    // 7,8: first-occurrence scatter index
    init_fp_kernel<<<N_PTS / 256, 256>>>(fpb);
    fill_fp_kernel<<<(S_SETS * L_LEN) / 256, 256>>>(vinds, fpb);
    // 9: x = LN(src + proj[first_pos]) (+ half copy)
    ln_kernel<true, true><<<N_PTS / 8, 256>>>(src, projb, fpb, g1, be1, xb, xh);
    // 10: FFN1 (A-resident, relu, half out)
    hgemm_ares<true, true, false, 12><<<MB, 256, ARES_SMEM>>>(xh, nullptr, nullptr, wh + WOFF_1, b1, nullptr, hh, FF_DIM);
    // 11: FFN2 (K=768, streaming kernel)
    hgemm<false, false><<<dim3(D_DIM/64, MB), 256>>>(hh, wh + WOFF_2, b2, yb, nullptr, FF_DIM, D_DIM);
    // 12: out = LN(x + ffn)
    ln_kernel<false, false><<<N_PTS / 8, 256>>>(xb, yb, nullptr, g2, be2, out, nullptr);
}

// round 12
// speedup vs baseline: 3.3581x; 1.0631x over previous
#include <cuda_runtime.h>
#include <cuda_fp16.h>
#include <math_constants.h>
#include <cstdint>

#define N_PTS   92160
#define D_DIM   192
#define BD_DIM  256
#define H_HEADS 8
#define FF_DIM  768
#define S_SETS  2560
#define L_LEN   36
#define M_BOX   256
#define HD_DIM  24

// ---------------- scratch (static device globals; no allocation) ----------------
__device__ float g_proj[N_PTS * D_DIM];
__device__ float g_x[N_PTS * D_DIM];
__device__ float g_y[N_PTS * D_DIM];
__device__ float g_k[M_BOX * D_DIM];
__device__ float g_v[M_BOX * D_DIM];
__device__ int   g_fp[N_PTS];

__device__ __half g_qh[N_PTS * D_DIM];
__device__ __half g_ctxh[N_PTS * D_DIM];
__device__ __half g_xh[N_PTS * D_DIM];
__device__ __half g_hh[(size_t)N_PTS * FF_DIM];
__device__ __half g_kh[H_HEADS * M_BOX * 32];      // [h][m][32] padded fp16 K
__device__ __half g_vt[H_HEADS * HD_DIM * M_BOX];  // [h][d][m]  transposed fp16 V
#define WOFF_Q 0
#define WOFF_O 36864
#define WOFF_1 73728
#define WOFF_2 221184
__device__ __half g_wh[368640];

__device__ __forceinline__ void mma16816(float* d, const uint32_t* a, const uint32_t* b) {
    asm volatile(
        "mma.sync.aligned.m16n8k16.row.col.f32.f16.f16.f32 "
        "{%0,%1,%2,%3}, {%4,%5,%6,%7}, {%8,%9}, {%0,%1,%2,%3};\n"
        : "+f"(d[0]), "+f"(d[1]), "+f"(d[2]), "+f"(d[3])
        : "r"(a[0]), "r"(a[1]), "r"(a[2]), "r"(a[3]), "r"(b[0]), "r"(b[1]));
}

__device__ __forceinline__ uint4 add_cvt8(const float* p, const float* q) {
    float4 x0 = *(const float4*)p;
    float4 x1 = *(const float4*)(p + 4);
    float4 y0 = *(const float4*)q;
    float4 y1 = *(const float4*)(q + 4);
    __half2 h0 = __floats2half2_rn(x0.x + y0.x, x0.y + y0.y);
    __half2 h1 = __floats2half2_rn(x0.z + y0.z, x0.w + y0.w);
    __half2 h2 = __floats2half2_rn(x1.x + y1.x, x1.y + y1.y);
    __half2 h3 = __floats2half2_rn(x1.z + y1.z, x1.w + y1.w);
    uint4 r;
    r.x = *(uint32_t*)&h0; r.y = *(uint32_t*)&h1;
    r.z = *(uint32_t*)&h2; r.w = *(uint32_t*)&h3;
    return r;
}

// ================= A-resident fp16 GEMM for K=192: C = A @ W^T + bias =================
#define ARES_SMEM ((128 * 200 + 2 * 64 * 40) * 2)

template<bool RELU, bool OUTH, bool ADDIN, int NTILES>
__global__ __launch_bounds__(256)
void hgemm_ares(const __half* __restrict__ A, const float* __restrict__ Af,
                const float* __restrict__ Af2, const __half* __restrict__ W,
                const float* __restrict__ bias, float* __restrict__ C,
                __half* __restrict__ Ch, int Dout)
{
    extern __shared__ __half dsm[];
    __half* As = dsm;                 // 128 x 200
    __half* Wb0 = dsm + 25600;        // 64 x 40
    __half* Wb1 = dsm + 28160;

    const int tid  = threadIdx.x;
    const int lane = tid & 31;
    const int wid  = tid >> 5;
    const int wm   = wid & 3;
    const int wn   = wid >> 2;
    const int m0   = blockIdx.x * 128;
    const int lr   = lane >> 2;
    const int lc2  = (lane & 3) * 2;

    #pragma unroll
    for (int j = 0; j < 12; j++) {
        const int idx = tid + 256 * j;
        const int r = idx / 24, c8 = (idx % 24) * 8;
        const size_t go = (size_t)(m0 + r) * 192 + c8;
        uint4 v;
        if (ADDIN) v = add_cvt8(Af + go, Af2 + go);
        else       v = *(const uint4*)(A + go);
        *(uint4*)(As + r * 200 + c8) = v;
    }

    const int rw = tid >> 2;
    const int cw = (tid & 3) * 8;
    const int sW = rw * 40 + cw;

    const int NI = NTILES * 6;
    uint4 pw = *(const uint4*)(W + (size_t)rw * 192 + cw);
    *(uint4*)(Wb0 + sW) = pw;

    float acc[2][4][4];

    for (int i = 0; i < NI; ++i) {
        const int nt = i / 6, kc = i % 6;
        __syncthreads();

        if (kc == 0) {
            #pragma unroll
            for (int a = 0; a < 2; a++)
                #pragma unroll
                for (int b = 0; b < 4; b++)
                    #pragma unroll
                    for (int e = 0; e < 4; e++) acc[a][b][e] = 0.f;
        }

        if (i + 1 < NI) {
            const int nt2 = (i + 1) / 6, kc2 = (i + 1) % 6;
            pw = *(const uint4*)(W + (size_t)(nt2 * 64 + rw) * 192 + kc2 * 32 + cw);
        }

        const __half* Ws = (i & 1) ? Wb1 : Wb0;
        const int ca = kc * 32;

        #pragma unroll
        for (int ks = 0; ks < 32; ks += 16) {
            uint32_t af[2][4], bf[4][2];
            #pragma unroll
            for (int a = 0; a < 2; a++) {
                const __half* p = As + (wm * 32 + a * 16 + lr) * 200 + ca + ks + lc2;
                af[a][0] = *(const uint32_t*)(p);
                af[a][1] = *(const uint32_t*)(p + 8 * 200);
                af[a][2] = *(const uint32_t*)(p + 8);
                af[a][3] = *(const uint32_t*)(p + 8 * 200 + 8);
            }
            #pragma unroll
            for (int b = 0; b < 4; b++) {
                const __half* p = Ws + (wn * 32 + b * 8 + lr) * 40 + ks + lc2;
                bf[b][0] = *(const uint32_t*)(p);
                bf[b][1] = *(const uint32_t*)(p + 8);
            }
            #pragma unroll
            for (int a = 0; a < 2; a++)
                #pragma unroll
                for (int b = 0; b < 4; b++)
                    mma16816(acc[a][b], af[a], bf[b]);
        }

        if (kc == 5) {
            const int n0 = nt * 64;
            #pragma unroll
            for (int a = 0; a < 2; a++) {
                const int r = m0 + wm * 32 + a * 16 + lr;
                #pragma unroll
                for (int b = 0; b < 4; b++) {
                    const int cj = n0 + wn * 32 + b * 8 + lc2;
                    const float2 bx = *(const float2*)(bias + cj);
                    float v0 = acc[a][b][0] + bx.x;
                    float v1 = acc[a][b][1] + bx.y;
                    float v2 = acc[a][b][2] + bx.x;
                    float v3 = acc[a][b][3] + bx.y;
                    if (RELU) {
                        v0 = fmaxf(v0, 0.f); v1 = fmaxf(v1, 0.f);
                        v2 = fmaxf(v2, 0.f); v3 = fmaxf(v3, 0.f);
                    }
                    if (OUTH) {
                        *(__half2*)(Ch + (size_t)r       * Dout + cj) = __floats2half2_rn(v0, v1);
                        *(__half2*)(Ch + (size_t)(r + 8) * Dout + cj) = __floats2half2_rn(v2, v3);
                    } else {
                        *(float2*)(C + (size_t)r       * Dout + cj) = make_float2(v0, v1);
                        *(float2*)(C + (size_t)(r + 8) * Dout + cj) = make_float2(v2, v3);
                    }
                }
            }
        }

        if (i + 1 < NI) {
            __half* nb = ((i + 1) & 1) ? Wb1 : Wb0;
            *(uint4*)(nb + sW) = pw;
        }
    }
}

// ================= fp16 mma.sync GEMM (generic K): used for FFN2 =================
#define HPAD 40

template<bool RELU, bool OUTH>
__global__ __launch_bounds__(256)
void hgemm(const __half* __restrict__ A, const __half* __restrict__ W,
           const float* __restrict__ bias, float* __restrict__ C,
           __half* __restrict__ Ch, int K, int Dout)
{
    __shared__ __half sb[2][192 * HPAD];

    const int tid  = threadIdx.x;
    const int lane = tid & 31;
    const int wid  = tid >> 5;
    const int wm   = wid & 3;
    const int wn   = wid >> 2;
    const int m0   = blockIdx.y * 128;
    const int n0   = blockIdx.x * 64;
    const int lr   = lane >> 2;
    const int lc2  = (lane & 3) * 2;

    const int r0 = tid >> 2;
    const int c8 = (tid & 3) * 8;
    const size_t oA0 = (size_t)(m0 + r0)      * K + c8;
    const size_t oA1 = (size_t)(m0 + r0 + 64) * K + c8;
    const __half* gW = W + (size_t)(n0 + r0) * K + c8;
    const int s0 = r0 * HPAD + c8;
    const int s1 = (r0 + 64) * HPAD + c8;
    const int s2 = (r0 + 128) * HPAD + c8;

    const int nT = K >> 5;

    uint4 pa0 = *(const uint4*)(A + oA0);
    uint4 pa1 = *(const uint4*)(A + oA1);
    uint4 pw  = *(const uint4*)gW;

    float acc[2][4][4];
    #pragma unroll
    for (int i = 0; i < 2; i++)
        #pragma unroll
        for (int j = 0; j < 4; j++)
            #pragma unroll
            for (int e = 0; e < 4; e++) acc[i][j][e] = 0.f;

    *(uint4*)(sb[0] + s0) = pa0;
    *(uint4*)(sb[0] + s1) = pa1;
    *(uint4*)(sb[0] + s2) = pw;

    for (int t = 0; t < nT; ++t) {
        __syncthreads();

        if (t + 1 < nT) {
            const int off = (t + 1) * 32;
            pa0 = *(const uint4*)(A + oA0 + off);
            pa1 = *(const uint4*)(A + oA1 + off);
            pw  = *(const uint4*)(gW + off);
        }

        const __half* As = sb[t & 1];
        const __half* Ws = As + 128 * HPAD;

        #pragma unroll
        for (int ks = 0; ks < 32; ks += 16) {
            uint32_t af[2][4], bf[4][2];
            #pragma unroll
            for (int i = 0; i < 2; i++) {
                const int base = (wm * 32 + i * 16 + lr) * HPAD + ks + lc2;
                af[i][0] = *(const uint32_t*)(As + base);
                af[i][1] = *(const uint32_t*)(As + base + 8 * HPAD);
                af[i][2] = *(const uint32_t*)(As + base + 8);
                af[i][3] = *(const uint32_t*)(As + base + 8 * HPAD + 8);
            }
            #pragma unroll
            for (int j = 0; j < 4; j++) {
                const int base = (wn * 32 + j * 8 + lr) * HPAD + ks + lc2;
                bf[j][0] = *(const uint32_t*)(Ws + base);
                bf[j][1] = *(const uint32_t*)(Ws + base + 8);
            }
            #pragma unroll
            for (int i = 0; i < 2; i++)
                #pragma unroll
                for (int j = 0; j < 4; j++)
                    mma16816(acc[i][j], af[i], bf[j]);
        }

        if (t + 1 < nT) {
            __half* nb = sb[(t + 1) & 1];
            *(uint4*)(nb + s0) = pa0;
            *(uint4*)(nb + s1) = pa1;
            *(uint4*)(nb + s2) = pw;
        }
    }

    float2 bx[4];
    #pragma unroll
    for (int j = 0; j < 4; j++) {
        const int cj = n0 + wn * 32 + j * 8 + lc2;
        bx[j] = *(const float2*)(bias + cj);
    }
    #pragma unroll
    for (int i = 0; i < 2; i++) {
        const int r = m0 + wm * 32 + i * 16 + lr;
        #pragma unroll
        for (int j = 0; j < 4; j++) {
            const int cj = n0 + wn * 32 + j * 8 + lc2;
            float v0 = acc[i][j][0] + bx[j].x;
            float v1 = acc[i][j][1] + bx[j].y;
            float v2 = acc[i][j][2] + bx[j].x;
            float v3 = acc[i][j][3] + bx[j].y;
            if (RELU) {
                v0 = fmaxf(v0, 0.f); v1 = fmaxf(v1, 0.f);
                v2 = fmaxf(v2, 0.f); v3 = fmaxf(v3, 0.f);
            }
            if (OUTH) {
                *(__half2*)(Ch + (size_t)r       * Dout + cj) = __floats2half2_rn(v0, v1);
                *(__half2*)(Ch + (size_t)(r + 8) * Dout + cj) = __floats2half2_rn(v2, v3);
            } else {
                *(float2*)(C + (size_t)r       * Dout + cj) = make_float2(v0, v1);
                *(float2*)(C + (size_t)(r + 8) * Dout + cj) = make_float2(v2, v3);
            }
        }
    }
}

// ---------------- combined K/V projection (SIMT fp32), blockIdx.z selects ----------------
#define BM 128
#define BN 64
#define BK 16

__global__ __launch_bounds__(256, 2)
void gemm_kv(const float* __restrict__ boxf, const float* __restrict__ boxp,
             const float* __restrict__ Wk, const float* __restrict__ bk, float* __restrict__ Ck,
             const float* __restrict__ Wv, const float* __restrict__ bv, float* __restrict__ Cv)
{
    const bool isK = (blockIdx.z == 0);
    const float* A   = boxf;
    const float* A2  = isK ? boxp : nullptr;
    const float* W   = isK ? Wk : Wv;
    const float* bias= isK ? bk : bv;
    float* C         = isK ? Ck : Cv;
    const int K = BD_DIM, Dout = D_DIM;

    __shared__ float As[BK][BM + 4];
    __shared__ float Ws[BK][BN + 4];

    const int tid = threadIdx.x;
    const int tx = tid & 15;
    const int ty = tid >> 4;
    const int m0 = blockIdx.y * BM;
    const int n0 = blockIdx.x * BN;

    const int ar = tid >> 2;
    const int ac = (tid & 3) << 2;

    const float* Ap0 = A + (size_t)(m0 + ar)      * K + ac;
    const float* Ap1 = A + (size_t)(m0 + ar + 64) * K + ac;
    const float* Wp  = W + (size_t)(n0 + ar)      * K + ac;

    const int nT = K / BK;

    float4 pa0 = *(const float4*)(Ap0);
    float4 pa1 = *(const float4*)(Ap1);
    float4 pw  = *(const float4*)(Wp);
    if (isK) {
        const float* B0 = A2 + (size_t)(m0 + ar) * K + ac;
        const float* B1 = A2 + (size_t)(m0 + ar + 64) * K + ac;
        float4 q0 = *(const float4*)B0;
        float4 q1 = *(const float4*)B1;
        pa0.x += q0.x; pa0.y += q0.y; pa0.z += q0.z; pa0.w += q0.w;
        pa1.x += q1.x; pa1.y += q1.y; pa1.z += q1.z; pa1.w += q1.w;
    }

    float acc[8][4];
    #pragma unroll
    for (int i = 0; i < 8; i++)
        #pragma unroll
        for (int j = 0; j < 4; j++) acc[i][j] = 0.f;

    for (int t = 0; t < nT; ++t) {
        As[ac+0][ar]    = pa0.x; As[ac+1][ar]    = pa0.y;
        As[ac+2][ar]    = pa0.z; As[ac+3][ar]    = pa0.w;
        As[ac+0][ar+64] = pa1.x; As[ac+1][ar+64] = pa1.y;
        As[ac+2][ar+64] = pa1.z; As[ac+3][ar+64] = pa1.w;
        Ws[ac+0][ar]    = pw.x;  Ws[ac+1][ar]    = pw.y;
        Ws[ac+2][ar]    = pw.z;  Ws[ac+3][ar]    = pw.w;
        __syncthreads();

        if (t + 1 < nT) {
            const int off = (t + 1) * BK;
            pa0 = *(const float4*)(Ap0 + off);
            pa1 = *(const float4*)(Ap1 + off);
            pw  = *(const float4*)(Wp  + off);
            if (isK) {
                const float* B0 = A2 + (size_t)(m0 + ar) * K + ac + off;
                const float* B1 = A2 + (size_t)(m0 + ar + 64) * K + ac + off;
                float4 q0 = *(const float4*)B0;
                float4 q1 = *(const float4*)B1;
                pa0.x += q0.x; pa0.y += q0.y; pa0.z += q0.z; pa0.w += q0.w;
                pa1.x += q1.x; pa1.y += q1.y; pa1.z += q1.z; pa1.w += q1.w;
            }
        }

        #pragma unroll
        for (int k = 0; k < BK; ++k) {
            float a[8], w[4];
            #pragma unroll
            for (int i = 0; i < 8; i++) a[i] = As[k][ty * 8 + i];
            #pragma unroll
            for (int j = 0; j < 4; j++) w[j] = Ws[k][tx * 4 + j];
            #pragma unroll
            for (int i = 0; i < 8; i++)
                #pragma unroll
                for (int j = 0; j < 4; j++) acc[i][j] += a[i] * w[j];
        }
        __syncthreads();
    }

    const float b0 = bias[n0 + tx*4 + 0];
    const float b1 = bias[n0 + tx*4 + 1];
    const float b2 = bias[n0 + tx*4 + 2];
    const float b3 = bias[n0 + tx*4 + 3];
    #pragma unroll
    for (int i = 0; i < 8; i++) {
        float4 o;
        o.x = acc[i][0] + b0; o.y = acc[i][1] + b1;
        o.z = acc[i][2] + b2; o.w = acc[i][3] + b3;
        *(float4*)(C + (size_t)(m0 + ty*8 + i) * Dout + n0 + tx*4) = o;
    }
}

// ---------------- K/V pack: fp32 -> fp16, K padded [h][m][32], V transposed [h][d][m] ----------------
__global__ void kv_pack(const float* __restrict__ kb, const float* __restrict__ vb,
                        __half* __restrict__ khg, __half* __restrict__ vtg)
{
    const int i = blockIdx.x * 256 + threadIdx.x;
    if (i >= H_HEADS * M_BOX) return;
    const int h = i >> 8, m = i & 255;

    {
        const float4* kp = (const float4*)(kb + (size_t)m * D_DIM + h * HD_DIM);
        __half2 hrow[16];
        #pragma unroll
        for (int j = 0; j < 6; j++) {
            float4 f = kp[j];
            hrow[2*j]   = __floats2half2_rn(f.x, f.y);
            hrow[2*j+1] = __floats2half2_rn(f.z, f.w);
        }
        const __half2 zz = __floats2half2_rn(0.f, 0.f);
        hrow[12] = zz; hrow[13] = zz; hrow[14] = zz; hrow[15] = zz;
        uint4* dst = (uint4*)(khg + ((size_t)h * M_BOX + m) * 32);
        dst[0] = ((const uint4*)hrow)[0];
        dst[1] = ((const uint4*)hrow)[1];
        dst[2] = ((const uint4*)hrow)[2];
        dst[3] = ((const uint4*)hrow)[3];
    }
    {
        const float4* vp = (const float4*)(vb + (size_t)m * D_DIM + h * HD_DIM);
        __half* base = vtg + (size_t)h * HD_DIM * M_BOX + m;
        #pragma unroll
        for (int j = 0; j < 6; j++) {
            float4 g = vp[j];
            base[(4*j+0) * M_BOX] = __float2half(g.x);
            base[(4*j+1) * M_BOX] = __float2half(g.y);
            base[(4*j+2) * M_BOX] = __float2half(g.z);
            base[(4*j+3) * M_BOX] = __float2half(g.w);
        }
    }
}

// ================= tensor-core attention: one CTA per (set, head) =================
#define AT_QS   0
#define AT_KS   1920
#define AT_VT   12160
#define AT_PS   18496
#define AT_INT  31168
#define ATTN_SMEM (31168 * 2 + (36 + 256) * 4)

__global__ __launch_bounds__(256)
void attn_mma(const __half* __restrict__ qh, const __half* __restrict__ khg,
              const __half* __restrict__ vtg, const int* __restrict__ vinds,
              const int* __restrict__ vcoords, const int* __restrict__ bcoords,
              __half* __restrict__ ctxh)
{
    extern __shared__ __half sm[];
    __half* Qs = sm + AT_QS;
    __half* Ks = sm + AT_KS;
    __half* Vt = sm + AT_VT;
    __half* Ps = sm + AT_PS;
    int* qb = (int*)(sm + AT_INT);
    int* bb = qb + 36;

    const int s = blockIdx.x, h = blockIdx.y;
    const int t = threadIdx.x, lane = t & 31, wid = t >> 5;
    const int lr = lane >> 2, lc2 = (lane & 3) * 2;

    {
        const uint4* kp = (const uint4*)(khg + ((size_t)h * M_BOX + t) * 32);
        uint4* krow = (uint4*)(Ks + t * 40);
        krow[0] = kp[0];
        krow[1] = kp[1];
        krow[2] = kp[2];
        krow[3] = kp[3];
        bb[t] = bcoords[t * 4];
    }
    {
        const __half* vsrc = vtg + (size_t)h * HD_DIM * M_BOX;
        #pragma unroll
        for (int j = 0; j < 3; j++) {
            const int idx = t + 256 * j;
            const int r = idx >> 5, c = idx & 31;
            *(uint4*)(Vt + r * 264 + c * 8) = *(const uint4*)(vsrc + r * M_BOX + c * 8);
        }
    }
    // ---- Q gather: half rows, 4 uint4 per row (cols 24..31 zeroed) ----
    {
        const uint4 z4 = make_uint4(0u, 0u, 0u, 0u);
        for (int i = t; i < 36 * 4; i += 256) {
            const int l = i >> 2, c = i & 3;   // c = uint4 index within row (8 halves each)
            uint4 v;
            if (c < 3) v = *(const uint4*)(qh + (size_t)vinds[s * L_LEN + l] * D_DIM + h * HD_DIM + c * 8);
            else       v = z4;
            *(uint4*)(Qs + l * 40 + c * 8) = v;
        }
    }
    if (t < 36) qb[t] = vcoords[(size_t)vinds[s * L_LEN + t] * 4];
    __syncthreads();

    // ---- scores: S = Q @ K^T ----
    float acc[3][4][4];
    #pragma unroll
    for (int i = 0; i < 3; i++)
        #pragma unroll
        for (int j = 0; j < 4; j++)
            #pragma unroll
            for (int e = 0; e < 4; e++) acc[i][j][e] = 0.f;

    #pragma unroll
    for (int kk = 0; kk < 2; kk++) {
        const int k0 = kk * 16;
        uint32_t af[3][4], bf[4][2];
        #pragma unroll
        for (int i = 0; i < 3; i++) {
            const __half* p = Qs + (i * 16 + lr) * 40 + k0 + lc2;
            af[i][0] = *(const uint32_t*)(p);
            af[i][1] = *(const uint32_t*)(p + 8 * 40);
            af[i][2] = *(const uint32_t*)(p + 8);
            af[i][3] = *(const uint32_t*)(p + 8 * 40 + 8);
        }
        #pragma unroll
        for (int j = 0; j < 4; j++) {
            const __half* p = Ks + (wid * 32 + j * 8 + lr) * 40 + k0 + lc2;
            bf[j][0] = *(const uint32_t*)(p);
            bf[j][1] = *(const uint32_t*)(p + 8);
        }
        #pragma unroll
        for (int i = 0; i < 3; i++)
            #pragma unroll
            for (int j = 0; j < 4; j++)
                mma16816(acc[i][j], af[i], bf[j]);
    }

    {
        const float scale = 0.20412414523193154f;
        #pragma unroll
        for (int i = 0; i < 3; i++) {
            const int r0 = i * 16 + lr, r1 = r0 + 8;
            const int q0 = (r0 < L_LEN) ? qb[r0] : 0;
            const int q1 = (r1 < L_LEN) ? qb[r1] : 0;
            #pragma unroll
            for (int j = 0; j < 4; j++) {
                const int c = wid * 32 + j * 8 + lc2;
                const int b0 = bb[c], b1 = bb[c + 1];
                if (r0 < L_LEN) {
                    float v0 = (q0 != b0) ? -CUDART_INF_F : acc[i][j][0] * scale;
                    float v1 = (q0 != b1) ? -CUDART_INF_F : acc[i][j][1] * scale;
                    *(__half2*)(Ps + r0 * 264 + c) = __floats2half2_rn(v0, v1);
                }
                if (r1 < L_LEN) {
                    float v2 = (q1 != b0) ? -CUDART_INF_F : acc[i][j][2] * scale;
                    float v3 = (q1 != b1) ? -CUDART_INF_F : acc[i][j][3] * scale;
                    *(__half2*)(Ps + r1 * 264 + c) = __floats2half2_rn(v2, v3);
                }
            }
        }
    }
    __syncthreads();

    // ---- softmax (fp32 math, half storage), warp per row, in place ----
    for (int l = wid; l < L_LEN; l += 8) {
        __half* row = Ps + l * 264;
        float e[8];
        float mx = -CUDART_INF_F;
        #pragma unroll
        for (int i = 0; i < 8; i++) { e[i] = __half2float(row[lane + 32*i]); mx = fmaxf(mx, e[i]); }
        #pragma unroll
        for (int o = 16; o > 0; o >>= 1) mx = fmaxf(mx, __shfl_xor_sync(0xffffffffu, mx, o));
        float sum = 0.f;
        if (mx > -CUDART_INF_F) {
            #pragma unroll
            for (int i = 0; i < 8; i++) { e[i] = __expf(e[i] - mx); sum += e[i]; }
        } else {
            #pragma unroll
            for (int i = 0; i < 8; i++) e[i] = 0.f;
        }
        #pragma unroll
        for (int o = 16; o > 0; o >>= 1) sum += __shfl_xor_sync(0xffffffffu, sum, o);
        const float inv = sum > 0.f ? 1.0f / sum : 0.f;
        #pragma unroll
        for (int i = 0; i < 8; i++) row[lane + 32*i] = __float2half(e[i] * inv);
    }
    __syncthreads();

    // ---- ctx = P @ V : warp mt (0..2) iterates nt inside; af loaded once per kt ----
    if (wid < 3) {
        const int mt = wid;
        float a2[3][4];
        #pragma unroll
        for (int n = 0; n < 3; n++)
            #pragma unroll
            for (int e = 0; e < 4; e++) a2[n][e] = 0.f;

        #pragma unroll 4
        for (int kt = 0; kt < 16; kt++) {
            uint32_t af[4];
            const __half* pa = Ps + (mt * 16 + lr) * 264 + kt * 16 + lc2;
            af[0] = *(const uint32_t*)(pa);
            af[1] = *(const uint32_t*)(pa + 8 * 264);
            af[2] = *(const uint32_t*)(pa + 8);
            af[3] = *(const uint32_t*)(pa + 8 * 264 + 8);
            #pragma unroll
            for (int nt = 0; nt < 3; nt++) {
                uint32_t bf[2];
                const __half* pb = Vt + (nt * 8 + lr) * 264 + kt * 16 + lc2;
                bf[0] = *(const uint32_t*)(pb);
                bf[1] = *(const uint32_t*)(pb + 8);
                mma16816(a2[nt], af, bf);
            }
        }

        const int r0 = mt * 16 + lr, r1 = r0 + 8;
        #pragma unroll
        for (int nt = 0; nt < 3; nt++) {
            const int c = nt * 8 + lc2;
            if (r0 < L_LEN)
                *(__half2*)(ctxh + ((size_t)s * L_LEN + r0) * D_DIM + h * HD_DIM + c) = __floats2half2_rn(a2[nt][0], a2[nt][1]);
            if (r1 < L_LEN)
                *(__half2*)(ctxh + ((size_t)s * L_LEN + r1) * D_DIM + h * HD_DIM + c) = __floats2half2_rn(a2[nt][2], a2[nt][3]);
        }
    }
}

// ---------------- first-occurrence scatter index ----------------
__global__ void init_fp_kernel(int* __restrict__ fp)
{
    int i = blockIdx.x * blockDim.x + threadIdx.x;
    if (i < N_PTS) fp[i] = 0x7FFFFFFF;
}

__global__ void fill_fp_kernel(const int* __restrict__ vinds, int* __restrict__ fp)
{
    int p = blockIdx.x * blockDim.x + threadIdx.x;
    if (p < S_SETS * L_LEN) {
        int n = vinds[p];
        if (n >= 0 && n < N_PTS) atomicMin(&fp[n], p);
    }
}

// ---------------- residual + layernorm (warp per row) ----------------
template<bool GATHER, bool OUTH>
__global__ __launch_bounds__(256)
void ln_kernel(const float* __restrict__ a, const float* __restrict__ b,
               const int* __restrict__ fp, const float* __restrict__ gamma,
               const float* __restrict__ beta, float* __restrict__ outp,
               __half* __restrict__ oh)
{
    const int row  = (blockIdx.x * 256 + threadIdx.x) >> 5;
    const int lane = threadIdx.x & 31;
    if (row >= N_PTS) return;

    const float* arow = a + (size_t)row * D_DIM;
    const float* brow;
    if (GATHER) {
        int p = fp[row];
        if (p < 0 || p >= N_PTS) p = row;
        brow = b + (size_t)p * D_DIM;
    } else {
        brow = b + (size_t)row * D_DIM;
    }

    float v[6];
    float s = 0.f;
    #pragma unroll
    for (int i = 0; i < 6; i++) {
        const int idx = lane + 32 * i;
        v[i] = arow[idx] + brow[idx];
        s += v[i];
    }
    #pragma unroll
    for (int o = 16; o > 0; o >>= 1) s += __shfl_xor_sync(0xffffffffu, s, o);
    const float mean = s * (1.0f / D_DIM);

    float q = 0.f;
    #pragma unroll
    for (int i = 0; i < 6; i++) { const float d = v[i] - mean; q += d * d; }
    #pragma unroll
    for (int o = 16; o > 0; o >>= 1) q += __shfl_xor_sync(0xffffffffu, q, o);
    const float inv = rsqrtf(q * (1.0f / D_DIM) + 1e-5f);

    float* orow = outp + (size_t)row * D_DIM;
    #pragma unroll
    for (int i = 0; i < 6; i++) {
        const int idx = lane + 32 * i;
        const float val = (v[i] - mean) * inv * gamma[idx] + beta[idx];
        orow[idx] = val;
        if (OUTH) oh[(size_t)row * D_DIM + idx] = __float2half(val);
    }
}

// ---------------- weight conversion (all four in one launch) ----------------
__global__ void cvt_weights_kernel(const float* __restrict__ Wq, const float* __restrict__ Wo,
                                   const float* __restrict__ W1, const float* __restrict__ W2,
                                   __half* __restrict__ wh)
{
    const int i = blockIdx.x * blockDim.x + threadIdx.x;
    const int n4 = 368640 / 4;
    if (i >= n4) return;
    const int e = i * 4;
    const float* srcp;
    int off;
    if (e < WOFF_O)      { srcp = Wq; off = e - WOFF_Q; }
    else if (e < WOFF_1) { srcp = Wo; off = e - WOFF_O; }
    else if (e < WOFF_2) { srcp = W1; off = e - WOFF_1; }
    else                 { srcp = W2; off = e - WOFF_2; }
    float4 x = *(const float4*)(srcp + off);
    ((__half2*)wh)[2*i]   = __floats2half2_rn(x.x, x.y);
    ((__half2*)wh)[2*i+1] = __floats2half2_rn(x.z, x.w);
}

// ---------------- launch ----------------
extern "C" void kernel_launch(void* const* d_in, const int* in_sizes, int n_in,
                              void* d_out, int out_size)
{
    const float* src     = (const float*)d_in[0];
    const float* pos     = (const float*)d_in[1];
    const float* boxf    = (const float*)d_in[2];
    const float* boxp    = (const float*)d_in[3];
    const int*   vcoords = (const int*)  d_in[4];
    const int*   bcoords = (const int*)  d_in[5];
    const int*   vinds   = (const int*)  d_in[6];
    const float* Wq = (const float*)d_in[7];  const float* bq  = (const float*)d_in[8];
    const float* Wk = (const float*)d_in[9];  const float* bk  = (const float*)d_in[10];
    const float* Wv = (const float*)d_in[11]; const float* bv  = (const float*)d_in[12];
    const float* Wo = (const float*)d_in[13]; const float* bo  = (const float*)d_in[14];
    const float* W1 = (const float*)d_in[15]; const float* b1  = (const float*)d_in[16];
    const float* W2 = (const float*)d_in[17]; const float* b2  = (const float*)d_in[18];
    const float* g1 = (const float*)d_in[19]; const float* be1 = (const float*)d_in[20];
    const float* g2 = (const float*)d_in[21]; const float* be2 = (const float*)d_in[22];
    float* out = (float*)d_out;

    float *projb, *xb, *yb, *kb, *vb;
    int* fpb;
    __half *qh, *ctxh, *xh, *hh, *wh, *khg, *vtg;
    cudaGetSymbolAddress((void**)&projb, g_proj);
    cudaGetSymbolAddress((void**)&xb,    g_x);
    cudaGetSymbolAddress((void**)&yb,    g_y);
    cudaGetSymbolAddress((void**)&kb,    g_k);
    cudaGetSymbolAddress((void**)&vb,    g_v);
    cudaGetSymbolAddress((void**)&fpb,   g_fp);
    cudaGetSymbolAddress((void**)&qh,    g_qh);
    cudaGetSymbolAddress((void**)&ctxh,  g_ctxh);
    cudaGetSymbolAddress((void**)&xh,    g_xh);
    cudaGetSymbolAddress((void**)&hh,    g_hh);
    cudaGetSymbolAddress((void**)&wh,    g_wh);
    cudaGetSymbolAddress((void**)&khg,   g_kh);
    cudaGetSymbolAddress((void**)&vtg,   g_vt);

    cudaFuncSetAttribute(attn_mma, cudaFuncAttributeMaxDynamicSharedMemorySize, ATTN_SMEM);
    cudaFuncSetAttribute(hgemm_ares<false, true,  true,  3>,  cudaFuncAttributeMaxDynamicSharedMemorySize, ARES_SMEM);
    cudaFuncSetAttribute(hgemm_ares<false, false, false, 3>,  cudaFuncAttributeMaxDynamicSharedMemorySize, ARES_SMEM);
    cudaFuncSetAttribute(hgemm_ares<true,  true,  false, 12>, cudaFuncAttributeMaxDynamicSharedMemorySize, ARES_SMEM);

    const int MB = N_PTS / 128;   // 720

    // 1: weight conversion
    cvt_weights_kernel<<<(368640/4 + 255)/256, 256>>>(Wq, Wo, W1, W2, wh);
    // 2: K/V projections
    gemm_kv<<<dim3(D_DIM/BN, M_BOX/BM, 2), 256>>>(boxf, boxp, Wk, bk, kb, Wv, bv, vb);
    // 3: pack K/V into attention-ready fp16 layouts
    kv_pack<<<(H_HEADS * M_BOX) / 256, 256>>>(kb, vb, khg, vtg);
    // 4: Q = (src + pos) @ Wq^T + bq  (A-resident, fused add+cvt, HALF output)
    hgemm_ares<false, true, true, 3><<<MB, 256, ARES_SMEM>>>(nullptr, src, pos, wh + WOFF_Q, bq, nullptr, qh, D_DIM);
    // 5: tensor-core masked attention (Q in half)
    attn_mma<<<dim3(S_SETS, H_HEADS), 256, ATTN_SMEM>>>(qh, khg, vtg, vinds, vcoords, bcoords, ctxh);
    // 6: O projection (A-resident)
    hgemm_ares<false, false, false, 3><<<MB, 256, ARES_SMEM>>>(ctxh, nullptr, nullptr, wh + WOFF_O, bo, projb, nullptr, D_DIM);
    // 7,8: first-occurrence scatter index
    init_fp_kernel<<<N_PTS / 256, 256>>>(fpb);
    fill_fp_kernel<<<(S_SETS * L_LEN) / 256, 256>>>(vinds, fpb);
    // 9: x = LN(src + proj[first_pos]) (+ half copy)
    ln_kernel<true, true><<<N_PTS / 8, 256>>>(src, projb, fpb, g1, be1, xb, xh);
    // 10: FFN1 (A-resident, relu, half out)
    hgemm_ares<true, true, false, 12><<<MB, 256, ARES_SMEM>>>(xh, nullptr, nullptr, wh + WOFF_1, b1, nullptr, hh, FF_DIM);
    // 11: FFN2 (K=768, streaming kernel)
    hgemm<false, false><<<dim3(D_DIM/64, MB), 256>>>(hh, wh + WOFF_2, b2, yb, nullptr, FF_DIM, D_DIM);
    // 12: out = LN(x + ffn)
    ln_kernel<false, false><<<N_PTS / 8, 256>>>(xb, yb, nullptr, g2, be2, out, nullptr);
}

// round 13
// speedup vs baseline: 3.5055x; 1.0439x over previous
#include <cuda_runtime.h>
#include <cuda_fp16.h>
#include <math_constants.h>
#include <cstdint>

#define N_PTS   92160
#define D_DIM   192
#define BD_DIM  256
#define H_HEADS 8
#define FF_DIM  768
#define S_SETS  2560
#define L_LEN   36
#define M_BOX   256
#define HD_DIM  24
#define SPC     4          // sets per attention CTA

// ---------------- scratch (static device globals; no allocation) ----------------
__device__ float g_proj[N_PTS * D_DIM];
__device__ float g_x[N_PTS * D_DIM];
__device__ float g_y[N_PTS * D_DIM];
__device__ float g_k[M_BOX * D_DIM];
__device__ float g_v[M_BOX * D_DIM];
__device__ int   g_fp[N_PTS];

__device__ __half g_qh[N_PTS * D_DIM];
__device__ __half g_ctxh[N_PTS * D_DIM];
__device__ __half g_xh[N_PTS * D_DIM];
__device__ __half g_hh[(size_t)N_PTS * FF_DIM];
__device__ __half g_kh[H_HEADS * M_BOX * 32];      // [h][m][32] padded fp16 K
__device__ __half g_vt[H_HEADS * HD_DIM * M_BOX];  // [h][d][m]  transposed fp16 V
#define WOFF_Q 0
#define WOFF_O 36864
#define WOFF_1 73728
#define WOFF_2 221184
__device__ __half g_wh[368640];

__device__ __forceinline__ void mma16816(float* d, const uint32_t* a, const uint32_t* b) {
    asm volatile(
        "mma.sync.aligned.m16n8k16.row.col.f32.f16.f16.f32 "
        "{%0,%1,%2,%3}, {%4,%5,%6,%7}, {%8,%9}, {%0,%1,%2,%3};\n"
        : "+f"(d[0]), "+f"(d[1]), "+f"(d[2]), "+f"(d[3])
        : "r"(a[0]), "r"(a[1]), "r"(a[2]), "r"(a[3]), "r"(b[0]), "r"(b[1]));
}

__device__ __forceinline__ uint4 add_cvt8(const float* p, const float* q) {
    float4 x0 = *(const float4*)p;
    float4 x1 = *(const float4*)(p + 4);
    float4 y0 = *(const float4*)q;
    float4 y1 = *(const float4*)(q + 4);
    __half2 h0 = __floats2half2_rn(x0.x + y0.x, x0.y + y0.y);
    __half2 h1 = __floats2half2_rn(x0.z + y0.z, x0.w + y0.w);
    __half2 h2 = __floats2half2_rn(x1.x + y1.x, x1.y + y1.y);
    __half2 h3 = __floats2half2_rn(x1.z + y1.z, x1.w + y1.w);
    uint4 r;
    r.x = *(uint32_t*)&h0; r.y = *(uint32_t*)&h1;
    r.z = *(uint32_t*)&h2; r.w = *(uint32_t*)&h3;
    return r;
}

// ================= A-resident fp16 GEMM for K=192: C = A @ W^T + bias =================
#define ARES_SMEM ((128 * 200 + 2 * 64 * 40) * 2)

template<bool RELU, bool OUTH, bool ADDIN, int NTILES>
__global__ __launch_bounds__(256)
void hgemm_ares(const __half* __restrict__ A, const float* __restrict__ Af,
                const float* __restrict__ Af2, const __half* __restrict__ W,
                const float* __restrict__ bias, float* __restrict__ C,
                __half* __restrict__ Ch, int Dout)
{
    extern __shared__ __half dsm[];
    __half* As = dsm;                 // 128 x 200
    __half* Wb0 = dsm + 25600;        // 64 x 40
    __half* Wb1 = dsm + 28160;

    const int tid  = threadIdx.x;
    const int lane = tid & 31;
    const int wid  = tid >> 5;
    const int wm   = wid & 3;
    const int wn   = wid >> 2;
    const int m0   = blockIdx.x * 128;
    const int lr   = lane >> 2;
    const int lc2  = (lane & 3) * 2;

    #pragma unroll
    for (int j = 0; j < 12; j++) {
        const int idx = tid + 256 * j;
        const int r = idx / 24, c8 = (idx % 24) * 8;
        const size_t go = (size_t)(m0 + r) * 192 + c8;
        uint4 v;
        if (ADDIN) v = add_cvt8(Af + go, Af2 + go);
        else       v = *(const uint4*)(A + go);
        *(uint4*)(As + r * 200 + c8) = v;
    }

    const int rw = tid >> 2;
    const int cw = (tid & 3) * 8;
    const int sW = rw * 40 + cw;

    const int NI = NTILES * 6;
    uint4 pw = *(const uint4*)(W + (size_t)rw * 192 + cw);
    *(uint4*)(Wb0 + sW) = pw;

    float acc[2][4][4];

    for (int i = 0; i < NI; ++i) {
        const int nt = i / 6, kc = i % 6;
        __syncthreads();

        if (kc == 0) {
            #pragma unroll
            for (int a = 0; a < 2; a++)
                #pragma unroll
                for (int b = 0; b < 4; b++)
                    #pragma unroll
                    for (int e = 0; e < 4; e++) acc[a][b][e] = 0.f;
        }

        if (i + 1 < NI) {
            const int nt2 = (i + 1) / 6, kc2 = (i + 1) % 6;
            pw = *(const uint4*)(W + (size_t)(nt2 * 64 + rw) * 192 + kc2 * 32 + cw);
        }

        const __half* Ws = (i & 1) ? Wb1 : Wb0;
        const int ca = kc * 32;

        #pragma unroll
        for (int ks = 0; ks < 32; ks += 16) {
            uint32_t af[2][4], bf[4][2];
            #pragma unroll
            for (int a = 0; a < 2; a++) {
                const __half* p = As + (wm * 32 + a * 16 + lr) * 200 + ca + ks + lc2;
                af[a][0] = *(const uint32_t*)(p);
                af[a][1] = *(const uint32_t*)(p + 8 * 200);
                af[a][2] = *(const uint32_t*)(p + 8);
                af[a][3] = *(const uint32_t*)(p + 8 * 200 + 8);
            }
            #pragma unroll
            for (int b = 0; b < 4; b++) {
                const __half* p = Ws + (wn * 32 + b * 8 + lr) * 40 + ks + lc2;
                bf[b][0] = *(const uint32_t*)(p);
                bf[b][1] = *(const uint32_t*)(p + 8);
            }
            #pragma unroll
            for (int a = 0; a < 2; a++)
                #pragma unroll
                for (int b = 0; b < 4; b++)
                    mma16816(acc[a][b], af[a], bf[b]);
        }

        if (kc == 5) {
            const int n0 = nt * 64;
            #pragma unroll
            for (int a = 0; a < 2; a++) {
                const int r = m0 + wm * 32 + a * 16 + lr;
                #pragma unroll
                for (int b = 0; b < 4; b++) {
                    const int cj = n0 + wn * 32 + b * 8 + lc2;
                    const float2 bx = *(const float2*)(bias + cj);
                    float v0 = acc[a][b][0] + bx.x;
                    float v1 = acc[a][b][1] + bx.y;
                    float v2 = acc[a][b][2] + bx.x;
                    float v3 = acc[a][b][3] + bx.y;
                    if (RELU) {
                        v0 = fmaxf(v0, 0.f); v1 = fmaxf(v1, 0.f);
                        v2 = fmaxf(v2, 0.f); v3 = fmaxf(v3, 0.f);
                    }
                    if (OUTH) {
                        *(__half2*)(Ch + (size_t)r       * Dout + cj) = __floats2half2_rn(v0, v1);
                        *(__half2*)(Ch + (size_t)(r + 8) * Dout + cj) = __floats2half2_rn(v2, v3);
                    } else {
                        *(float2*)(C + (size_t)r       * Dout + cj) = make_float2(v0, v1);
                        *(float2*)(C + (size_t)(r + 8) * Dout + cj) = make_float2(v2, v3);
                    }
                }
            }
        }

        if (i + 1 < NI) {
            __half* nb = ((i + 1) & 1) ? Wb1 : Wb0;
            *(uint4*)(nb + sW) = pw;
        }
    }
}

// ================= fp16 mma.sync GEMM (generic K): used for FFN2 =================
#define HPAD 40

template<bool RELU, bool OUTH>
__global__ __launch_bounds__(256)
void hgemm(const __half* __restrict__ A, const __half* __restrict__ W,
           const float* __restrict__ bias, float* __restrict__ C,
           __half* __restrict__ Ch, int K, int Dout)
{
    __shared__ __half sb[2][192 * HPAD];

    const int tid  = threadIdx.x;
    const int lane = tid & 31;
    const int wid  = tid >> 5;
    const int wm   = wid & 3;
    const int wn   = wid >> 2;
    const int m0   = blockIdx.y * 128;
    const int n0   = blockIdx.x * 64;
    const int lr   = lane >> 2;
    const int lc2  = (lane & 3) * 2;

    const int r0 = tid >> 2;
    const int c8 = (tid & 3) * 8;
    const size_t oA0 = (size_t)(m0 + r0)      * K + c8;
    const size_t oA1 = (size_t)(m0 + r0 + 64) * K + c8;
    const __half* gW = W + (size_t)(n0 + r0) * K + c8;
    const int s0 = r0 * HPAD + c8;
    const int s1 = (r0 + 64) * HPAD + c8;
    const int s2 = (r0 + 128) * HPAD + c8;

    const int nT = K >> 5;

    uint4 pa0 = *(const uint4*)(A + oA0);
    uint4 pa1 = *(const uint4*)(A + oA1);
    uint4 pw  = *(const uint4*)gW;

    float acc[2][4][4];
    #pragma unroll
    for (int i = 0; i < 2; i++)
        #pragma unroll
        for (int j = 0; j < 4; j++)
            #pragma unroll
            for (int e = 0; e < 4; e++) acc[i][j][e] = 0.f;

    *(uint4*)(sb[0] + s0) = pa0;
    *(uint4*)(sb[0] + s1) = pa1;
    *(uint4*)(sb[0] + s2) = pw;

    for (int t = 0; t < nT; ++t) {
        __syncthreads();

        if (t + 1 < nT) {
            const int off = (t + 1) * 32;
            pa0 = *(const uint4*)(A + oA0 + off);
            pa1 = *(const uint4*)(A + oA1 + off);
            pw  = *(const uint4*)(gW + off);
        }

        const __half* As = sb[t & 1];
        const __half* Ws = As + 128 * HPAD;

        #pragma unroll
        for (int ks = 0; ks < 32; ks += 16) {
            uint32_t af[2][4], bf[4][2];
            #pragma unroll
            for (int i = 0; i < 2; i++) {
                const int base = (wm * 32 + i * 16 + lr) * HPAD + ks + lc2;
                af[i][0] = *(const uint32_t*)(As + base);
                af[i][1] = *(const uint32_t*)(As + base + 8 * HPAD);
                af[i][2] = *(const uint32_t*)(As + base + 8);
                af[i][3] = *(const uint32_t*)(As + base + 8 * HPAD + 8);
            }
            #pragma unroll
            for (int j = 0; j < 4; j++) {
                const int base = (wn * 32 + j * 8 + lr) * HPAD + ks + lc2;
                bf[j][0] = *(const uint32_t*)(Ws + base);
                bf[j][1] = *(const uint32_t*)(Ws + base + 8);
            }
            #pragma unroll
            for (int i = 0; i < 2; i++)
                #pragma unroll
                for (int j = 0; j < 4; j++)
                    mma16816(acc[i][j], af[i], bf[j]);
        }

        if (t + 1 < nT) {
            __half* nb = sb[(t + 1) & 1];
            *(uint4*)(nb + s0) = pa0;
            *(uint4*)(nb + s1) = pa1;
            *(uint4*)(nb + s2) = pw;
        }
    }

    float2 bx[4];
    #pragma unroll
    for (int j = 0; j < 4; j++) {
        const int cj = n0 + wn * 32 + j * 8 + lc2;
        bx[j] = *(const float2*)(bias + cj);
    }
    #pragma unroll
    for (int i = 0; i < 2; i++) {
        const int r = m0 + wm * 32 + i * 16 + lr;
        #pragma unroll
        for (int j = 0; j < 4; j++) {
            const int cj = n0 + wn * 32 + j * 8 + lc2;
            float v0 = acc[i][j][0] + bx[j].x;
            float v1 = acc[i][j][1] + bx[j].y;
            float v2 = acc[i][j][2] + bx[j].x;
            float v3 = acc[i][j][3] + bx[j].y;
            if (RELU) {
                v0 = fmaxf(v0, 0.f); v1 = fmaxf(v1, 0.f);
                v2 = fmaxf(v2, 0.f); v3 = fmaxf(v3, 0.f);
            }
            if (OUTH) {
                *(__half2*)(Ch + (size_t)r       * Dout + cj) = __floats2half2_rn(v0, v1);
                *(__half2*)(Ch + (size_t)(r + 8) * Dout + cj) = __floats2half2_rn(v2, v3);
            } else {
                *(float2*)(C + (size_t)r       * Dout + cj) = make_float2(v0, v1);
                *(float2*)(C + (size_t)(r + 8) * Dout + cj) = make_float2(v2, v3);
            }
        }
    }
}

// ---------------- combined K/V projection (SIMT fp32), blockIdx.z selects ----------------
#define BM 128
#define BN 64
#define BK 16

__global__ __launch_bounds__(256, 2)
void gemm_kv(const float* __restrict__ boxf, const float* __restrict__ boxp,
             const float* __restrict__ Wk, const float* __restrict__ bk, float* __restrict__ Ck,
             const float* __restrict__ Wv, const float* __restrict__ bv, float* __restrict__ Cv)
{
    const bool isK = (blockIdx.z == 0);
    const float* A   = boxf;
    const float* A2  = isK ? boxp : nullptr;
    const float* W   = isK ? Wk : Wv;
    const float* bias= isK ? bk : bv;
    float* C         = isK ? Ck : Cv;
    const int K = BD_DIM, Dout = D_DIM;

    __shared__ float As[BK][BM + 4];
    __shared__ float Ws[BK][BN + 4];

    const int tid = threadIdx.x;
    const int tx = tid & 15;
    const int ty = tid >> 4;
    const int m0 = blockIdx.y * BM;
    const int n0 = blockIdx.x * BN;

    const int ar = tid >> 2;
    const int ac = (tid & 3) << 2;

    const float* Ap0 = A + (size_t)(m0 + ar)      * K + ac;
    const float* Ap1 = A + (size_t)(m0 + ar + 64) * K + ac;
    const float* Wp  = W + (size_t)(n0 + ar)      * K + ac;

    const int nT = K / BK;

    float4 pa0 = *(const float4*)(Ap0);
    float4 pa1 = *(const float4*)(Ap1);
    float4 pw  = *(const float4*)(Wp);
    if (isK) {
        const float* B0 = A2 + (size_t)(m0 + ar) * K + ac;
        const float* B1 = A2 + (size_t)(m0 + ar + 64) * K + ac;
        float4 q0 = *(const float4*)B0;
        float4 q1 = *(const float4*)B1;
        pa0.x += q0.x; pa0.y += q0.y; pa0.z += q0.z; pa0.w += q0.w;
        pa1.x += q1.x; pa1.y += q1.y; pa1.z += q1.z; pa1.w += q1.w;
    }

    float acc[8][4];
    #pragma unroll
    for (int i = 0; i < 8; i++)
        #pragma unroll
        for (int j = 0; j < 4; j++) acc[i][j] = 0.f;

    for (int t = 0; t < nT; ++t) {
        As[ac+0][ar]    = pa0.x; As[ac+1][ar]    = pa0.y;
        As[ac+2][ar]    = pa0.z; As[ac+3][ar]    = pa0.w;
        As[ac+0][ar+64] = pa1.x; As[ac+1][ar+64] = pa1.y;
        As[ac+2][ar+64] = pa1.z; As[ac+3][ar+64] = pa1.w;
        Ws[ac+0][ar]    = pw.x;  Ws[ac+1][ar]    = pw.y;
        Ws[ac+2][ar]    = pw.z;  Ws[ac+3][ar]    = pw.w;
        __syncthreads();

        if (t + 1 < nT) {
            const int off = (t + 1) * BK;
            pa0 = *(const float4*)(Ap0 + off);
            pa1 = *(const float4*)(Ap1 + off);
            pw  = *(const float4*)(Wp  + off);
            if (isK) {
                const float* B0 = A2 + (size_t)(m0 + ar) * K + ac + off;
                const float* B1 = A2 + (size_t)(m0 + ar + 64) * K + ac + off;
                float4 q0 = *(const float4*)B0;
                float4 q1 = *(const float4*)B1;
                pa0.x += q0.x; pa0.y += q0.y; pa0.z += q0.z; pa0.w += q0.w;
                pa1.x += q1.x; pa1.y += q1.y; pa1.z += q1.z; pa1.w += q1.w;
            }
        }

        #pragma unroll
        for (int k = 0; k < BK; ++k) {
            float a[8], w[4];
            #pragma unroll
            for (int i = 0; i < 8; i++) a[i] = As[k][ty * 8 + i];
            #pragma unroll
            for (int j = 0; j < 4; j++) w[j] = Ws[k][tx * 4 + j];
            #pragma unroll
            for (int i = 0; i < 8; i++)
                #pragma unroll
                for (int j = 0; j < 4; j++) acc[i][j] += a[i] * w[j];
        }
        __syncthreads();
    }

    const float b0 = bias[n0 + tx*4 + 0];
    const float b1 = bias[n0 + tx*4 + 1];
    const float b2 = bias[n0 + tx*4 + 2];
    const float b3 = bias[n0 + tx*4 + 3];
    #pragma unroll
    for (int i = 0; i < 8; i++) {
        float4 o;
        o.x = acc[i][0] + b0; o.y = acc[i][1] + b1;
        o.z = acc[i][2] + b2; o.w = acc[i][3] + b3;
        *(float4*)(C + (size_t)(m0 + ty*8 + i) * Dout + n0 + tx*4) = o;
    }
}

// ---------------- K/V pack ----------------
__global__ void kv_pack(const float* __restrict__ kb, const float* __restrict__ vb,
                        __half* __restrict__ khg, __half* __restrict__ vtg)
{
    const int i = blockIdx.x * 256 + threadIdx.x;
    if (i >= H_HEADS * M_BOX) return;
    const int h = i >> 8, m = i & 255;

    {
        const float4* kp = (const float4*)(kb + (size_t)m * D_DIM + h * HD_DIM);
        __half2 hrow[16];
        #pragma unroll
        for (int j = 0; j < 6; j++) {
            float4 f = kp[j];
            hrow[2*j]   = __floats2half2_rn(f.x, f.y);
            hrow[2*j+1] = __floats2half2_rn(f.z, f.w);
        }
        const __half2 zz = __floats2half2_rn(0.f, 0.f);
        hrow[12] = zz; hrow[13] = zz; hrow[14] = zz; hrow[15] = zz;
        uint4* dst = (uint4*)(khg + ((size_t)h * M_BOX + m) * 32);
        dst[0] = ((const uint4*)hrow)[0];
        dst[1] = ((const uint4*)hrow)[1];
        dst[2] = ((const uint4*)hrow)[2];
        dst[3] = ((const uint4*)hrow)[3];
    }
    {
        const float4* vp = (const float4*)(vb + (size_t)m * D_DIM + h * HD_DIM);
        __half* base = vtg + (size_t)h * HD_DIM * M_BOX + m;
        #pragma unroll
        for (int j = 0; j < 6; j++) {
            float4 g = vp[j];
            base[(4*j+0) * M_BOX] = __float2half(g.x);
            base[(4*j+1) * M_BOX] = __float2half(g.y);
            base[(4*j+2) * M_BOX] = __float2half(g.z);
            base[(4*j+3) * M_BOX] = __float2half(g.w);
        }
    }
}

// ================= tensor-core attention: one CTA per (4 sets, head) =================
#define AT_QS   0
#define AT_KS   1920
#define AT_VT   12160
#define AT_PS   18496
#define AT_INT  31168
#define ATTN_SMEM (31168 * 2 + (36 + 256) * 4)

__global__ __launch_bounds__(256)
void attn_mma(const __half* __restrict__ qh, const __half* __restrict__ khg,
              const __half* __restrict__ vtg, const int* __restrict__ vinds,
              const int* __restrict__ vcoords, const int* __restrict__ bcoords,
              __half* __restrict__ ctxh)
{
    extern __shared__ __half sm[];
    __half* Qs = sm + AT_QS;
    __half* Ks = sm + AT_KS;
    __half* Vt = sm + AT_VT;
    __half* Ps = sm + AT_PS;
    int* qb = (int*)(sm + AT_INT);
    int* bb = qb + 36;

    const int s0idx = blockIdx.x * SPC, h = blockIdx.y;
    const int t = threadIdx.x, lane = t & 31, wid = t >> 5;
    const int lr = lane >> 2, lc2 = (lane & 3) * 2;

    // ---- K/V staging: ONCE per CTA ----
    {
        const uint4* kp = (const uint4*)(khg + ((size_t)h * M_BOX + t) * 32);
        uint4* krow = (uint4*)(Ks + t * 40);
        krow[0] = kp[0];
        krow[1] = kp[1];
        krow[2] = kp[2];
        krow[3] = kp[3];
        bb[t] = bcoords[t * 4];
    }
    {
        const __half* vsrc = vtg + (size_t)h * HD_DIM * M_BOX;
        #pragma unroll
        for (int j = 0; j < 3; j++) {
            const int idx = t + 256 * j;
            const int r = idx >> 5, c = idx & 31;
            *(uint4*)(Vt + r * 264 + c * 8) = *(const uint4*)(vsrc + r * M_BOX + c * 8);
        }
    }

    for (int si = 0; si < SPC; ++si) {
        const int s = s0idx + si;

        // ---- Q gather (overlaps previous set's ctx: disjoint buffers) ----
        {
            const uint4 z4 = make_uint4(0u, 0u, 0u, 0u);
            for (int i = t; i < 36 * 4; i += 256) {
                const int l = i >> 2, c = i & 3;
                uint4 v;
                if (c < 3) v = *(const uint4*)(qh + (size_t)vinds[s * L_LEN + l] * D_DIM + h * HD_DIM + c * 8);
                else       v = z4;
                *(uint4*)(Qs + l * 40 + c * 8) = v;
            }
        }
        if (t < 36) qb[t] = vcoords[(size_t)vinds[s * L_LEN + t] * 4];
        __syncthreads();   // Q visible; previous set's ctx (Ps readers) finished

        // ---- scores: S = Q @ K^T ----
        float acc[3][4][4];
        #pragma unroll
        for (int i = 0; i < 3; i++)
            #pragma unroll
            for (int j = 0; j < 4; j++)
                #pragma unroll
                for (int e = 0; e < 4; e++) acc[i][j][e] = 0.f;

        #pragma unroll
        for (int kk = 0; kk < 2; kk++) {
            const int k0 = kk * 16;
            uint32_t af[3][4], bf[4][2];
            #pragma unroll
            for (int i = 0; i < 3; i++) {
                const __half* p = Qs + (i * 16 + lr) * 40 + k0 + lc2;
                af[i][0] = *(const uint32_t*)(p);
                af[i][1] = *(const uint32_t*)(p + 8 * 40);
                af[i][2] = *(const uint32_t*)(p + 8);
                af[i][3] = *(const uint32_t*)(p + 8 * 40 + 8);
            }
            #pragma unroll
            for (int j = 0; j < 4; j++) {
                const __half* p = Ks + (wid * 32 + j * 8 + lr) * 40 + k0 + lc2;
                bf[j][0] = *(const uint32_t*)(p);
                bf[j][1] = *(const uint32_t*)(p + 8);
            }
            #pragma unroll
            for (int i = 0; i < 3; i++)
                #pragma unroll
                for (int j = 0; j < 4; j++)
                    mma16816(acc[i][j], af[i], bf[j]);
        }

        {
            const float scale = 0.20412414523193154f;
            #pragma unroll
            for (int i = 0; i < 3; i++) {
                const int r0 = i * 16 + lr, r1 = r0 + 8;
                const int q0 = (r0 < L_LEN) ? qb[r0] : 0;
                const int q1 = (r1 < L_LEN) ? qb[r1] : 0;
                #pragma unroll
                for (int j = 0; j < 4; j++) {
                    const int c = wid * 32 + j * 8 + lc2;
                    const int b0 = bb[c], b1 = bb[c + 1];
                    if (r0 < L_LEN) {
                        float v0 = (q0 != b0) ? -CUDART_INF_F : acc[i][j][0] * scale;
                        float v1 = (q0 != b1) ? -CUDART_INF_F : acc[i][j][1] * scale;
                        *(__half2*)(Ps + r0 * 264 + c) = __floats2half2_rn(v0, v1);
                    }
                    if (r1 < L_LEN) {
                        float v2 = (q1 != b0) ? -CUDART_INF_F : acc[i][j][2] * scale;
                        float v3 = (q1 != b1) ? -CUDART_INF_F : acc[i][j][3] * scale;
                        *(__half2*)(Ps + r1 * 264 + c) = __floats2half2_rn(v2, v3);
                    }
                }
            }
        }
        __syncthreads();

        // ---- softmax (fp32 math, half storage), warp per row, in place ----
        for (int l = wid; l < L_LEN; l += 8) {
            __half* row = Ps + l * 264;
            float e[8];
            float mx = -CUDART_INF_F;
            #pragma unroll
            for (int i = 0; i < 8; i++) { e[i] = __half2float(row[lane + 32*i]); mx = fmaxf(mx, e[i]); }
            #pragma unroll
            for (int o = 16; o > 0; o >>= 1) mx = fmaxf(mx, __shfl_xor_sync(0xffffffffu, mx, o));
            float sum = 0.f;
            if (mx > -CUDART_INF_F) {
                #pragma unroll
                for (int i = 0; i < 8; i++) { e[i] = __expf(e[i] - mx); sum += e[i]; }
            } else {
                #pragma unroll
                for (int i = 0; i < 8; i++) e[i] = 0.f;
            }
            #pragma unroll
            for (int o = 16; o > 0; o >>= 1) sum += __shfl_xor_sync(0xffffffffu, sum, o);
            const float inv = sum > 0.f ? 1.0f / sum : 0.f;
            #pragma unroll
            for (int i = 0; i < 8; i++) row[lane + 32*i] = __float2half(e[i] * inv);
        }
        __syncthreads();

        // ---- ctx = P @ V : warp mt (0..2), af loaded once per kt ----
        if (wid < 3) {
            const int mt = wid;
            float a2[3][4];
            #pragma unroll
            for (int n = 0; n < 3; n++)
                #pragma unroll
                for (int e = 0; e < 4; e++) a2[n][e] = 0.f;

            #pragma unroll 4
            for (int kt = 0; kt < 16; kt++) {
                uint32_t af[4];
                const __half* pa = Ps + (mt * 16 + lr) * 264 + kt * 16 + lc2;
                af[0] = *(const uint32_t*)(pa);
                af[1] = *(const uint32_t*)(pa + 8 * 264);
                af[2] = *(const uint32_t*)(pa + 8);
                af[3] = *(const uint32_t*)(pa + 8 * 264 + 8);
                #pragma unroll
                for (int nt = 0; nt < 3; nt++) {
                    uint32_t bf[2];
                    const __half* pb = Vt + (nt * 8 + lr) * 264 + kt * 16 + lc2;
                    bf[0] = *(const uint32_t*)(pb);
                    bf[1] = *(const uint32_t*)(pb + 8);
                    mma16816(a2[nt], af, bf);
                }
            }

            const int r0 = mt * 16 + lr, r1 = r0 + 8;
            #pragma unroll
            for (int nt = 0; nt < 3; nt++) {
                const int c = nt * 8 + lc2;
                if (r0 < L_LEN)
                    *(__half2*)(ctxh + ((size_t)s * L_LEN + r0) * D_DIM + h * HD_DIM + c) = __floats2half2_rn(a2[nt][0], a2[nt][1]);
                if (r1 < L_LEN)
                    *(__half2*)(ctxh + ((size_t)s * L_LEN + r1) * D_DIM + h * HD_DIM + c) = __floats2half2_rn(a2[nt][2], a2[nt][3]);
            }
        }
        // no trailing sync: next iteration's post-Q-gather sync orders Ps reuse
    }
}

// ---------------- first-occurrence scatter index ----------------
__global__ void init_fp_kernel(int* __restrict__ fp)
{
    int i = blockIdx.x * blockDim.x + threadIdx.x;
    if (i < N_PTS) fp[i] = 0x7FFFFFFF;
}

__global__ void fill_fp_kernel(const int* __restrict__ vinds, int* __restrict__ fp)
{
    int p = blockIdx.x * blockDim.x + threadIdx.x;
    if (p < S_SETS * L_LEN) {
        int n = vinds[p];
        if (n >= 0 && n < N_PTS) atomicMin(&fp[n], p);
    }
}

// ---------------- residual + layernorm (warp per row) ----------------
template<bool GATHER, bool OUTH>
__global__ __launch_bounds__(256)
void ln_kernel(const float* __restrict__ a, const float* __restrict__ b,
               const int* __restrict__ fp, const float* __restrict__ gamma,
               const float* __restrict__ beta, float* __restrict__ outp,
               __half* __restrict__ oh)
{
    const int row  = (blockIdx.x * 256 + threadIdx.x) >> 5;
    const int lane = threadIdx.x & 31;
    if (row >= N_PTS) return;

    const float* arow = a + (size_t)row * D_DIM;
    const float* brow;
    if (GATHER) {
        int p = fp[row];
        if (p < 0 || p >= N_PTS) p = row;
        brow = b + (size_t)p * D_DIM;
    } else {
        brow = b + (size_t)row * D_DIM;
    }

    float v[6];
    float s = 0.f;
    #pragma unroll
    for (int i = 0; i < 6; i++) {
        const int idx = lane + 32 * i;
        v[i] = arow[idx] + brow[idx];
        s += v[i];
    }
    #pragma unroll
    for (int o = 16; o > 0; o >>= 1) s += __shfl_xor_sync(0xffffffffu, s, o);
    const float mean = s * (1.0f / D_DIM);

    float q = 0.f;
    #pragma unroll
    for (int i = 0; i < 6; i++) { const float d = v[i] - mean; q += d * d; }
    #pragma unroll
    for (int o = 16; o > 0; o >>= 1) q += __shfl_xor_sync(0xffffffffu, q, o);
    const float inv = rsqrtf(q * (1.0f / D_DIM) + 1e-5f);

    float* orow = outp + (size_t)row * D_DIM;
    #pragma unroll
    for (int i = 0; i < 6; i++) {
        const int idx = lane + 32 * i;
        const float val = (v[i] - mean) * inv * gamma[idx] + beta[idx];
        orow[idx] = val;
        if (OUTH) oh[(size_t)row * D_DIM + idx] = __float2half(val);
    }
}

// ---------------- weight conversion (all four in one launch) ----------------
__global__ void cvt_weights_kernel(const float* __restrict__ Wq, const float* __restrict__ Wo,
                                   const float* __restrict__ W1, const float* __restrict__ W2,
                                   __half* __restrict__ wh)
{
    const int i = blockIdx.x * blockDim.x + threadIdx.x;
    const int n4 = 368640 / 4;
    if (i >= n4) return;
    const int e = i * 4;
    const float* srcp;
    int off;
    if (e < WOFF_O)      { srcp = Wq; off = e - WOFF_Q; }
    else if (e < WOFF_1) { srcp = Wo; off = e - WOFF_O; }
    else if (e < WOFF_2) { srcp = W1; off = e - WOFF_1; }
    else                 { srcp = W2; off = e - WOFF_2; }
    float4 x = *(const float4*)(srcp + off);
    ((__half2*)wh)[2*i]   = __floats2half2_rn(x.x, x.y);
    ((__half2*)wh)[2*i+1] = __floats2half2_rn(x.z, x.w);
}

// ---------------- launch ----------------
extern "C" void kernel_launch(void* const* d_in, const int* in_sizes, int n_in,
                              void* d_out, int out_size)
{
    const float* src     = (const float*)d_in[0];
    const float* pos     = (const float*)d_in[1];
    const float* boxf    = (const float*)d_in[2];
    const float* boxp    = (const float*)d_in[3];
    const int*   vcoords = (const int*)  d_in[4];
    const int*   bcoords = (const int*)  d_in[5];
    const int*   vinds   = (const int*)  d_in[6];
    const float* Wq = (const float*)d_in[7];  const float* bq  = (const float*)d_in[8];
    const float* Wk = (const float*)d_in[9];  const float* bk  = (const float*)d_in[10];
    const float* Wv = (const float*)d_in[11]; const float* bv  = (const float*)d_in[12];
    const float* Wo = (const float*)d_in[13]; const float* bo  = (const float*)d_in[14];
    const float* W1 = (const float*)d_in[15]; const float* b1  = (const float*)d_in[16];
    const float* W2 = (const float*)d_in[17]; const float* b2  = (const float*)d_in[18];
    const float* g1 = (const float*)d_in[19]; const float* be1 = (const float*)d_in[20];
    const float* g2 = (const float*)d_in[21]; const float* be2 = (const float*)d_in[22];
    float* out = (float*)d_out;

    float *projb, *xb, *yb, *kb, *vb;
    int* fpb;
    __half *qh, *ctxh, *xh, *hh, *wh, *khg, *vtg;
    cudaGetSymbolAddress((void**)&projb, g_proj);
    cudaGetSymbolAddress((void**)&xb,    g_x);
    cudaGetSymbolAddress((void**)&yb,    g_y);
    cudaGetSymbolAddress((void**)&kb,    g_k);
    cudaGetSymbolAddress((void**)&vb,    g_v);
    cudaGetSymbolAddress((void**)&fpb,   g_fp);
    cudaGetSymbolAddress((void**)&qh,    g_qh);
    cudaGetSymbolAddress((void**)&ctxh,  g_ctxh);
    cudaGetSymbolAddress((void**)&xh,    g_xh);
    cudaGetSymbolAddress((void**)&hh,    g_hh);
    cudaGetSymbolAddress((void**)&wh,    g_wh);
    cudaGetSymbolAddress((void**)&khg,   g_kh);
    cudaGetSymbolAddress((void**)&vtg,   g_vt);

    cudaFuncSetAttribute(attn_mma, cudaFuncAttributeMaxDynamicSharedMemorySize, ATTN_SMEM);
    cudaFuncSetAttribute(hgemm_ares<false, true,  true,  3>,  cudaFuncAttributeMaxDynamicSharedMemorySize, ARES_SMEM);
    cudaFuncSetAttribute(hgemm_ares<false, false, false, 3>,  cudaFuncAttributeMaxDynamicSharedMemorySize, ARES_SMEM);
    cudaFuncSetAttribute(hgemm_ares<true,  true,  false, 12>, cudaFuncAttributeMaxDynamicSharedMemorySize, ARES_SMEM);

    const int MB = N_PTS / 128;   // 720

    // 1: weight conversion
    cvt_weights_kernel<<<(368640/4 + 255)/256, 256>>>(Wq, Wo, W1, W2, wh);
    // 2: K/V projections
    gemm_kv<<<dim3(D_DIM/BN, M_BOX/BM, 2), 256>>>(boxf, boxp, Wk, bk, kb, Wv, bv, vb);
    // 3: pack K/V into attention-ready fp16 layouts
    kv_pack<<<(H_HEADS * M_BOX) / 256, 256>>>(kb, vb, khg, vtg);
    // 4: Q = (src + pos) @ Wq^T + bq  (A-resident, fused add+cvt, HALF output)
    hgemm_ares<false, true, true, 3><<<MB, 256, ARES_SMEM>>>(nullptr, src, pos, wh + WOFF_Q, bq, nullptr, qh, D_DIM);
    // 5: tensor-core masked attention (4 sets per CTA)
    attn_mma<<<dim3(S_SETS / SPC, H_HEADS), 256, ATTN_SMEM>>>(qh, khg, vtg, vinds, vcoords, bcoords, ctxh);
    // 6: O projection (A-resident)
    hgemm_ares<false, false, false, 3><<<MB, 256, ARES_SMEM>>>(ctxh, nullptr, nullptr, wh + WOFF_O, bo, projb, nullptr, D_DIM);
    // 7,8: first-occurrence scatter index
    init_fp_kernel<<<N_PTS / 256, 256>>>(fpb);
    fill_fp_kernel<<<(S_SETS * L_LEN) / 256, 256>>>(vinds, fpb);
    // 9: x = LN(src + proj[first_pos]) (+ half copy)
    ln_kernel<true, true><<<N_PTS / 8, 256>>>(src, projb, fpb, g1, be1, xb, xh);
    // 10: FFN1 (A-resident, relu, half out)
    hgemm_ares<true, true, false, 12><<<MB, 256, ARES_SMEM>>>(xh, nullptr, nullptr, wh + WOFF_1, b1, nullptr, hh, FF_DIM);
    // 11: FFN2 (K=768, streaming kernel)
    hgemm<false, false><<<dim3(D_DIM/64, MB), 256>>>(hh, wh + WOFF_2, b2, yb, nullptr, FF_DIM, D_DIM);
    // 12: out = LN(x + ffn)
    ln_kernel<false, false><<<N_PTS / 8, 256>>>(xb, yb, nullptr, g2, be2, out, nullptr);
}

// round 14
// speedup vs baseline: 3.6258x; 1.0343x over previous
#include <cuda_runtime.h>
#include <cuda_fp16.h>
#include <math_constants.h>
#include <cstdint>

#define N_PTS   92160
#define D_DIM   192
#define BD_DIM  256
#define H_HEADS 8
#define FF_DIM  768
#define S_SETS  2560
#define L_LEN   36
#define M_BOX   256
#define HD_DIM  24
#define SPC     4          // sets per attention CTA

// ---------------- scratch (static device globals; no allocation) ----------------
__device__ float g_proj[N_PTS * D_DIM];
__device__ float g_x[N_PTS * D_DIM];
__device__ float g_y[N_PTS * D_DIM];
__device__ float g_k[M_BOX * D_DIM];
__device__ float g_v[M_BOX * D_DIM];
__device__ int   g_fp[N_PTS];

__device__ __half g_qh[N_PTS * D_DIM];
__device__ __half g_ctxh[N_PTS * D_DIM];
__device__ __half g_xh[N_PTS * D_DIM];
__device__ __half g_hh[(size_t)N_PTS * FF_DIM];
__device__ __half g_kh[H_HEADS * M_BOX * 32];      // [h][m][32] padded fp16 K
__device__ __half g_vt[H_HEADS * HD_DIM * M_BOX];  // [h][d][m]  transposed fp16 V
#define WOFF_Q 0
#define WOFF_O 36864
#define WOFF_1 73728
#define WOFF_2 221184
__device__ __half g_wh[368640];

__device__ __forceinline__ void mma16816(float* d, const uint32_t* a, const uint32_t* b) {
    asm volatile(
        "mma.sync.aligned.m16n8k16.row.col.f32.f16.f16.f32 "
        "{%0,%1,%2,%3}, {%4,%5,%6,%7}, {%8,%9}, {%0,%1,%2,%3};\n"
        : "+f"(d[0]), "+f"(d[1]), "+f"(d[2]), "+f"(d[3])
        : "r"(a[0]), "r"(a[1]), "r"(a[2]), "r"(a[3]), "r"(b[0]), "r"(b[1]));
}

__device__ __forceinline__ uint4 add_cvt8(const float* p, const float* q) {
    float4 x0 = *(const float4*)p;
    float4 x1 = *(const float4*)(p + 4);
    float4 y0 = *(const float4*)q;
    float4 y1 = *(const float4*)(q + 4);
    __half2 h0 = __floats2half2_rn(x0.x + y0.x, x0.y + y0.y);
    __half2 h1 = __floats2half2_rn(x0.z + y0.z, x0.w + y0.w);
    __half2 h2 = __floats2half2_rn(x1.x + y1.x, x1.y + y1.y);
    __half2 h3 = __floats2half2_rn(x1.z + y1.z, x1.w + y1.w);
    uint4 r;
    r.x = *(uint32_t*)&h0; r.y = *(uint32_t*)&h1;
    r.z = *(uint32_t*)&h2; r.w = *(uint32_t*)&h3;
    return r;
}

// ================= A-resident fp16 GEMM for K=192: C = A @ W^T + bias =================
#define ARES_SMEM ((128 * 200 + 2 * 64 * 40) * 2)

template<bool RELU, bool OUTH, bool ADDIN, int NTILES>
__global__ __launch_bounds__(256)
void hgemm_ares(const __half* __restrict__ A, const float* __restrict__ Af,
                const float* __restrict__ Af2, const __half* __restrict__ W,
                const float* __restrict__ bias, float* __restrict__ C,
                __half* __restrict__ Ch, int Dout)
{
    extern __shared__ __half dsm[];
    __half* As = dsm;                 // 128 x 200
    __half* Wb0 = dsm + 25600;        // 64 x 40
    __half* Wb1 = dsm + 28160;

    const int tid  = threadIdx.x;
    const int lane = tid & 31;
    const int wid  = tid >> 5;
    const int wm   = wid & 3;
    const int wn   = wid >> 2;
    const int m0   = blockIdx.x * 128;
    const int lr   = lane >> 2;
    const int lc2  = (lane & 3) * 2;

    #pragma unroll
    for (int j = 0; j < 12; j++) {
        const int idx = tid + 256 * j;
        const int r = idx / 24, c8 = (idx % 24) * 8;
        const size_t go = (size_t)(m0 + r) * 192 + c8;
        uint4 v;
        if (ADDIN) v = add_cvt8(Af + go, Af2 + go);
        else       v = *(const uint4*)(A + go);
        *(uint4*)(As + r * 200 + c8) = v;
    }

    const int rw = tid >> 2;
    const int cw = (tid & 3) * 8;
    const int sW = rw * 40 + cw;

    const int NI = NTILES * 6;
    uint4 pw = *(const uint4*)(W + (size_t)rw * 192 + cw);
    *(uint4*)(Wb0 + sW) = pw;

    float acc[2][4][4];

    for (int i = 0; i < NI; ++i) {
        const int nt = i / 6, kc = i % 6;
        __syncthreads();

        if (kc == 0) {
            #pragma unroll
            for (int a = 0; a < 2; a++)
                #pragma unroll
                for (int b = 0; b < 4; b++)
                    #pragma unroll
                    for (int e = 0; e < 4; e++) acc[a][b][e] = 0.f;
        }

        if (i + 1 < NI) {
            const int nt2 = (i + 1) / 6, kc2 = (i + 1) % 6;
            pw = *(const uint4*)(W + (size_t)(nt2 * 64 + rw) * 192 + kc2 * 32 + cw);
        }

        const __half* Ws = (i & 1) ? Wb1 : Wb0;
        const int ca = kc * 32;

        #pragma unroll
        for (int ks = 0; ks < 32; ks += 16) {
            uint32_t af[2][4], bf[4][2];
            #pragma unroll
            for (int a = 0; a < 2; a++) {
                const __half* p = As + (wm * 32 + a * 16 + lr) * 200 + ca + ks + lc2;
                af[a][0] = *(const uint32_t*)(p);
                af[a][1] = *(const uint32_t*)(p + 8 * 200);
                af[a][2] = *(const uint32_t*)(p + 8);
                af[a][3] = *(const uint32_t*)(p + 8 * 200 + 8);
            }
            #pragma unroll
            for (int b = 0; b < 4; b++) {
                const __half* p = Ws + (wn * 32 + b * 8 + lr) * 40 + ks + lc2;
                bf[b][0] = *(const uint32_t*)(p);
                bf[b][1] = *(const uint32_t*)(p + 8);
            }
            #pragma unroll
            for (int a = 0; a < 2; a++)
                #pragma unroll
                for (int b = 0; b < 4; b++)
                    mma16816(acc[a][b], af[a], bf[b]);
        }

        if (kc == 5) {
            const int n0 = nt * 64;
            #pragma unroll
            for (int a = 0; a < 2; a++) {
                const int r = m0 + wm * 32 + a * 16 + lr;
                #pragma unroll
                for (int b = 0; b < 4; b++) {
                    const int cj = n0 + wn * 32 + b * 8 + lc2;
                    const float2 bx = *(const float2*)(bias + cj);
                    float v0 = acc[a][b][0] + bx.x;
                    float v1 = acc[a][b][1] + bx.y;
                    float v2 = acc[a][b][2] + bx.x;
                    float v3 = acc[a][b][3] + bx.y;
                    if (RELU) {
                        v0 = fmaxf(v0, 0.f); v1 = fmaxf(v1, 0.f);
                        v2 = fmaxf(v2, 0.f); v3 = fmaxf(v3, 0.f);
                    }
                    if (OUTH) {
                        *(__half2*)(Ch + (size_t)r       * Dout + cj) = __floats2half2_rn(v0, v1);
                        *(__half2*)(Ch + (size_t)(r + 8) * Dout + cj) = __floats2half2_rn(v2, v3);
                    } else {
                        *(float2*)(C + (size_t)r       * Dout + cj) = make_float2(v0, v1);
                        *(float2*)(C + (size_t)(r + 8) * Dout + cj) = make_float2(v2, v3);
                    }
                }
            }
        }

        if (i + 1 < NI) {
            __half* nb = ((i + 1) & 1) ? Wb1 : Wb0;
            *(uint4*)(nb + sW) = pw;
        }
    }
}

// ================= wide fp16 GEMM: C = A @ W^T + bias, BN = 192 (full row) =================
// Used for FFN2 (K=768). A read exactly once. CTA 128 x 192, 8 warps = 4m x 2n,
// warp tile 32 x 96. Per K-chunk: 320 rows (128 A + 192 W) x 32 halves in smem.
#define WIDE_SMEM (2 * 320 * 40 * 2)   // 51200 B

__global__ __launch_bounds__(256)
void hgemm_wide(const __half* __restrict__ A, const __half* __restrict__ W,
                const float* __restrict__ bias, float* __restrict__ C)
{
    extern __shared__ __half wsm[];
    const int K = FF_DIM;              // 768
    const int Dout = D_DIM;            // 192

    const int tid  = threadIdx.x;
    const int lane = tid & 31;
    const int wid  = tid >> 5;
    const int wm   = wid & 3;          // row band (32)
    const int wn   = wid >> 2;         // col band (96)
    const int m0   = blockIdx.x * 128;
    const int lr   = lane >> 2;
    const int lc2  = (lane & 3) * 2;

    // loader: 1280 uint4 per chunk = 5 per thread; unified row space r: 0..127 A, 128..319 W
    const int nT = K >> 5;             // 24

    int lrow[5], lcol[5];
    const __half* gptr[5];
    #pragma unroll
    for (int j = 0; j < 5; j++) {
        const int u = tid + 256 * j;   // 0..1279
        const int r = u >> 2, c8 = (u & 3) * 8;
        lrow[j] = r; lcol[j] = c8;
        gptr[j] = (r < 128) ? (A + (size_t)(m0 + r) * K + c8)
                            : (W + (size_t)(r - 128) * K + c8);
    }

    uint4 st[5];
    #pragma unroll
    for (int j = 0; j < 5; j++) st[j] = *(const uint4*)(gptr[j]);

    float acc[2][12][4];
    #pragma unroll
    for (int a = 0; a < 2; a++)
        #pragma unroll
        for (int b = 0; b < 12; b++)
            #pragma unroll
            for (int e = 0; e < 4; e++) acc[a][b][e] = 0.f;

    // stage 0 store
    {
        __half* s0 = wsm;
        #pragma unroll
        for (int j = 0; j < 5; j++)
            *(uint4*)(s0 + lrow[j] * 40 + lcol[j]) = st[j];
    }

    for (int t = 0; t < nT; ++t) {
        __syncthreads();

        if (t + 1 < nT) {
            const int off = (t + 1) * 32;
            #pragma unroll
            for (int j = 0; j < 5; j++) st[j] = *(const uint4*)(gptr[j] + off);
        }

        const __half* As = wsm + (t & 1) * (320 * 40);
        const __half* Ws = As + 128 * 40;

        #pragma unroll
        for (int ks = 0; ks < 32; ks += 16) {
            uint32_t af[2][4];
            #pragma unroll
            for (int a = 0; a < 2; a++) {
                const __half* p = As + (wm * 32 + a * 16 + lr) * 40 + ks + lc2;
                af[a][0] = *(const uint32_t*)(p);
                af[a][1] = *(const uint32_t*)(p + 8 * 40);
                af[a][2] = *(const uint32_t*)(p + 8);
                af[a][3] = *(const uint32_t*)(p + 8 * 40 + 8);
            }
            #pragma unroll
            for (int b = 0; b < 12; b++) {
                uint32_t bf[2];
                const __half* p = Ws + (wn * 96 + b * 8 + lr) * 40 + ks + lc2;
                bf[0] = *(const uint32_t*)(p);
                bf[1] = *(const uint32_t*)(p + 8);
                mma16816(acc[0][b], af[0], bf);
                mma16816(acc[1][b], af[1], bf);
            }
        }

        if (t + 1 < nT) {
            __half* nb = wsm + ((t + 1) & 1) * (320 * 40);
            #pragma unroll
            for (int j = 0; j < 5; j++)
                *(uint4*)(nb + lrow[j] * 40 + lcol[j]) = st[j];
        }
    }

    // epilogue
    #pragma unroll
    for (int a = 0; a < 2; a++) {
        const int r = m0 + wm * 32 + a * 16 + lr;
        #pragma unroll
        for (int b = 0; b < 12; b++) {
            const int cj = wn * 96 + b * 8 + lc2;
            const float2 bx = *(const float2*)(bias + cj);
            *(float2*)(C + (size_t)r       * Dout + cj) = make_float2(acc[a][b][0] + bx.x, acc[a][b][1] + bx.y);
            *(float2*)(C + (size_t)(r + 8) * Dout + cj) = make_float2(acc[a][b][2] + bx.x, acc[a][b][3] + bx.y);
        }
    }
}

// ---------------- combined K/V projection (SIMT fp32), blockIdx.z selects ----------------
#define BM 128
#define BN 64
#define BK 16

__global__ __launch_bounds__(256, 2)
void gemm_kv(const float* __restrict__ boxf, const float* __restrict__ boxp,
             const float* __restrict__ Wk, const float* __restrict__ bk, float* __restrict__ Ck,
             const float* __restrict__ Wv, const float* __restrict__ bv, float* __restrict__ Cv)
{
    const bool isK = (blockIdx.z == 0);
    const float* A   = boxf;
    const float* A2  = isK ? boxp : nullptr;
    const float* W   = isK ? Wk : Wv;
    const float* bias= isK ? bk : bv;
    float* C         = isK ? Ck : Cv;
    const int K = BD_DIM, Dout = D_DIM;

    __shared__ float As[BK][BM + 4];
    __shared__ float Ws[BK][BN + 4];

    const int tid = threadIdx.x;
    const int tx = tid & 15;
    const int ty = tid >> 4;
    const int m0 = blockIdx.y * BM;
    const int n0 = blockIdx.x * BN;

    const int ar = tid >> 2;
    const int ac = (tid & 3) << 2;

    const float* Ap0 = A + (size_t)(m0 + ar)      * K + ac;
    const float* Ap1 = A + (size_t)(m0 + ar + 64) * K + ac;
    const float* Wp  = W + (size_t)(n0 + ar)      * K + ac;

    const int nT = K / BK;

    float4 pa0 = *(const float4*)(Ap0);
    float4 pa1 = *(const float4*)(Ap1);
    float4 pw  = *(const float4*)(Wp);
    if (isK) {
        const float* B0 = A2 + (size_t)(m0 + ar) * K + ac;
        const float* B1 = A2 + (size_t)(m0 + ar + 64) * K + ac;
        float4 q0 = *(const float4*)B0;
        float4 q1 = *(const float4*)B1;
        pa0.x += q0.x; pa0.y += q0.y; pa0.z += q0.z; pa0.w += q0.w;
        pa1.x += q1.x; pa1.y += q1.y; pa1.z += q1.z; pa1.w += q1.w;
    }

    float acc[8][4];
    #pragma unroll
    for (int i = 0; i < 8; i++)
        #pragma unroll
        for (int j = 0; j < 4; j++) acc[i][j] = 0.f;

    for (int t = 0; t < nT; ++t) {
        As[ac+0][ar]    = pa0.x; As[ac+1][ar]    = pa0.y;
        As[ac+2][ar]    = pa0.z; As[ac+3][ar]    = pa0.w;
        As[ac+0][ar+64] = pa1.x; As[ac+1][ar+64] = pa1.y;
        As[ac+2][ar+64] = pa1.z; As[ac+3][ar+64] = pa1.w;
        Ws[ac+0][ar]    = pw.x;  Ws[ac+1][ar]    = pw.y;
        Ws[ac+2][ar]    = pw.z;  Ws[ac+3][ar]    = pw.w;
        __syncthreads();

        if (t + 1 < nT) {
            const int off = (t + 1) * BK;
            pa0 = *(const float4*)(Ap0 + off);
            pa1 = *(const float4*)(Ap1 + off);
            pw  = *(const float4*)(Wp  + off);
            if (isK) {
                const float* B0 = A2 + (size_t)(m0 + ar) * K + ac + off;
                const float* B1 = A2 + (size_t)(m0 + ar + 64) * K + ac + off;
                float4 q0 = *(const float4*)B0;
                float4 q1 = *(const float4*)B1;
                pa0.x += q0.x; pa0.y += q0.y; pa0.z += q0.z; pa0.w += q0.w;
                pa1.x += q1.x; pa1.y += q1.y; pa1.z += q1.z; pa1.w += q1.w;
            }
        }

        #pragma unroll
        for (int k = 0; k < BK; ++k) {
            float a[8], w[4];
            #pragma unroll
            for (int i = 0; i < 8; i++) a[i] = As[k][ty * 8 + i];
            #pragma unroll
            for (int j = 0; j < 4; j++) w[j] = Ws[k][tx * 4 + j];
            #pragma unroll
            for (int i = 0; i < 8; i++)
                #pragma unroll
                for (int j = 0; j < 4; j++) acc[i][j] += a[i] * w[j];
        }
        __syncthreads();
    }

    const float b0 = bias[n0 + tx*4 + 0];
    const float b1 = bias[n0 + tx*4 + 1];
    const float b2 = bias[n0 + tx*4 + 2];
    const float b3 = bias[n0 + tx*4 + 3];
    #pragma unroll
    for (int i = 0; i < 8; i++) {
        float4 o;
        o.x = acc[i][0] + b0; o.y = acc[i][1] + b1;
        o.z = acc[i][2] + b2; o.w = acc[i][3] + b3;
        *(float4*)(C + (size_t)(m0 + ty*8 + i) * Dout + n0 + tx*4) = o;
    }
}

// ---------------- K/V pack ----------------
__global__ void kv_pack(const float* __restrict__ kb, const float* __restrict__ vb,
                        __half* __restrict__ khg, __half* __restrict__ vtg)
{
    const int i = blockIdx.x * 256 + threadIdx.x;
    if (i >= H_HEADS * M_BOX) return;
    const int h = i >> 8, m = i & 255;

    {
        const float4* kp = (const float4*)(kb + (size_t)m * D_DIM + h * HD_DIM);
        __half2 hrow[16];
        #pragma unroll
        for (int j = 0; j < 6; j++) {
            float4 f = kp[j];
            hrow[2*j]   = __floats2half2_rn(f.x, f.y);
            hrow[2*j+1] = __floats2half2_rn(f.z, f.w);
        }
        const __half2 zz = __floats2half2_rn(0.f, 0.f);
        hrow[12] = zz; hrow[13] = zz; hrow[14] = zz; hrow[15] = zz;
        uint4* dst = (uint4*)(khg + ((size_t)h * M_BOX + m) * 32);
        dst[0] = ((const uint4*)hrow)[0];
        dst[1] = ((const uint4*)hrow)[1];
        dst[2] = ((const uint4*)hrow)[2];
        dst[3] = ((const uint4*)hrow)[3];
    }
    {
        const float4* vp = (const float4*)(vb + (size_t)m * D_DIM + h * HD_DIM);
        __half* base = vtg + (size_t)h * HD_DIM * M_BOX + m;
        #pragma unroll
        for (int j = 0; j < 6; j++) {
            float4 g = vp[j];
            base[(4*j+0) * M_BOX] = __float2half(g.x);
            base[(4*j+1) * M_BOX] = __float2half(g.y);
            base[(4*j+2) * M_BOX] = __float2half(g.z);
            base[(4*j+3) * M_BOX] = __float2half(g.w);
        }
    }
}

// ================= tensor-core attention: one CTA per (4 sets, head) =================
#define AT_QS   0
#define AT_KS   1920
#define AT_VT   12160
#define AT_PS   18496
#define AT_INT  31168
#define ATTN_SMEM (31168 * 2 + (36 + 256) * 4)

__global__ __launch_bounds__(256)
void attn_mma(const __half* __restrict__ qh, const __half* __restrict__ khg,
              const __half* __restrict__ vtg, const int* __restrict__ vinds,
              const int* __restrict__ vcoords, const int* __restrict__ bcoords,
              __half* __restrict__ ctxh)
{
    extern __shared__ __half sm[];
    __half* Qs = sm + AT_QS;
    __half* Ks = sm + AT_KS;
    __half* Vt = sm + AT_VT;
    __half* Ps = sm + AT_PS;
    int* qb = (int*)(sm + AT_INT);
    int* bb = qb + 36;

    const int s0idx = blockIdx.x * SPC, h = blockIdx.y;
    const int t = threadIdx.x, lane = t & 31, wid = t >> 5;
    const int lr = lane >> 2, lc2 = (lane & 3) * 2;

    {
        const uint4* kp = (const uint4*)(khg + ((size_t)h * M_BOX + t) * 32);
        uint4* krow = (uint4*)(Ks + t * 40);
        krow[0] = kp[0];
        krow[1] = kp[1];
        krow[2] = kp[2];
        krow[3] = kp[3];
        bb[t] = bcoords[t * 4];
    }
    {
        const __half* vsrc = vtg + (size_t)h * HD_DIM * M_BOX;
        #pragma unroll
        for (int j = 0; j < 3; j++) {
            const int idx = t + 256 * j;
            const int r = idx >> 5, c = idx & 31;
            *(uint4*)(Vt + r * 264 + c * 8) = *(const uint4*)(vsrc + r * M_BOX + c * 8);
        }
    }

    for (int si = 0; si < SPC; ++si) {
        const int s = s0idx + si;

        {
            const uint4 z4 = make_uint4(0u, 0u, 0u, 0u);
            for (int i = t; i < 36 * 4; i += 256) {
                const int l = i >> 2, c = i & 3;
                uint4 v;
                if (c < 3) v = *(const uint4*)(qh + (size_t)vinds[s * L_LEN + l] * D_DIM + h * HD_DIM + c * 8);
                else       v = z4;
                *(uint4*)(Qs + l * 40 + c * 8) = v;
            }
        }
        if (t < 36) qb[t] = vcoords[(size_t)vinds[s * L_LEN + t] * 4];
        __syncthreads();

        float acc[3][4][4];
        #pragma unroll
        for (int i = 0; i < 3; i++)
            #pragma unroll
            for (int j = 0; j < 4; j++)
                #pragma unroll
                for (int e = 0; e < 4; e++) acc[i][j][e] = 0.f;

        #pragma unroll
        for (int kk = 0; kk < 2; kk++) {
            const int k0 = kk * 16;
            uint32_t af[3][4], bf[4][2];
            #pragma unroll
            for (int i = 0; i < 3; i++) {
                const __half* p = Qs + (i * 16 + lr) * 40 + k0 + lc2;
                af[i][0] = *(const uint32_t*)(p);
                af[i][1] = *(const uint32_t*)(p + 8 * 40);
                af[i][2] = *(const uint32_t*)(p + 8);
                af[i][3] = *(const uint32_t*)(p + 8 * 40 + 8);
            }
            #pragma unroll
            for (int j = 0; j < 4; j++) {
                const __half* p = Ks + (wid * 32 + j * 8 + lr) * 40 + k0 + lc2;
                bf[j][0] = *(const uint32_t*)(p);
                bf[j][1] = *(const uint32_t*)(p + 8);
            }
            #pragma unroll
            for (int i = 0; i < 3; i++)
                #pragma unroll
                for (int j = 0; j < 4; j++)
                    mma16816(acc[i][j], af[i], bf[j]);
        }

        {
            const float scale = 0.20412414523193154f;
            #pragma unroll
            for (int i = 0; i < 3; i++) {
                const int r0 = i * 16 + lr, r1 = r0 + 8;
                const int q0 = (r0 < L_LEN) ? qb[r0] : 0;
                const int q1 = (r1 < L_LEN) ? qb[r1] : 0;
                #pragma unroll
                for (int j = 0; j < 4; j++) {
                    const int c = wid * 32 + j * 8 + lc2;
                    const int b0 = bb[c], b1 = bb[c + 1];
                    if (r0 < L_LEN) {
                        float v0 = (q0 != b0) ? -CUDART_INF_F : acc[i][j][0] * scale;
                        float v1 = (q0 != b1) ? -CUDART_INF_F : acc[i][j][1] * scale;
                        *(__half2*)(Ps + r0 * 264 + c) = __floats2half2_rn(v0, v1);
                    }
                    if (r1 < L_LEN) {
                        float v2 = (q1 != b0) ? -CUDART_INF_F : acc[i][j][2] * scale;
                        float v3 = (q1 != b1) ? -CUDART_INF_F : acc[i][j][3] * scale;
                        *(__half2*)(Ps + r1 * 264 + c) = __floats2half2_rn(v2, v3);
                    }
                }
            }
        }
        __syncthreads();

        for (int l = wid; l < L_LEN; l += 8) {
            __half* row = Ps + l * 264;
            float e[8];
            float mx = -CUDART_INF_F;
            #pragma unroll
            for (int i = 0; i < 8; i++) { e[i] = __half2float(row[lane + 32*i]); mx = fmaxf(mx, e[i]); }
            #pragma unroll
            for (int o = 16; o > 0; o >>= 1) mx = fmaxf(mx, __shfl_xor_sync(0xffffffffu, mx, o));
            float sum = 0.f;
            if (mx > -CUDART_INF_F) {
                #pragma unroll
                for (int i = 0; i < 8; i++) { e[i] = __expf(e[i] - mx); sum += e[i]; }
            } else {
                #pragma unroll
                for (int i = 0; i < 8; i++) e[i] = 0.f;
            }
            #pragma unroll
            for (int o = 16; o > 0; o >>= 1) sum += __shfl_xor_sync(0xffffffffu, sum, o);
            const float inv = sum > 0.f ? 1.0f / sum : 0.f;
            #pragma unroll
            for (int i = 0; i < 8; i++) row[lane + 32*i] = __float2half(e[i] * inv);
        }
        __syncthreads();

        if (wid < 3) {
            const int mt = wid;
            float a2[3][4];
            #pragma unroll
            for (int n = 0; n < 3; n++)
                #pragma unroll
                for (int e = 0; e < 4; e++) a2[n][e] = 0.f;

            #pragma unroll 4
            for (int kt = 0; kt < 16; kt++) {
                uint32_t af[4];
                const __half* pa = Ps + (mt * 16 + lr) * 264 + kt * 16 + lc2;
                af[0] = *(const uint32_t*)(pa);
                af[1] = *(const uint32_t*)(pa + 8 * 264);
                af[2] = *(const uint32_t*)(pa + 8);
                af[3] = *(const uint32_t*)(pa + 8 * 264 + 8);
                #pragma unroll
                for (int nt = 0; nt < 3; nt++) {
                    uint32_t bf[2];
                    const __half* pb = Vt + (nt * 8 + lr) * 264 + kt * 16 + lc2;
                    bf[0] = *(const uint32_t*)(pb);
                    bf[1] = *(const uint32_t*)(pb + 8);
                    mma16816(a2[nt], af, bf);
                }
            }

            const int r0 = mt * 16 + lr, r1 = r0 + 8;
            #pragma unroll
            for (int nt = 0; nt < 3; nt++) {
                const int c = nt * 8 + lc2;
                if (r0 < L_LEN)
                    *(__half2*)(ctxh + ((size_t)s * L_LEN + r0) * D_DIM + h * HD_DIM + c) = __floats2half2_rn(a2[nt][0], a2[nt][1]);
                if (r1 < L_LEN)
                    *(__half2*)(ctxh + ((size_t)s * L_LEN + r1) * D_DIM + h * HD_DIM + c) = __floats2half2_rn(a2[nt][2], a2[nt][3]);
            }
        }
    }
}

// ---------------- first-occurrence scatter index ----------------
__global__ void init_fp_kernel(int* __restrict__ fp)
{
    int i = blockIdx.x * blockDim.x + threadIdx.x;
    if (i < N_PTS) fp[i] = 0x7FFFFFFF;
}

__global__ void fill_fp_kernel(const int* __restrict__ vinds, int* __restrict__ fp)
{
    int p = blockIdx.x * blockDim.x + threadIdx.x;
    if (p < S_SETS * L_LEN) {
        int n = vinds[p];
        if (n >= 0 && n < N_PTS) atomicMin(&fp[n], p);
    }
}

// ---------------- residual + layernorm (warp per row) ----------------
template<bool GATHER, bool OUTH>
__global__ __launch_bounds__(256)
void ln_kernel(const float* __restrict__ a, const float* __restrict__ b,
               const int* __restrict__ fp, const float* __restrict__ gamma,
               const float* __restrict__ beta, float* __restrict__ outp,
               __half* __restrict__ oh)
{
    const int row  = (blockIdx.x * 256 + threadIdx.x) >> 5;
    const int lane = threadIdx.x & 31;
    if (row >= N_PTS) return;

    const float* arow = a + (size_t)row * D_DIM;
    const float* brow;
    if (GATHER) {
        int p = fp[row];
        if (p < 0 || p >= N_PTS) p = row;
        brow = b + (size_t)p * D_DIM;
    } else {
        brow = b + (size_t)row * D_DIM;
    }

    float v[6];
    float s = 0.f;
    #pragma unroll
    for (int i = 0; i < 6; i++) {
        const int idx = lane + 32 * i;
        v[i] = arow[idx] + brow[idx];
        s += v[i];
    }
    #pragma unroll
    for (int o = 16; o > 0; o >>= 1) s += __shfl_xor_sync(0xffffffffu, s, o);
    const float mean = s * (1.0f / D_DIM);

    float q = 0.f;
    #pragma unroll
    for (int i = 0; i < 6; i++) { const float d = v[i] - mean; q += d * d; }
    #pragma unroll
    for (int o = 16; o > 0; o >>= 1) q += __shfl_xor_sync(0xffffffffu, q, o);
    const float inv = rsqrtf(q * (1.0f / D_DIM) + 1e-5f);

    float* orow = outp + (size_t)row * D_DIM;
    #pragma unroll
    for (int i = 0; i < 6; i++) {
        const int idx = lane + 32 * i;
        const float val = (v[i] - mean) * inv * gamma[idx] + beta[idx];
        orow[idx] = val;
        if (OUTH) oh[(size_t)row * D_DIM + idx] = __float2half(val);
    }
}

// ---------------- weight conversion (all four in one launch) ----------------
__global__ void cvt_weights_kernel(const float* __restrict__ Wq, const float* __restrict__ Wo,
                                   const float* __restrict__ W1, const float* __restrict__ W2,
                                   __half* __restrict__ wh)
{
    const int i = blockIdx.x * blockDim.x + threadIdx.x;
    const int n4 = 368640 / 4;
    if (i >= n4) return;
    const int e = i * 4;
    const float* srcp;
    int off;
    if (e < WOFF_O)      { srcp = Wq; off = e - WOFF_Q; }
    else if (e < WOFF_1) { srcp = Wo; off = e - WOFF_O; }
    else if (e < WOFF_2) { srcp = W1; off = e - WOFF_1; }
    else                 { srcp = W2; off = e - WOFF_2; }
    float4 x = *(const float4*)(srcp + off);
    ((__half2*)wh)[2*i]   = __floats2half2_rn(x.x, x.y);
    ((__half2*)wh)[2*i+1] = __floats2half2_rn(x.z, x.w);
}

// ---------------- launch ----------------
extern "C" void kernel_launch(void* const* d_in, const int* in_sizes, int n_in,
                              void* d_out, int out_size)
{
    const float* src     = (const float*)d_in[0];
    const float* pos     = (const float*)d_in[1];
    const float* boxf    = (const float*)d_in[2];
    const float* boxp    = (const float*)d_in[3];
    const int*   vcoords = (const int*)  d_in[4];
    const int*   bcoords = (const int*)  d_in[5];
    const int*   vinds   = (const int*)  d_in[6];
    const float* Wq = (const float*)d_in[7];  const float* bq  = (const float*)d_in[8];
    const float* Wk = (const float*)d_in[9];  const float* bk  = (const float*)d_in[10];
    const float* Wv = (const float*)d_in[11]; const float* bv  = (const float*)d_in[12];
    const float* Wo = (const float*)d_in[13]; const float* bo  = (const float*)d_in[14];
    const float* W1 = (const float*)d_in[15]; const float* b1  = (const float*)d_in[16];
    const float* W2 = (const float*)d_in[17]; const float* b2  = (const float*)d_in[18];
    const float* g1 = (const float*)d_in[19]; const float* be1 = (const float*)d_in[20];
    const float* g2 = (const float*)d_in[21]; const float* be2 = (const float*)d_in[22];
    float* out = (float*)d_out;

    float *projb, *xb, *yb, *kb, *vb;
    int* fpb;
    __half *qh, *ctxh, *xh, *hh, *wh, *khg, *vtg;
    cudaGetSymbolAddress((void**)&projb, g_proj);
    cudaGetSymbolAddress((void**)&xb,    g_x);
    cudaGetSymbolAddress((void**)&yb,    g_y);
    cudaGetSymbolAddress((void**)&kb,    g_k);
    cudaGetSymbolAddress((void**)&vb,    g_v);
    cudaGetSymbolAddress((void**)&fpb,   g_fp);
    cudaGetSymbolAddress((void**)&qh,    g_qh);
    cudaGetSymbolAddress((void**)&ctxh,  g_ctxh);
    cudaGetSymbolAddress((void**)&xh,    g_xh);
    cudaGetSymbolAddress((void**)&hh,    g_hh);
    cudaGetSymbolAddress((void**)&wh,    g_wh);
    cudaGetSymbolAddress((void**)&khg,   g_kh);
    cudaGetSymbolAddress((void**)&vtg,   g_vt);

    cudaFuncSetAttribute(attn_mma, cudaFuncAttributeMaxDynamicSharedMemorySize, ATTN_SMEM);
    cudaFuncSetAttribute(hgemm_ares<false, true,  true,  3>,  cudaFuncAttributeMaxDynamicSharedMemorySize, ARES_SMEM);
    cudaFuncSetAttribute(hgemm_ares<false, false, false, 3>,  cudaFuncAttributeMaxDynamicSharedMemorySize, ARES_SMEM);
    cudaFuncSetAttribute(hgemm_ares<true,  true,  false, 12>, cudaFuncAttributeMaxDynamicSharedMemorySize, ARES_SMEM);
    cudaFuncSetAttribute(hgemm_wide, cudaFuncAttributeMaxDynamicSharedMemorySize, WIDE_SMEM);

    const int MB = N_PTS / 128;   // 720

    // 1: weight conversion
    cvt_weights_kernel<<<(368640/4 + 255)/256, 256>>>(Wq, Wo, W1, W2, wh);
    // 2: K/V projections
    gemm_kv<<<dim3(D_DIM/BN, M_BOX/BM, 2), 256>>>(boxf, boxp, Wk, bk, kb, Wv, bv, vb);
    // 3: pack K/V into attention-ready fp16 layouts
    kv_pack<<<(H_HEADS * M_BOX) / 256, 256>>>(kb, vb, khg, vtg);
    // 4: Q = (src + pos) @ Wq^T + bq  (A-resident, fused add+cvt, HALF output)
    hgemm_ares<false, true, true, 3><<<MB, 256, ARES_SMEM>>>(nullptr, src, pos, wh + WOFF_Q, bq, nullptr, qh, D_DIM);
    // 5: tensor-core masked attention (4 sets per CTA)
    attn_mma<<<dim3(S_SETS / SPC, H_HEADS), 256, ATTN_SMEM>>>(qh, khg, vtg, vinds, vcoords, bcoords, ctxh);
    // 6: O projection (A-resident)
    hgemm_ares<false, false, false, 3><<<MB, 256, ARES_SMEM>>>(ctxh, nullptr, nullptr, wh + WOFF_O, bo, projb, nullptr, D_DIM);
    // 7,8: first-occurrence scatter index
    init_fp_kernel<<<N_PTS / 256, 256>>>(fpb);
    fill_fp_kernel<<<(S_SETS * L_LEN) / 256, 256>>>(vinds, fpb);
    // 9: x = LN(src + proj[first_pos]) (+ half copy)
    ln_kernel<true, true><<<N_PTS / 8, 256>>>(src, projb, fpb, g1, be1, xb, xh);
    // 10: FFN1 (A-resident, relu, half out)
    hgemm_ares<true, true, false, 12><<<MB, 256, ARES_SMEM>>>(xh, nullptr, nullptr, wh + WOFF_1, b1, nullptr, hh, FF_DIM);
    // 11: FFN2 (K=768, wide: hh read once)
    hgemm_wide<<<MB, 256, WIDE_SMEM>>>(hh, wh + WOFF_2, b2, yb);
    // 12: out = LN(x + ffn)
    ln_kernel<false, false><<<N_PTS / 8, 256>>>(xb, yb, nullptr, g2, be2, out, nullptr);
}

// round 15
// speedup vs baseline: 3.7038x; 1.0215x over previous
#include <cuda_runtime.h>
#include <cuda_fp16.h>
#include <math_constants.h>
#include <cstdint>

#define N_PTS   92160
#define D_DIM   192
#define BD_DIM  256
#define H_HEADS 8
#define FF_DIM  768
#define S_SETS  2560
#define L_LEN   36
#define M_BOX   256
#define HD_DIM  24
#define SPC     4          // sets per attention CTA

// ---------------- scratch (static device globals; no allocation) ----------------
__device__ float g_proj[N_PTS * D_DIM];
__device__ float g_x[N_PTS * D_DIM];
__device__ float g_k[M_BOX * D_DIM];
__device__ float g_v[M_BOX * D_DIM];
__device__ int   g_fp[N_PTS];

__device__ __half g_qh[N_PTS * D_DIM];
__device__ __half g_ctxh[N_PTS * D_DIM];
__device__ __half g_xh[N_PTS * D_DIM];
__device__ __half g_hh[(size_t)N_PTS * FF_DIM];
__device__ __half g_kh[H_HEADS * M_BOX * 32];      // [h][m][32] padded fp16 K
__device__ __half g_vt[H_HEADS * HD_DIM * M_BOX];  // [h][d][m]  transposed fp16 V
#define WOFF_Q 0
#define WOFF_O 36864
#define WOFF_1 73728
#define WOFF_2 221184
__device__ __half g_wh[368640];

__device__ __forceinline__ void mma16816(float* d, const uint32_t* a, const uint32_t* b) {
    asm volatile(
        "mma.sync.aligned.m16n8k16.row.col.f32.f16.f16.f32 "
        "{%0,%1,%2,%3}, {%4,%5,%6,%7}, {%8,%9}, {%0,%1,%2,%3};\n"
        : "+f"(d[0]), "+f"(d[1]), "+f"(d[2]), "+f"(d[3])
        : "r"(a[0]), "r"(a[1]), "r"(a[2]), "r"(a[3]), "r"(b[0]), "r"(b[1]));
}

__device__ __forceinline__ uint4 add_cvt8(const float* p, const float* q) {
    float4 x0 = *(const float4*)p;
    float4 x1 = *(const float4*)(p + 4);
    float4 y0 = *(const float4*)q;
    float4 y1 = *(const float4*)(q + 4);
    __half2 h0 = __floats2half2_rn(x0.x + y0.x, x0.y + y0.y);
    __half2 h1 = __floats2half2_rn(x0.z + y0.z, x0.w + y0.w);
    __half2 h2 = __floats2half2_rn(x1.x + y1.x, x1.y + y1.y);
    __half2 h3 = __floats2half2_rn(x1.z + y1.z, x1.w + y1.w);
    uint4 r;
    r.x = *(uint32_t*)&h0; r.y = *(uint32_t*)&h1;
    r.z = *(uint32_t*)&h2; r.w = *(uint32_t*)&h3;
    return r;
}

// ================= A-resident fp16 GEMM for K=192: C = A @ W^T + bias =================
#define ARES_SMEM ((128 * 200 + 2 * 64 * 40) * 2)

template<bool RELU, bool OUTH, bool ADDIN, int NTILES>
__global__ __launch_bounds__(256)
void hgemm_ares(const __half* __restrict__ A, const float* __restrict__ Af,
                const float* __restrict__ Af2, const __half* __restrict__ W,
                const float* __restrict__ bias, float* __restrict__ C,
                __half* __restrict__ Ch, int Dout)
{
    extern __shared__ __half dsm[];
    __half* As = dsm;                 // 128 x 200
    __half* Wb0 = dsm + 25600;        // 64 x 40
    __half* Wb1 = dsm + 28160;

    const int tid  = threadIdx.x;
    const int lane = tid & 31;
    const int wid  = tid >> 5;
    const int wm   = wid & 3;
    const int wn   = wid >> 2;
    const int m0   = blockIdx.x * 128;
    const int lr   = lane >> 2;
    const int lc2  = (lane & 3) * 2;

    #pragma unroll
    for (int j = 0; j < 12; j++) {
        const int idx = tid + 256 * j;
        const int r = idx / 24, c8 = (idx % 24) * 8;
        const size_t go = (size_t)(m0 + r) * 192 + c8;
        uint4 v;
        if (ADDIN) v = add_cvt8(Af + go, Af2 + go);
        else       v = *(const uint4*)(A + go);
        *(uint4*)(As + r * 200 + c8) = v;
    }

    const int rw = tid >> 2;
    const int cw = (tid & 3) * 8;
    const int sW = rw * 40 + cw;

    const int NI = NTILES * 6;
    uint4 pw = *(const uint4*)(W + (size_t)rw * 192 + cw);
    *(uint4*)(Wb0 + sW) = pw;

    float acc[2][4][4];

    for (int i = 0; i < NI; ++i) {
        const int nt = i / 6, kc = i % 6;
        __syncthreads();

        if (kc == 0) {
            #pragma unroll
            for (int a = 0; a < 2; a++)
                #pragma unroll
                for (int b = 0; b < 4; b++)
                    #pragma unroll
                    for (int e = 0; e < 4; e++) acc[a][b][e] = 0.f;
        }

        if (i + 1 < NI) {
            const int nt2 = (i + 1) / 6, kc2 = (i + 1) % 6;
            pw = *(const uint4*)(W + (size_t)(nt2 * 64 + rw) * 192 + kc2 * 32 + cw);
        }

        const __half* Ws = (i & 1) ? Wb1 : Wb0;
        const int ca = kc * 32;

        #pragma unroll
        for (int ks = 0; ks < 32; ks += 16) {
            uint32_t af[2][4], bf[4][2];
            #pragma unroll
            for (int a = 0; a < 2; a++) {
                const __half* p = As + (wm * 32 + a * 16 + lr) * 200 + ca + ks + lc2;
                af[a][0] = *(const uint32_t*)(p);
                af[a][1] = *(const uint32_t*)(p + 8 * 200);
                af[a][2] = *(const uint32_t*)(p + 8);
                af[a][3] = *(const uint32_t*)(p + 8 * 200 + 8);
            }
            #pragma unroll
            for (int b = 0; b < 4; b++) {
                const __half* p = Ws + (wn * 32 + b * 8 + lr) * 40 + ks + lc2;
                bf[b][0] = *(const uint32_t*)(p);
                bf[b][1] = *(const uint32_t*)(p + 8);
            }
            #pragma unroll
            for (int a = 0; a < 2; a++)
                #pragma unroll
                for (int b = 0; b < 4; b++)
                    mma16816(acc[a][b], af[a], bf[b]);
        }

        if (kc == 5) {
            const int n0 = nt * 64;
            #pragma unroll
            for (int a = 0; a < 2; a++) {
                const int r = m0 + wm * 32 + a * 16 + lr;
                #pragma unroll
                for (int b = 0; b < 4; b++) {
                    const int cj = n0 + wn * 32 + b * 8 + lc2;
                    const float2 bx = *(const float2*)(bias + cj);
                    float v0 = acc[a][b][0] + bx.x;
                    float v1 = acc[a][b][1] + bx.y;
                    float v2 = acc[a][b][2] + bx.x;
                    float v3 = acc[a][b][3] + bx.y;
                    if (RELU) {
                        v0 = fmaxf(v0, 0.f); v1 = fmaxf(v1, 0.f);
                        v2 = fmaxf(v2, 0.f); v3 = fmaxf(v3, 0.f);
                    }
                    if (OUTH) {
                        *(__half2*)(Ch + (size_t)r       * Dout + cj) = __floats2half2_rn(v0, v1);
                        *(__half2*)(Ch + (size_t)(r + 8) * Dout + cj) = __floats2half2_rn(v2, v3);
                    } else {
                        *(float2*)(C + (size_t)r       * Dout + cj) = make_float2(v0, v1);
                        *(float2*)(C + (size_t)(r + 8) * Dout + cj) = make_float2(v2, v3);
                    }
                }
            }
        }

        if (i + 1 < NI) {
            __half* nb = ((i + 1) & 1) ? Wb1 : Wb0;
            *(uint4*)(nb + sW) = pw;
        }
    }
}

// ================= wide fp16 GEMM + fused LayerNorm: out = LN(X + A@W^T + bias) =================
// FFN2 (K=768), BN = 192 = full output row per CTA. A read once; LN done in-epilogue.
#define WIDE_SMEM (2 * 320 * 40 * 2)   // 51200 B (also hosts the 9 KB LN reduction scratch)

__global__ __launch_bounds__(256)
void hgemm_wide_ln(const __half* __restrict__ A, const __half* __restrict__ W,
                   const float* __restrict__ bias, const float* __restrict__ X,
                   const float* __restrict__ gamma, const float* __restrict__ beta,
                   float* __restrict__ Out)
{
    extern __shared__ __half wsm[];
    const int K = FF_DIM;              // 768
    const int Dout = D_DIM;            // 192

    const int tid  = threadIdx.x;
    const int lane = tid & 31;
    const int wid  = tid >> 5;
    const int wm   = wid & 3;
    const int wn   = wid >> 2;
    const int m0   = blockIdx.x * 128;
    const int lr   = lane >> 2;
    const int lc2  = (lane & 3) * 2;

    const int nT = K >> 5;             // 24

    int lrow[5], lcol[5];
    const __half* gptr[5];
    #pragma unroll
    for (int j = 0; j < 5; j++) {
        const int u = tid + 256 * j;
        const int r = u >> 2, c8 = (u & 3) * 8;
        lrow[j] = r; lcol[j] = c8;
        gptr[j] = (r < 128) ? (A + (size_t)(m0 + r) * K + c8)
                            : (W + (size_t)(r - 128) * K + c8);
    }

    uint4 st[5];
    #pragma unroll
    for (int j = 0; j < 5; j++) st[j] = *(const uint4*)(gptr[j]);

    float acc[2][12][4];
    #pragma unroll
    for (int a = 0; a < 2; a++)
        #pragma unroll
        for (int b = 0; b < 12; b++)
            #pragma unroll
            for (int e = 0; e < 4; e++) acc[a][b][e] = 0.f;

    {
        __half* s0 = wsm;
        #pragma unroll
        for (int j = 0; j < 5; j++)
            *(uint4*)(s0 + lrow[j] * 40 + lcol[j]) = st[j];
    }

    for (int t = 0; t < nT; ++t) {
        __syncthreads();

        if (t + 1 < nT) {
            const int off = (t + 1) * 32;
            #pragma unroll
            for (int j = 0; j < 5; j++) st[j] = *(const uint4*)(gptr[j] + off);
        }

        const __half* As = wsm + (t & 1) * (320 * 40);
        const __half* Ws = As + 128 * 40;

        #pragma unroll
        for (int ks = 0; ks < 32; ks += 16) {
            uint32_t af[2][4];
            #pragma unroll
            for (int a = 0; a < 2; a++) {
                const __half* p = As + (wm * 32 + a * 16 + lr) * 40 + ks + lc2;
                af[a][0] = *(const uint32_t*)(p);
                af[a][1] = *(const uint32_t*)(p + 8 * 40);
                af[a][2] = *(const uint32_t*)(p + 8);
                af[a][3] = *(const uint32_t*)(p + 8 * 40 + 8);
            }
            #pragma unroll
            for (int b = 0; b < 12; b++) {
                uint32_t bf[2];
                const __half* p = Ws + (wn * 96 + b * 8 + lr) * 40 + ks + lc2;
                bf[0] = *(const uint32_t*)(p);
                bf[1] = *(const uint32_t*)(p + 8);
                mma16816(acc[0][b], af[0], bf);
                mma16816(acc[1][b], af[1], bf);
            }
        }

        if (t + 1 < nT) {
            __half* nb = wsm + ((t + 1) & 1) * (320 * 40);
            #pragma unroll
            for (int j = 0; j < 5; j++)
                *(uint4*)(nb + lrow[j] * 40 + lcol[j]) = st[j];
        }
    }

    // ---- fused epilogue: v = X + acc + bias; LN over each row ----
    __syncthreads();                           // pipeline smem now dead; reuse for reduction
    float* redsum = (float*)wsm;               // [128][8]
    float* redsq  = redsum + 1024;             // [128][8]
    float* stats  = redsq + 1024;              // [128][2]

    const int part = wn * 4 + (lane & 3);      // 0..7; the 8 owners of each row

    #pragma unroll
    for (int a = 0; a < 2; a++) {
        #pragma unroll
        for (int hf = 0; hf < 2; hf++) {
            const int rl = wm * 32 + a * 16 + hf * 8 + lr;     // local row 0..127
            const int r  = m0 + rl;
            float s = 0.f, q = 0.f;
            #pragma unroll
            for (int b = 0; b < 12; b++) {
                const int cj = wn * 96 + b * 8 + lc2;
                const float2 bx = *(const float2*)(bias + cj);
                const float2 xv = *(const float2*)(X + (size_t)r * Dout + cj);
                float v0 = acc[a][b][hf*2+0] + bx.x + xv.x;
                float v1 = acc[a][b][hf*2+1] + bx.y + xv.y;
                acc[a][b][hf*2+0] = v0;
                acc[a][b][hf*2+1] = v1;
                s += v0 + v1;
                q += v0 * v0 + v1 * v1;
            }
            redsum[rl * 8 + part] = s;
            redsq [rl * 8 + part] = q;
        }
    }
    __syncthreads();

    if (tid < 128) {
        float s = 0.f, q = 0.f;
        #pragma unroll
        for (int p = 0; p < 8; p++) { s += redsum[tid * 8 + p]; q += redsq[tid * 8 + p]; }
        const float mean = s * (1.0f / D_DIM);
        const float var  = q * (1.0f / D_DIM) - mean * mean;
        stats[tid * 2]     = mean;
        stats[tid * 2 + 1] = rsqrtf(var + 1e-5f);
    }
    __syncthreads();

    #pragma unroll
    for (int a = 0; a < 2; a++) {
        #pragma unroll
        for (int hf = 0; hf < 2; hf++) {
            const int rl = wm * 32 + a * 16 + hf * 8 + lr;
            const int r  = m0 + rl;
            const float mean = stats[rl * 2];
            const float inv  = stats[rl * 2 + 1];
            #pragma unroll
            for (int b = 0; b < 12; b++) {
                const int cj = wn * 96 + b * 8 + lc2;
                const float2 gg = *(const float2*)(gamma + cj);
                const float2 bb2 = *(const float2*)(beta + cj);
                const float v0 = acc[a][b][hf*2+0];
                const float v1 = acc[a][b][hf*2+1];
                *(float2*)(Out + (size_t)r * Dout + cj) =
                    make_float2((v0 - mean) * inv * gg.x + bb2.x,
                                (v1 - mean) * inv * gg.y + bb2.y);
            }
        }
    }
}

// ---------------- combined K/V projection (SIMT fp32), blockIdx.z selects ----------------
#define BM 128
#define BN 64
#define BK 16

__global__ __launch_bounds__(256, 2)
void gemm_kv(const float* __restrict__ boxf, const float* __restrict__ boxp,
             const float* __restrict__ Wk, const float* __restrict__ bk, float* __restrict__ Ck,
             const float* __restrict__ Wv, const float* __restrict__ bv, float* __restrict__ Cv)
{
    const bool isK = (blockIdx.z == 0);
    const float* A   = boxf;
    const float* A2  = isK ? boxp : nullptr;
    const float* W   = isK ? Wk : Wv;
    const float* bias= isK ? bk : bv;
    float* C         = isK ? Ck : Cv;
    const int K = BD_DIM, Dout = D_DIM;

    __shared__ float As[BK][BM + 4];
    __shared__ float Ws[BK][BN + 4];

    const int tid = threadIdx.x;
    const int tx = tid & 15;
    const int ty = tid >> 4;
    const int m0 = blockIdx.y * BM;
    const int n0 = blockIdx.x * BN;

    const int ar = tid >> 2;
    const int ac = (tid & 3) << 2;

    const float* Ap0 = A + (size_t)(m0 + ar)      * K + ac;
    const float* Ap1 = A + (size_t)(m0 + ar + 64) * K + ac;
    const float* Wp  = W + (size_t)(n0 + ar)      * K + ac;

    const int nT = K / BK;

    float4 pa0 = *(const float4*)(Ap0);
    float4 pa1 = *(const float4*)(Ap1);
    float4 pw  = *(const float4*)(Wp);
    if (isK) {
        const float* B0 = A2 + (size_t)(m0 + ar) * K + ac;
        const float* B1 = A2 + (size_t)(m0 + ar + 64) * K + ac;
        float4 q0 = *(const float4*)B0;
        float4 q1 = *(const float4*)B1;
        pa0.x += q0.x; pa0.y += q0.y; pa0.z += q0.z; pa0.w += q0.w;
        pa1.x += q1.x; pa1.y += q1.y; pa1.z += q1.z; pa1.w += q1.w;
    }

    float acc[8][4];
    #pragma unroll
    for (int i = 0; i < 8; i++)
        #pragma unroll
        for (int j = 0; j < 4; j++) acc[i][j] = 0.f;

    for (int t = 0; t < nT; ++t) {
        As[ac+0][ar]    = pa0.x; As[ac+1][ar]    = pa0.y;
        As[ac+2][ar]    = pa0.z; As[ac+3][ar]    = pa0.w;
        As[ac+0][ar+64] = pa1.x; As[ac+1][ar+64] = pa1.y;
        As[ac+2][ar+64] = pa1.z; As[ac+3][ar+64] = pa1.w;
        Ws[ac+0][ar]    = pw.x;  Ws[ac+1][ar]    = pw.y;
        Ws[ac+2][ar]    = pw.z;  Ws[ac+3][ar]    = pw.w;
        __syncthreads();

        if (t + 1 < nT) {
            const int off = (t + 1) * BK;
            pa0 = *(const float4*)(Ap0 + off);
            pa1 = *(const float4*)(Ap1 + off);
            pw  = *(const float4*)(Wp  + off);
            if (isK) {
                const float* B0 = A2 + (size_t)(m0 + ar) * K + ac + off;
                const float* B1 = A2 + (size_t)(m0 + ar + 64) * K + ac + off;
                float4 q0 = *(const float4*)B0;
                float4 q1 = *(const float4*)B1;
                pa0.x += q0.x; pa0.y += q0.y; pa0.z += q0.z; pa0.w += q0.w;
                pa1.x += q1.x; pa1.y += q1.y; pa1.z += q1.z; pa1.w += q1.w;
            }
        }

        #pragma unroll
        for (int k = 0; k < BK; ++k) {
            float a[8], w[4];
            #pragma unroll
            for (int i = 0; i < 8; i++) a[i] = As[k][ty * 8 + i];
            #pragma unroll
            for (int j = 0; j < 4; j++) w[j] = Ws[k][tx * 4 + j];
            #pragma unroll
            for (int i = 0; i < 8; i++)
                #pragma unroll
                for (int j = 0; j < 4; j++) acc[i][j] += a[i] * w[j];
        }
        __syncthreads();
    }

    const float b0 = bias[n0 + tx*4 + 0];
    const float b1 = bias[n0 + tx*4 + 1];
    const float b2 = bias[n0 + tx*4 + 2];
    const float b3 = bias[n0 + tx*4 + 3];
    #pragma unroll
    for (int i = 0; i < 8; i++) {
        float4 o;
        o.x = acc[i][0] + b0; o.y = acc[i][1] + b1;
        o.z = acc[i][2] + b2; o.w = acc[i][3] + b3;
        *(float4*)(C + (size_t)(m0 + ty*8 + i) * Dout + n0 + tx*4) = o;
    }
}

// ---------------- K/V pack ----------------
__global__ void kv_pack(const float* __restrict__ kb, const float* __restrict__ vb,
                        __half* __restrict__ khg, __half* __restrict__ vtg)
{
    const int i = blockIdx.x * 256 + threadIdx.x;
    if (i >= H_HEADS * M_BOX) return;
    const int h = i >> 8, m = i & 255;

    {
        const float4* kp = (const float4*)(kb + (size_t)m * D_DIM + h * HD_DIM);
        __half2 hrow[16];
        #pragma unroll
        for (int j = 0; j < 6; j++) {
            float4 f = kp[j];
            hrow[2*j]   = __floats2half2_rn(f.x, f.y);
            hrow[2*j+1] = __floats2half2_rn(f.z, f.w);
        }
        const __half2 zz = __floats2half2_rn(0.f, 0.f);
        hrow[12] = zz; hrow[13] = zz; hrow[14] = zz; hrow[15] = zz;
        uint4* dst = (uint4*)(khg + ((size_t)h * M_BOX + m) * 32);
        dst[0] = ((const uint4*)hrow)[0];
        dst[1] = ((const uint4*)hrow)[1];
        dst[2] = ((const uint4*)hrow)[2];
        dst[3] = ((const uint4*)hrow)[3];
    }
    {
        const float4* vp = (const float4*)(vb + (size_t)m * D_DIM + h * HD_DIM);
        __half* base = vtg + (size_t)h * HD_DIM * M_BOX + m;
        #pragma unroll
        for (int j = 0; j < 6; j++) {
            float4 g = vp[j];
            base[(4*j+0) * M_BOX] = __float2half(g.x);
            base[(4*j+1) * M_BOX] = __float2half(g.y);
            base[(4*j+2) * M_BOX] = __float2half(g.z);
            base[(4*j+3) * M_BOX] = __float2half(g.w);
        }
    }
}

// ================= tensor-core attention: one CTA per (4 sets, head) =================
#define AT_QS   0
#define AT_KS   1920
#define AT_VT   12160
#define AT_PS   18496
#define AT_INT  31168
#define ATTN_SMEM (31168 * 2 + (36 + 256) * 4)

__global__ __launch_bounds__(256)
void attn_mma(const __half* __restrict__ qh, const __half* __restrict__ khg,
              const __half* __restrict__ vtg, const int* __restrict__ vinds,
              const int* __restrict__ vcoords, const int* __restrict__ bcoords,
              __half* __restrict__ ctxh)
{
    extern __shared__ __half sm[];
    __half* Qs = sm + AT_QS;
    __half* Ks = sm + AT_KS;
    __half* Vt = sm + AT_VT;
    __half* Ps = sm + AT_PS;
    int* qb = (int*)(sm + AT_INT);
    int* bb = qb + 36;

    const int s0idx = blockIdx.x * SPC, h = blockIdx.y;
    const int t = threadIdx.x, lane = t & 31, wid = t >> 5;
    const int lr = lane >> 2, lc2 = (lane & 3) * 2;

    {
        const uint4* kp = (const uint4*)(khg + ((size_t)h * M_BOX + t) * 32);
        uint4* krow = (uint4*)(Ks + t * 40);
        krow[0] = kp[0];
        krow[1] = kp[1];
        krow[2] = kp[2];
        krow[3] = kp[3];
        bb[t] = bcoords[t * 4];
    }
    {
        const __half* vsrc = vtg + (size_t)h * HD_DIM * M_BOX;
        #pragma unroll
        for (int j = 0; j < 3; j++) {
            const int idx = t + 256 * j;
            const int r = idx >> 5, c = idx & 31;
            *(uint4*)(Vt + r * 264 + c * 8) = *(const uint4*)(vsrc + r * M_BOX + c * 8);
        }
    }

    for (int si = 0; si < SPC; ++si) {
        const int s = s0idx + si;

        {
            const uint4 z4 = make_uint4(0u, 0u, 0u, 0u);
            for (int i = t; i < 36 * 4; i += 256) {
                const int l = i >> 2, c = i & 3;
                uint4 v;
                if (c < 3) v = *(const uint4*)(qh + (size_t)vinds[s * L_LEN + l] * D_DIM + h * HD_DIM + c * 8);
                else       v = z4;
                *(uint4*)(Qs + l * 40 + c * 8) = v;
            }
        }
        if (t < 36) qb[t] = vcoords[(size_t)vinds[s * L_LEN + t] * 4];
        __syncthreads();

        float acc[3][4][4];
        #pragma unroll
        for (int i = 0; i < 3; i++)
            #pragma unroll
            for (int j = 0; j < 4; j++)
                #pragma unroll
                for (int e = 0; e < 4; e++) acc[i][j][e] = 0.f;

        #pragma unroll
        for (int kk = 0; kk < 2; kk++) {
            const int k0 = kk * 16;
            uint32_t af[3][4], bf[4][2];
            #pragma unroll
            for (int i = 0; i < 3; i++) {
                const __half* p = Qs + (i * 16 + lr) * 40 + k0 + lc2;
                af[i][0] = *(const uint32_t*)(p);
                af[i][1] = *(const uint32_t*)(p + 8 * 40);
                af[i][2] = *(const uint32_t*)(p + 8);
                af[i][3] = *(const uint32_t*)(p + 8 * 40 + 8);
            }
            #pragma unroll
            for (int j = 0; j < 4; j++) {
                const __half* p = Ks + (wid * 32 + j * 8 + lr) * 40 + k0 + lc2;
                bf[j][0] = *(const uint32_t*)(p);
                bf[j][1] = *(const uint32_t*)(p + 8);
            }
            #pragma unroll
            for (int i = 0; i < 3; i++)
                #pragma unroll
                for (int j = 0; j < 4; j++)
                    mma16816(acc[i][j], af[i], bf[j]);
        }

        {
            const float scale = 0.20412414523193154f;
            #pragma unroll
            for (int i = 0; i < 3; i++) {
                const int r0 = i * 16 + lr, r1 = r0 + 8;
                const int q0 = (r0 < L_LEN) ? qb[r0] : 0;
                const int q1 = (r1 < L_LEN) ? qb[r1] : 0;
                #pragma unroll
                for (int j = 0; j < 4; j++) {
                    const int c = wid * 32 + j * 8 + lc2;
                    const int b0 = bb[c], b1 = bb[c + 1];
                    if (r0 < L_LEN) {
                        float v0 = (q0 != b0) ? -CUDART_INF_F : acc[i][j][0] * scale;
                        float v1 = (q0 != b1) ? -CUDART_INF_F : acc[i][j][1] * scale;
                        *(__half2*)(Ps + r0 * 264 + c) = __floats2half2_rn(v0, v1);
                    }
                    if (r1 < L_LEN) {
                        float v2 = (q1 != b0) ? -CUDART_INF_F : acc[i][j][2] * scale;
                        float v3 = (q1 != b1) ? -CUDART_INF_F : acc[i][j][3] * scale;
                        *(__half2*)(Ps + r1 * 264 + c) = __floats2half2_rn(v2, v3);
                    }
                }
            }
        }
        __syncthreads();

        for (int l = wid; l < L_LEN; l += 8) {
            __half* row = Ps + l * 264;
            float e[8];
            float mx = -CUDART_INF_F;
            #pragma unroll
            for (int i = 0; i < 8; i++) { e[i] = __half2float(row[lane + 32*i]); mx = fmaxf(mx, e[i]); }
            #pragma unroll
            for (int o = 16; o > 0; o >>= 1) mx = fmaxf(mx, __shfl_xor_sync(0xffffffffu, mx, o));
            float sum = 0.f;
            if (mx > -CUDART_INF_F) {
                #pragma unroll
                for (int i = 0; i < 8; i++) { e[i] = __expf(e[i] - mx); sum += e[i]; }
            } else {
                #pragma unroll
                for (int i = 0; i < 8; i++) e[i] = 0.f;
            }
            #pragma unroll
            for (int o = 16; o > 0; o >>= 1) sum += __shfl_xor_sync(0xffffffffu, sum, o);
            const float inv = sum > 0.f ? 1.0f / sum : 0.f;
            #pragma unroll
            for (int i = 0; i < 8; i++) row[lane + 32*i] = __float2half(e[i] * inv);
        }
        __syncthreads();

        if (wid < 3) {
            const int mt = wid;
            float a2[3][4];
            #pragma unroll
            for (int n = 0; n < 3; n++)
                #pragma unroll
                for (int e = 0; e < 4; e++) a2[n][e] = 0.f;

            #pragma unroll 4
            for (int kt = 0; kt < 16; kt++) {
                uint32_t af[4];
                const __half* pa = Ps + (mt * 16 + lr) * 264 + kt * 16 + lc2;
                af[0] = *(const uint32_t*)(pa);
                af[1] = *(const uint32_t*)(pa + 8 * 264);
                af[2] = *(const uint32_t*)(pa + 8);
                af[3] = *(const uint32_t*)(pa + 8 * 264 + 8);
                #pragma unroll
                for (int nt = 0; nt < 3; nt++) {
                    uint32_t bf[2];
                    const __half* pb = Vt + (nt * 8 + lr) * 264 + kt * 16 + lc2;
                    bf[0] = *(const uint32_t*)(pb);
                    bf[1] = *(const uint32_t*)(pb + 8);
                    mma16816(a2[nt], af, bf);
                }
            }

            const int r0 = mt * 16 + lr, r1 = r0 + 8;
            #pragma unroll
            for (int nt = 0; nt < 3; nt++) {
                const int c = nt * 8 + lc2;
                if (r0 < L_LEN)
                    *(__half2*)(ctxh + ((size_t)s * L_LEN + r0) * D_DIM + h * HD_DIM + c) = __floats2half2_rn(a2[nt][0], a2[nt][1]);
                if (r1 < L_LEN)
                    *(__half2*)(ctxh + ((size_t)s * L_LEN + r1) * D_DIM + h * HD_DIM + c) = __floats2half2_rn(a2[nt][2], a2[nt][3]);
            }
        }
    }
}

// ---------------- first-occurrence scatter index ----------------
__global__ void init_fp_kernel(int* __restrict__ fp)
{
    int i = blockIdx.x * blockDim.x + threadIdx.x;
    if (i < N_PTS) fp[i] = 0x7FFFFFFF;
}

__global__ void fill_fp_kernel(const int* __restrict__ vinds, int* __restrict__ fp)
{
    int p = blockIdx.x * blockDim.x + threadIdx.x;
    if (p < S_SETS * L_LEN) {
        int n = vinds[p];
        if (n >= 0 && n < N_PTS) atomicMin(&fp[n], p);
    }
}

// ---------------- residual + layernorm (warp per row) ----------------
template<bool GATHER, bool OUTH>
__global__ __launch_bounds__(256)
void ln_kernel(const float* __restrict__ a, const float* __restrict__ b,
               const int* __restrict__ fp, const float* __restrict__ gamma,
               const float* __restrict__ beta, float* __restrict__ outp,
               __half* __restrict__ oh)
{
    const int row  = (blockIdx.x * 256 + threadIdx.x) >> 5;
    const int lane = threadIdx.x & 31;
    if (row >= N_PTS) return;

    const float* arow = a + (size_t)row * D_DIM;
    const float* brow;
    if (GATHER) {
        int p = fp[row];
        if (p < 0 || p >= N_PTS) p = row;
        brow = b + (size_t)p * D_DIM;
    } else {
        brow = b + (size_t)row * D_DIM;
    }

    float v[6];
    float s = 0.f;
    #pragma unroll
    for (int i = 0; i < 6; i++) {
        const int idx = lane + 32 * i;
        v[i] = arow[idx] + brow[idx];
        s += v[i];
    }
    #pragma unroll
    for (int o = 16; o > 0; o >>= 1) s += __shfl_xor_sync(0xffffffffu, s, o);
    const float mean = s * (1.0f / D_DIM);

    float q = 0.f;
    #pragma unroll
    for (int i = 0; i < 6; i++) { const float d = v[i] - mean; q += d * d; }
    #pragma unroll
    for (int o = 16; o > 0; o >>= 1) q += __shfl_xor_sync(0xffffffffu, q, o);
    const float inv = rsqrtf(q * (1.0f / D_DIM) + 1e-5f);

    float* orow = outp + (size_t)row * D_DIM;
    #pragma unroll
    for (int i = 0; i < 6; i++) {
        const int idx = lane + 32 * i;
        const float val = (v[i] - mean) * inv * gamma[idx] + beta[idx];
        orow[idx] = val;
        if (OUTH) oh[(size_t)row * D_DIM + idx] = __float2half(val);
    }
}

// ---------------- weight conversion (all four in one launch) ----------------
__global__ void cvt_weights_kernel(const float* __restrict__ Wq, const float* __restrict__ Wo,
                                   const float* __restrict__ W1, const float* __restrict__ W2,
                                   __half* __restrict__ wh)
{
    const int i = blockIdx.x * blockDim.x + threadIdx.x;
    const int n4 = 368640 / 4;
    if (i >= n4) return;
    const int e = i * 4;
    const float* srcp;
    int off;
    if (e < WOFF_O)      { srcp = Wq; off = e - WOFF_Q; }
    else if (e < WOFF_1) { srcp = Wo; off = e - WOFF_O; }
    else if (e < WOFF_2) { srcp = W1; off = e - WOFF_1; }
    else                 { srcp = W2; off = e - WOFF_2; }
    float4 x = *(const float4*)(srcp + off);
    ((__half2*)wh)[2*i]   = __floats2half2_rn(x.x, x.y);
    ((__half2*)wh)[2*i+1] = __floats2half2_rn(x.z, x.w);
}

// ---------------- launch ----------------
extern "C" void kernel_launch(void* const* d_in, const int* in_sizes, int n_in,
                              void* d_out, int out_size)
{
    const float* src     = (const float*)d_in[0];
    const float* pos     = (const float*)d_in[1];
    const float* boxf    = (const float*)d_in[2];
    const float* boxp    = (const float*)d_in[3];
    const int*   vcoords = (const int*)  d_in[4];
    const int*   bcoords = (const int*)  d_in[5];
    const int*   vinds   = (const int*)  d_in[6];
    const float* Wq = (const float*)d_in[7];  const float* bq  = (const float*)d_in[8];
    const float* Wk = (const float*)d_in[9];  const float* bk  = (const float*)d_in[10];
    const float* Wv = (const float*)d_in[11]; const float* bv  = (const float*)d_in[12];
    const float* Wo = (const float*)d_in[13]; const float* bo  = (const float*)d_in[14];
    const float* W1 = (const float*)d_in[15]; const float* b1  = (const float*)d_in[16];
    const float* W2 = (const float*)d_in[17]; const float* b2  = (const float*)d_in[18];
    const float* g1 = (const float*)d_in[19]; const float* be1 = (const float*)d_in[20];
    const float* g2 = (const float*)d_in[21]; const float* be2 = (const float*)d_in[22];
    float* out = (float*)d_out;

    float *projb, *xb, *kb, *vb;
    int* fpb;
    __half *qh, *ctxh, *xh, *hh, *wh, *khg, *vtg;
    cudaGetSymbolAddress((void**)&projb, g_proj);
    cudaGetSymbolAddress((void**)&xb,    g_x);
    cudaGetSymbolAddress((void**)&kb,    g_k);
    cudaGetSymbolAddress((void**)&vb,    g_v);
    cudaGetSymbolAddress((void**)&fpb,   g_fp);
    cudaGetSymbolAddress((void**)&qh,    g_qh);
    cudaGetSymbolAddress((void**)&ctxh,  g_ctxh);
    cudaGetSymbolAddress((void**)&xh,    g_xh);
    cudaGetSymbolAddress((void**)&hh,    g_hh);
    cudaGetSymbolAddress((void**)&wh,    g_wh);
    cudaGetSymbolAddress((void**)&khg,   g_kh);
    cudaGetSymbolAddress((void**)&vtg,   g_vt);

    cudaFuncSetAttribute(attn_mma, cudaFuncAttributeMaxDynamicSharedMemorySize, ATTN_SMEM);
    cudaFuncSetAttribute(hgemm_ares<false, true,  true,  3>,  cudaFuncAttributeMaxDynamicSharedMemorySize, ARES_SMEM);
    cudaFuncSetAttribute(hgemm_ares<false, false, false, 3>,  cudaFuncAttributeMaxDynamicSharedMemorySize, ARES_SMEM);
    cudaFuncSetAttribute(hgemm_ares<true,  true,  false, 12>, cudaFuncAttributeMaxDynamicSharedMemorySize, ARES_SMEM);
    cudaFuncSetAttribute(hgemm_wide_ln, cudaFuncAttributeMaxDynamicSharedMemorySize, WIDE_SMEM);

    const int MB = N_PTS / 128;   // 720

    // 1: weight conversion
    cvt_weights_kernel<<<(368640/4 + 255)/256, 256>>>(Wq, Wo, W1, W2, wh);
    // 2: K/V projections
    gemm_kv<<<dim3(D_DIM/BN, M_BOX/BM, 2), 256>>>(boxf, boxp, Wk, bk, kb, Wv, bv, vb);
    // 3: pack K/V into attention-ready fp16 layouts
    kv_pack<<<(H_HEADS * M_BOX) / 256, 256>>>(kb, vb, khg, vtg);
    // 4: Q = (src + pos) @ Wq^T + bq  (A-resident, fused add+cvt, HALF output)
    hgemm_ares<false, true, true, 3><<<MB, 256, ARES_SMEM>>>(nullptr, src, pos, wh + WOFF_Q, bq, nullptr, qh, D_DIM);
    // 5: tensor-core masked attention (4 sets per CTA)
    attn_mma<<<dim3(S_SETS / SPC, H_HEADS), 256, ATTN_SMEM>>>(qh, khg, vtg, vinds, vcoords, bcoords, ctxh);
    // 6: O projection (A-resident)
    hgemm_ares<false, false, false, 3><<<MB, 256, ARES_SMEM>>>(ctxh, nullptr, nullptr, wh + WOFF_O, bo, projb, nullptr, D_DIM);
    // 7,8: first-occurrence scatter index
    init_fp_kernel<<<N_PTS / 256, 256>>>(fpb);
    fill_fp_kernel<<<(S_SETS * L_LEN) / 256, 256>>>(vinds, fpb);
    // 9: x = LN(src + proj[first_pos]) (+ half copy)
    ln_kernel<true, true><<<N_PTS / 8, 256>>>(src, projb, fpb, g1, be1, xb, xh);
    // 10: FFN1 (A-resident, relu, half out)
    hgemm_ares<true, true, false, 12><<<MB, 256, ARES_SMEM>>>(xh, nullptr, nullptr, wh + WOFF_1, b1, nullptr, hh, FF_DIM);
    // 11: FFN2 + fused LN2 -> final output (K=768, hh read once, no y round-trip)
    hgemm_wide_ln<<<MB, 256, WIDE_SMEM>>>(hh, wh + WOFF_2, b2, xb, g2, be2, out);
}